// round 11
// baseline (speedup 1.0000x reference)
#include <cuda_runtime.h>
#include <cstdint>
#include <cstddef>

#define HIDDIM 1024
#define NHEADS 16
#define MEMQ   512
#define LWIN   2048
#define KVLEN  2560
#define DH     64
#define NBATCH 8
#define BHTOT  128
#define QTILE  128

// ---------------- scratch ----------------
static __device__ float g_q  [(size_t)BHTOT * MEMQ  * DH];
static __device__ float g_k  [(size_t)BHTOT * KVLEN * DH];
static __device__ float g_v  [(size_t)BHTOT * KVLEN * DH];
static __device__ float g_peT[(size_t)LWIN * DH];
static __device__ float g_pos[(size_t)BHTOT * MEMQ  * LWIN];
static __device__ float g_att[(size_t)NBATCH * MEMQ * HIDDIM];
static __device__ float g_w0 [(size_t)HIDDIM * HIDDIM];
static __device__ float g_w1 [(size_t)HIDDIM * HIDDIM];
static __device__ float g_w2 [(size_t)HIDDIM * HIDDIM];
static __device__ float g_w3 [(size_t)HIDDIM * HIDDIM];

// ---------------- helpers ----------------
__device__ __forceinline__ float to_tf32(float x){
    uint32_t y;
    asm("cvt.rna.tf32.f32 %0, %1;" : "=r"(y) : "f"(x));
    return __uint_as_float(y);
}
__device__ __forceinline__ uint32_t tf32u(float x){
    uint32_t y;
    asm("cvt.rna.tf32.f32 %0, %1;" : "=r"(y) : "f"(x));
    return y;
}
__device__ __forceinline__ void mma_tf32(float c[4], const uint32_t a[4],
                                         uint32_t b0, uint32_t b1){
    asm("mma.sync.aligned.m16n8k8.row.col.f32.tf32.tf32.f32 "
        "{%0,%1,%2,%3}, {%4,%5,%6,%7}, {%8,%9}, {%0,%1,%2,%3};"
        : "+f"(c[0]), "+f"(c[1]), "+f"(c[2]), "+f"(c[3])
        : "r"(a[0]), "r"(a[1]), "r"(a[2]), "r"(a[3]), "r"(b0), "r"(b1));
}
__device__ __forceinline__ void cp_async16(void* sptr, const void* gptr){
    uint32_t sa = (uint32_t)__cvta_generic_to_shared(sptr);
    asm volatile("cp.async.cg.shared.global [%0], [%1], 16;\n" :: "r"(sa), "l"(gptr));
}

// ---------------- elementwise tf32 cast (float4) ----------------
__global__ void tf32_cast(const float4* __restrict__ src, float4* __restrict__ dst, int n4){
    int i = blockIdx.x * 256 + threadIdx.x;
    if (i < n4) {
        float4 v = src[i];
        v.x = to_tf32(v.x); v.y = to_tf32(v.y);
        v.z = to_tf32(v.z); v.w = to_tf32(v.w);
        dst[i] = v;
    }
}

// ---------------- pe transpose (rounded) ----------------
__global__ void transpose_pe(const float* __restrict__ pe, float* __restrict__ peT){
    int idx = blockIdx.x * 256 + threadIdx.x;
    int l = idx >> 6;
    int d = idx & 63;
    peT[idx] = to_tf32(pe[(size_t)d * LWIN + l]);
}

// ---------------- pipelined NT GEMM (R9-proven) ----------------
#define GSTRIDE 36
#define GSTAGE  (128 * GSTRIDE)

__global__ __launch_bounds__(256, 2)
void gemm_nt(const float* __restrict__ A, int lda,
             const float* __restrict__ B,
             float* __restrict__ C,
             int K, int ldc, int mode, int S)
{
    extern __shared__ float sm[];

    const int tid  = threadIdx.x;
    const int warp = tid >> 5, lane = tid & 31;
    const int wm = warp >> 2, wn = warp & 3;
    const int g  = lane >> 2, tg = lane & 3;
    const int rowBase = blockIdx.x * 128;
    const int colBase = blockIdx.y * 128;

    float acc[4][4][4];
    #pragma unroll
    for (int mt = 0; mt < 4; mt++)
        #pragma unroll
        for (int nt = 0; nt < 4; nt++)
            #pragma unroll
            for (int i = 0; i < 4; i++) acc[mt][nt][i] = 0.f;

    const int niter = K >> 5;

    auto load_tiles = [&](int st, int k0){
        float* As = sm + st * (2 * GSTAGE);
        float* Bs = As + GSTAGE;
        #pragma unroll
        for (int i = 0; i < 4; i++) {
            int c = tid + i * 256;
            int row = c >> 3, ko = (c & 7) << 2;
            cp_async16(&As[row * GSTRIDE + ko],
                       A + (size_t)(rowBase + row) * lda + k0 + ko);
        }
        #pragma unroll
        for (int i = 0; i < 4; i++) {
            int c = tid + i * 256;
            int row = c >> 3, ko = (c & 7) << 2;
            cp_async16(&Bs[row * GSTRIDE + ko],
                       B + (size_t)(colBase + row) * K + k0 + ko);
        }
    };

    load_tiles(0, 0);
    asm volatile("cp.async.commit_group;\n" ::: "memory");

    for (int it = 0; it < niter; it++) {
        if (it + 1 < niter) load_tiles((it + 1) & 1, (it + 1) << 5);
        asm volatile("cp.async.commit_group;\n" ::: "memory");
        asm volatile("cp.async.wait_group 1;\n" ::: "memory");
        __syncthreads();

        const float* As = sm + (it & 1) * (2 * GSTAGE);
        const float* Bs = As + GSTAGE;

        #pragma unroll
        for (int ks = 0; ks < 4; ks++) {
            const int kb = ks * 8;
            uint32_t a[4][4];
            #pragma unroll
            for (int mt = 0; mt < 4; mt++) {
                int r = wm * 64 + mt * 16 + g;
                a[mt][0] = tf32u(As[r * GSTRIDE       + kb     + tg]);
                a[mt][1] = tf32u(As[(r + 8) * GSTRIDE + kb     + tg]);
                a[mt][2] = tf32u(As[r * GSTRIDE       + kb + 4 + tg]);
                a[mt][3] = tf32u(As[(r + 8) * GSTRIDE + kb + 4 + tg]);
            }
            #pragma unroll
            for (int nt = 0; nt < 4; nt++) {
                int j = wn * 32 + nt * 8 + g;
                uint32_t b0 = __float_as_uint(Bs[j * GSTRIDE + kb     + tg]);
                uint32_t b1 = __float_as_uint(Bs[j * GSTRIDE + kb + 4 + tg]);
                #pragma unroll
                for (int mt = 0; mt < 4; mt++)
                    mma_tf32(acc[mt][nt], a[mt], b0, b1);
            }
        }
        __syncthreads();
    }

    #pragma unroll
    for (int mt = 0; mt < 4; mt++) {
        int r = rowBase + wm * 64 + mt * 16 + g;
        #pragma unroll
        for (int nt = 0; nt < 4; nt++) {
            int jc = colBase + wn * 32 + nt * 8 + 2 * tg;
            if (mode == 0) {
                C[(size_t)r       * ldc + jc    ] = acc[mt][nt][0];
                C[(size_t)r       * ldc + jc + 1] = acc[mt][nt][1];
                C[(size_t)(r + 8) * ldc + jc    ] = acc[mt][nt][2];
                C[(size_t)(r + 8) * ldc + jc + 1] = acc[mt][nt][3];
            } else {
                int h = jc >> 6, d = jc & 63;
                int b1r = r / S,  s1 = r - b1r * S;
                int r2  = r + 8;
                int b2r = r2 / S, s2 = r2 - b2r * S;
                float* p0 = C + (((size_t)(b1r * NHEADS + h) * S + s1) << 6) + d;
                float* p1 = C + (((size_t)(b2r * NHEADS + h) * S + s2) << 6) + d;
                p0[0] = to_tf32(acc[mt][nt][0]);
                p0[1] = to_tf32(acc[mt][nt][1]);
                p1[0] = to_tf32(acc[mt][nt][2]);
                p1[1] = to_tf32(acc[mt][nt][3]);
            }
        }
    }
}

// ---------------- specialized pos GEMM: pos[m, l] = q[m,:]·peT[l,:], K=64 ----------------
// One block per 128-row strip. A tile loaded ONCE (smem + register fragments);
// B (peT, 512 KB total -> L2 resident) streamed in 64-row double-buffered stages.
// mma k-order identical to gemm_nt (8 sequential k8 steps) -> bit-identical output.
__global__ __launch_bounds__(256, 2)
void pos_kernel(const float* __restrict__ gq, const float* __restrict__ peT,
                float* __restrict__ gpos)
{
    extern __shared__ float sp[];
    float* As = sp;                  // 128 x 68
    float* Bst = sp + 128 * 68;      // 2 stages x (64 x 68)

    const int tid  = threadIdx.x;
    const int warp = tid >> 5, lane = tid & 31;
    const int g  = lane >> 2, tg = lane & 3;
    const int r0 = warp * 16 + g;                 // 0..127
    const size_t rowBase = (size_t)blockIdx.x * 128;

    // A tile fill (128 rows x 64 floats, contiguous)
    #pragma unroll
    for (int i = tid; i < 2048; i += 256) {
        int r = i >> 4, cc = (i & 15) << 2;
        cp_async16(&As[r*68 + cc], gq + (rowBase + r) * DH + cc);
    }
    asm volatile("cp.async.commit_group;\n" ::: "memory");

    // prefetch B tile 0
    #pragma unroll
    for (int i = tid; i < 1024; i += 256) {
        int r = i >> 4, cc = (i & 15) << 2;
        cp_async16(&Bst[r*68 + cc], peT + (size_t)r * DH + cc);
    }
    asm volatile("cp.async.commit_group;\n" ::: "memory");
    asm volatile("cp.async.wait_group 1;\n" ::: "memory");   // A done
    __syncthreads();

    // hoist Q fragments (identical mapping to gemm_nt's A fragments)
    uint32_t qf[8][4];
    #pragma unroll
    for (int ks = 0; ks < 8; ks++) {
        const int kb8 = ks * 8;
        qf[ks][0] = __float_as_uint(As[r0*68     + kb8     + tg]);
        qf[ks][1] = __float_as_uint(As[(r0+8)*68 + kb8     + tg]);
        qf[ks][2] = __float_as_uint(As[r0*68     + kb8 + 4 + tg]);
        qf[ks][3] = __float_as_uint(As[(r0+8)*68 + kb8 + 4 + tg]);
    }

    for (int ct = 0; ct < 32; ct++) {
        __syncthreads();   // previous stage fully consumed before overwrite
        if (ct + 1 < 32) {
            const float* bsrc = peT + (size_t)(ct + 1) * 64 * DH;
            float* Bn = Bst + ((ct + 1) & 1) * (64 * 68);
            #pragma unroll
            for (int i = tid; i < 1024; i += 256) {
                int r = i >> 4, cc = (i & 15) << 2;
                cp_async16(&Bn[r*68 + cc], bsrc + (size_t)r * DH + cc);
            }
            asm volatile("cp.async.commit_group;\n" ::: "memory");
            asm volatile("cp.async.wait_group 1;\n" ::: "memory");  // stage ct ready
        } else {
            asm volatile("cp.async.wait_group 0;\n" ::: "memory");
        }
        __syncthreads();

        const float* Bs = Bst + (ct & 1) * (64 * 68);

        float s[8][4];
        #pragma unroll
        for (int nt = 0; nt < 8; nt++)
            #pragma unroll
            for (int i = 0; i < 4; i++) s[nt][i] = 0.f;
        #pragma unroll
        for (int ks = 0; ks < 8; ks++) {
            const int kb8 = ks * 8;
            #pragma unroll
            for (int nt = 0; nt < 8; nt++) {
                int j = nt*8 + g;
                uint32_t b0 = __float_as_uint(Bs[j*68 + kb8     + tg]);
                uint32_t b1 = __float_as_uint(Bs[j*68 + kb8 + 4 + tg]);
                mma_tf32(s[nt], qf[ks], b0, b1);
            }
        }

        // store: rows rowBase+r0 (+8), cols ct*64 + nt*8 + 2tg
        float* pr0 = gpos + (rowBase + r0) * (size_t)LWIN + ct * 64;
        float* pr1 = pr0 + (size_t)8 * LWIN;
        #pragma unroll
        for (int nt = 0; nt < 8; nt++) {
            int col = nt*8 + 2*tg;
            pr0[col    ] = s[nt][0];
            pr0[col + 1] = s[nt][1];
            pr1[col    ] = s[nt][2];
            pr1[col + 1] = s[nt][3];
        }
    }
}

// ---------------- flash-style windowed attention (R9-proven) ----------------
__global__ __launch_bounds__(256, 2)
void attn_kernel(const float* __restrict__ gq, const float* __restrict__ gk,
                 const float* __restrict__ gv, const float* __restrict__ gpos,
                 float* __restrict__ gatt)
{
    extern __shared__ float smb[];
    float* Ps = smb + 17920;

    const int bh = blockIdx.x;
    const int m0 = blockIdx.y * QTILE;
    const int tid  = threadIdx.x;
    const int warp = tid >> 5, lane = tid & 31;
    const int g  = lane >> 2, tg = lane & 3;
    const int r0 = warp*16 + g;

    {
        const float* qb = gq + ((size_t)bh * MEMQ + m0) * DH;
        #pragma unroll
        for (int i = tid; i < 2048; i += 256) {
            int r = i >> 4, cc = (i & 15) << 2;
            cp_async16(&Ps[r*68 + cc], qb + r*DH + cc);
        }
    }
    asm volatile("cp.async.commit_group;\n" ::: "memory");

    {
        const float* kb = gk + ((size_t)bh * KVLEN + m0) * DH;
        const float* vb = gv + ((size_t)bh * KVLEN + m0) * DH;
        float* Ks = smb;
        float* Vs = smb + 4352;
        #pragma unroll
        for (int i = tid; i < 1024; i += 256) {
            int r = i >> 4, cc = (i & 15) << 2;
            cp_async16(&Ks[r*68 + cc], kb + r*DH + cc);
            cp_async16(&Vs[r*72 + cc], vb + r*DH + cc);
        }
    }
    asm volatile("cp.async.commit_group;\n" ::: "memory");
    asm volatile("cp.async.wait_group 1;\n" ::: "memory");
    __syncthreads();

    uint32_t qf[8][4];
    #pragma unroll
    for (int ks = 0; ks < 8; ks++) {
        const int kb8 = ks * 8;
        qf[ks][0] = __float_as_uint(Ps[r0*68     + kb8     + tg]);
        qf[ks][1] = __float_as_uint(Ps[(r0+8)*68 + kb8     + tg]);
        qf[ks][2] = __float_as_uint(Ps[r0*68     + kb8 + 4 + tg]);
        qf[ks][3] = __float_as_uint(Ps[(r0+8)*68 + kb8 + 4 + tg]);
    }

    float o[8][4];
    #pragma unroll
    for (int nt = 0; nt < 8; nt++)
        #pragma unroll
        for (int i = 0; i < 4; i++) o[nt][i] = 0.f;
    float mi0 = -1e30f, mi1 = -1e30f, li0 = 0.f, li1 = 0.f;

    const float* posr0 = gpos + ((size_t)bh * MEMQ + m0 + r0) * LWIN;
    const float* posr1 = posr0 + (size_t)8 * LWIN;

    for (int t = 0; t < 34; t++) {
        __syncthreads();
        if (t + 1 < 34) {
            const int j1 = m0 + (t + 1) * 64;
            const float* kb = gk + ((size_t)bh * KVLEN + j1) * DH;
            const float* vb = gv + ((size_t)bh * KVLEN + j1) * DH;
            float* Kn = smb + ((t + 1) & 1) * 8960;
            float* Vn = Kn + 4352;
            #pragma unroll
            for (int i = tid; i < 1024; i += 256) {
                int r = i >> 4, cc = (i & 15) << 2;
                cp_async16(&Kn[r*68 + cc], kb + r*DH + cc);
                cp_async16(&Vn[r*72 + cc], vb + r*DH + cc);
            }
            asm volatile("cp.async.commit_group;\n" ::: "memory");
            asm volatile("cp.async.wait_group 1;\n" ::: "memory");
        } else {
            asm volatile("cp.async.wait_group 0;\n" ::: "memory");
        }
        __syncthreads();

        const float* Ks = smb + (t & 1) * 8960;
        const float* Vs = Ks + 4352;

        float s[8][4];
        #pragma unroll
        for (int nt = 0; nt < 8; nt++)
            #pragma unroll
            for (int i = 0; i < 4; i++) s[nt][i] = 0.f;
        #pragma unroll
        for (int ks = 0; ks < 8; ks++) {
            const int kb8 = ks * 8;
            #pragma unroll
            for (int nt = 0; nt < 8; nt++) {
                int j = nt*8 + g;
                uint32_t b0 = __float_as_uint(Ks[j*68 + kb8     + tg]);
                uint32_t b1 = __float_as_uint(Ks[j*68 + kb8 + 4 + tg]);
                mma_tf32(s[nt], qf[ks], b0, b1);
            }
        }

        #pragma unroll
        for (int nt = 0; nt < 8; nt++) {
            int jj = nt*8 + 2*tg;
            int lA = t*64 + jj - r0;
            int lB = lA - 8;
            #pragma unroll
            for (int e = 0; e < 2; e++) {
                int l1 = lA + e;
                s[nt][e]     = (l1 >= 0 && l1 < LWIN)
                             ? (s[nt][e]     + __ldg(posr0 + l1)) * 0.125f : -1e30f;
                int l2 = lB + e;
                s[nt][2 + e] = (l2 >= 0 && l2 < LWIN)
                             ? (s[nt][2 + e] + __ldg(posr1 + l2)) * 0.125f : -1e30f;
            }
        }

        float mx0 = -1e30f, mx1 = -1e30f;
        #pragma unroll
        for (int nt = 0; nt < 8; nt++) {
            mx0 = fmaxf(mx0, fmaxf(s[nt][0], s[nt][1]));
            mx1 = fmaxf(mx1, fmaxf(s[nt][2], s[nt][3]));
        }
        mx0 = fmaxf(mx0, __shfl_xor_sync(0xffffffffu, mx0, 1));
        mx0 = fmaxf(mx0, __shfl_xor_sync(0xffffffffu, mx0, 2));
        mx1 = fmaxf(mx1, __shfl_xor_sync(0xffffffffu, mx1, 1));
        mx1 = fmaxf(mx1, __shfl_xor_sync(0xffffffffu, mx1, 2));
        float mn0 = fmaxf(mi0, mx0), mn1 = fmaxf(mi1, mx1);
        float al0 = __expf(mi0 - mn0), al1 = __expf(mi1 - mn1);
        float rs0 = 0.f, rs1 = 0.f;
        #pragma unroll
        for (int nt = 0; nt < 8; nt++) {
            s[nt][0] = __expf(s[nt][0] - mn0);
            s[nt][1] = __expf(s[nt][1] - mn0);
            s[nt][2] = __expf(s[nt][2] - mn1);
            s[nt][3] = __expf(s[nt][3] - mn1);
            rs0 += s[nt][0] + s[nt][1];
            rs1 += s[nt][2] + s[nt][3];
        }
        rs0 += __shfl_xor_sync(0xffffffffu, rs0, 1);
        rs0 += __shfl_xor_sync(0xffffffffu, rs0, 2);
        rs1 += __shfl_xor_sync(0xffffffffu, rs1, 1);
        rs1 += __shfl_xor_sync(0xffffffffu, rs1, 2);
        li0 = li0 * al0 + rs0;
        li1 = li1 * al1 + rs1;
        mi0 = mn0; mi1 = mn1;

        #pragma unroll
        for (int nt = 0; nt < 8; nt++) {
            o[nt][0] *= al0; o[nt][1] *= al0; o[nt][2] *= al1; o[nt][3] *= al1;
            int col = nt*8 + 2*tg;
            Ps[r0*68     + col    ] = to_tf32(s[nt][0]);
            Ps[r0*68     + col + 1] = to_tf32(s[nt][1]);
            Ps[(r0+8)*68 + col    ] = to_tf32(s[nt][2]);
            Ps[(r0+8)*68 + col + 1] = to_tf32(s[nt][3]);
        }
        __syncwarp();

        #pragma unroll
        for (int ks = 0; ks < 8; ks++) {
            const int kb8 = ks * 8;
            uint32_t a[4];
            a[0] = __float_as_uint(Ps[r0*68     + kb8     + tg]);
            a[1] = __float_as_uint(Ps[(r0+8)*68 + kb8     + tg]);
            a[2] = __float_as_uint(Ps[r0*68     + kb8 + 4 + tg]);
            a[3] = __float_as_uint(Ps[(r0+8)*68 + kb8 + 4 + tg]);
            #pragma unroll
            for (int nt = 0; nt < 8; nt++) {
                uint32_t b0 = __float_as_uint(Vs[(kb8     + tg)*72 + nt*8 + g]);
                uint32_t b1 = __float_as_uint(Vs[(kb8 + 4 + tg)*72 + nt*8 + g]);
                mma_tf32(o[nt], a, b0, b1);
            }
        }
        __syncwarp();
    }

    const float inv0 = 1.f / li0, inv1 = 1.f / li1;
    const int b = bh >> 4, h = bh & 15;
    #pragma unroll
    for (int nt = 0; nt < 8; nt++) {
        int d = nt*8 + 2*tg;
        size_t i0 = (((size_t)(b*MEMQ + (m0 + r0    )) * NHEADS + h) << 6) + d;
        size_t i1 = (((size_t)(b*MEMQ + (m0 + r0 + 8)) * NHEADS + h) << 6) + d;
        gatt[i0    ] = to_tf32(o[nt][0] * inv0);
        gatt[i0 + 1] = to_tf32(o[nt][1] * inv0);
        gatt[i1    ] = to_tf32(o[nt][2] * inv1);
        gatt[i1 + 1] = to_tf32(o[nt][3] * inv1);
    }
}

// ---------------- launch ----------------
extern "C" void kernel_launch(void* const* d_in, const int* in_sizes, int n_in,
                              void* d_out, int out_size)
{
    const float* query = (const float*)d_in[0];
    const float* key   = (const float*)d_in[1];
    const float* value = (const float*)d_in[2];
    const float* keype = (const float*)d_in[3];
    const float* Wq    = (const float*)d_in[4];
    const float* Wk    = (const float*)d_in[5];
    const float* Wv    = (const float*)d_in[6];
    const float* Wo    = (const float*)d_in[7];
    float* out = (float*)d_out;

    float *pq, *pk, *pv, *ppeT, *ppos, *patt;
    float *pw0, *pw1, *pw2, *pw3;
    cudaGetSymbolAddress((void**)&pq,   g_q);
    cudaGetSymbolAddress((void**)&pk,   g_k);
    cudaGetSymbolAddress((void**)&pv,   g_v);
    cudaGetSymbolAddress((void**)&ppeT, g_peT);
    cudaGetSymbolAddress((void**)&ppos, g_pos);
    cudaGetSymbolAddress((void**)&patt, g_att);
    cudaGetSymbolAddress((void**)&pw0,  g_w0);
    cudaGetSymbolAddress((void**)&pw1,  g_w1);
    cudaGetSymbolAddress((void**)&pw2,  g_w2);
    cudaGetSymbolAddress((void**)&pw3,  g_w3);

    const int gemm_smem = 2 * 2 * GSTAGE * 4;                 // 73728 B
    const int attn_smem = (2 * 8960 + 128 * 68) * 4;          // 106496 B
    const int pos_smem  = (128 * 68 + 2 * 64 * 68) * 4;       // 69632 B
    cudaFuncSetAttribute(gemm_nt, cudaFuncAttributeMaxDynamicSharedMemorySize, gemm_smem);
    cudaFuncSetAttribute(attn_kernel, cudaFuncAttributeMaxDynamicSharedMemorySize, attn_smem);
    cudaFuncSetAttribute(pos_kernel, cudaFuncAttributeMaxDynamicSharedMemorySize, pos_smem);

    const int nw4 = HIDDIM * HIDDIM / 4;
    tf32_cast<<<(nw4 + 255) / 256, 256>>>((const float4*)Wq, (float4*)pw0, nw4);
    tf32_cast<<<(nw4 + 255) / 256, 256>>>((const float4*)Wk, (float4*)pw1, nw4);
    tf32_cast<<<(nw4 + 255) / 256, 256>>>((const float4*)Wv, (float4*)pw2, nw4);
    tf32_cast<<<(nw4 + 255) / 256, 256>>>((const float4*)Wo, (float4*)pw3, nw4);
    transpose_pe<<<512, 256>>>(keype, ppeT);

    gemm_nt<<<dim3(32, 8),  256, gemm_smem>>>(query, HIDDIM, pw0, pq, HIDDIM, 0, 1, MEMQ);
    gemm_nt<<<dim3(160, 8), 256, gemm_smem>>>(key,   HIDDIM, pw1, pk, HIDDIM, 0, 1, KVLEN);
    gemm_nt<<<dim3(160, 8), 256, gemm_smem>>>(value, HIDDIM, pw2, pv, HIDDIM, 0, 1, KVLEN);
    pos_kernel<<<512, 256, pos_smem>>>(pq, ppeT, ppos);
    attn_kernel<<<dim3(BHTOT, 4), 256, attn_smem>>>(pq, pk, pv, ppos, patt);
    gemm_nt<<<dim3(32, 8), 256, gemm_smem>>>(patt, HIDDIM, pw3, out, HIDDIM, HIDDIM, 0, 0);
}

// round 12
// speedup vs baseline: 1.6893x; 1.6893x over previous
#include <cuda_runtime.h>
#include <cuda_fp16.h>
#include <cstdint>
#include <cstddef>

#define HIDDIM 1024
#define NHEADS 16
#define MEMQ   512
#define LWIN   2048
#define KVLEN  2560
#define DH     64
#define NBATCH 8
#define BHTOT  128
#define QTILE  128

// ---------------- scratch ----------------
static __device__ __half g_q  [(size_t)BHTOT * MEMQ  * DH];     // [bh][m][d]
static __device__ __half g_k  [(size_t)BHTOT * KVLEN * DH];     // [bh][j][d]
static __device__ __half g_v  [(size_t)BHTOT * DH * KVLEN];     // [bh][d][j]  (transposed)
static __device__ __half g_peT[(size_t)LWIN * DH];              // [l][d]
static __device__ float  g_pos[(size_t)BHTOT * MEMQ  * LWIN];   // fp32
static __device__ __half g_att[(size_t)NBATCH * MEMQ * HIDDIM]; // [b][m][h][d]
static __device__ __half g_qc [(size_t)NBATCH * MEMQ  * HIDDIM];
static __device__ __half g_kc [(size_t)NBATCH * KVLEN * HIDDIM];
static __device__ __half g_vc [(size_t)NBATCH * KVLEN * HIDDIM];
static __device__ __half g_w0 [(size_t)HIDDIM * HIDDIM];
static __device__ __half g_w1 [(size_t)HIDDIM * HIDDIM];
static __device__ __half g_w2 [(size_t)HIDDIM * HIDDIM];
static __device__ __half g_w3 [(size_t)HIDDIM * HIDDIM];

// ---------------- helpers ----------------
__device__ __forceinline__ uint32_t f2h2(float a, float b){
    __half2 h = __floats2half2_rn(a, b);
    return *reinterpret_cast<uint32_t*>(&h);
}
__device__ __forceinline__ void mma_f16(float c[4], const uint32_t a[4],
                                        uint32_t b0, uint32_t b1){
    asm("mma.sync.aligned.m16n8k16.row.col.f32.f16.f16.f32 "
        "{%0,%1,%2,%3}, {%4,%5,%6,%7}, {%8,%9}, {%0,%1,%2,%3};"
        : "+f"(c[0]), "+f"(c[1]), "+f"(c[2]), "+f"(c[3])
        : "r"(a[0]), "r"(a[1]), "r"(a[2]), "r"(a[3]), "r"(b0), "r"(b1));
}
__device__ __forceinline__ void cp_async16(void* sptr, const void* gptr){
    uint32_t sa = (uint32_t)__cvta_generic_to_shared(sptr);
    asm volatile("cp.async.cg.shared.global [%0], [%1], 16;\n" :: "r"(sa), "l"(gptr));
}
__device__ __forceinline__ uint32_t ldsm_u32(const __half* p){
    return *reinterpret_cast<const uint32_t*>(p);
}

// ---------------- fp32 -> fp16 cast (float4 -> 4 halfs) ----------------
__global__ void half_cast(const float4* __restrict__ src, uint2* __restrict__ dst, int n4){
    int i = blockIdx.x * 256 + threadIdx.x;
    if (i < n4) {
        float4 v = src[i];
        uint2 o;
        o.x = f2h2(v.x, v.y);
        o.y = f2h2(v.z, v.w);
        dst[i] = o;
    }
}

// ---------------- pe transpose -> half ----------------
__global__ void transpose_pe(const float* __restrict__ pe, __half* __restrict__ peT){
    int idx = blockIdx.x * 256 + threadIdx.x;
    int l = idx >> 6;
    int d = idx & 63;
    peT[idx] = __float2half_rn(pe[(size_t)d * LWIN + l]);
}

// ---------------- fp16 pipelined NT GEMM: C[n,j] = sum_c A[n,c]*B[j,c] ----------------
// BM=128 BN=128 BK=64(halfs), 2-stage cp.async. smem stride 72 halfs (conflict-free).
// mode 0: plain f32 store; mode 1: head-split half store; mode 2: head-split TRANSPOSED
// half store to [bh][d][S] (for V).
#define HSTRIDE 72
#define HSTAGE  (256 * HSTRIDE)       // halfs per stage (A rows 0-127, B rows 128-255)

__global__ __launch_bounds__(256, 2)
void gemm_h(const __half* __restrict__ A, int lda,
            const __half* __restrict__ B,
            void* __restrict__ Cv,
            int K, int ldc, int mode, int S)
{
    extern __shared__ __half smh[];

    const int tid  = threadIdx.x;
    const int warp = tid >> 5, lane = tid & 31;
    const int wm = warp >> 2, wn = warp & 3;
    const int g  = lane >> 2, tg = lane & 3;
    const int rowBase = blockIdx.x * 128;
    const int colBase = blockIdx.y * 128;

    float acc[4][4][4];
    #pragma unroll
    for (int mt = 0; mt < 4; mt++)
        #pragma unroll
        for (int nt = 0; nt < 4; nt++)
            #pragma unroll
            for (int i = 0; i < 4; i++) acc[mt][nt][i] = 0.f;

    const int niter = K >> 6;

    auto load_tiles = [&](int st, int k0){
        __half* As = smh + st * HSTAGE;
        __half* Bs = As + 128 * HSTRIDE;
        #pragma unroll
        for (int i = 0; i < 4; i++) {                 // A: 128 rows x 8 chunks
            int c = tid + i * 256;
            int row = c >> 3, ko = c & 7;
            cp_async16(&As[row * HSTRIDE + ko * 8],
                       A + (size_t)(rowBase + row) * lda + k0 + ko * 8);
        }
        #pragma unroll
        for (int i = 0; i < 4; i++) {                 // B: 128 rows x 8 chunks
            int c = tid + i * 256;
            int row = c >> 3, ko = c & 7;
            cp_async16(&Bs[row * HSTRIDE + ko * 8],
                       B + (size_t)(colBase + row) * K + k0 + ko * 8);
        }
    };

    load_tiles(0, 0);
    asm volatile("cp.async.commit_group;\n" ::: "memory");

    for (int it = 0; it < niter; it++) {
        if (it + 1 < niter) load_tiles((it + 1) & 1, (it + 1) << 6);
        asm volatile("cp.async.commit_group;\n" ::: "memory");
        asm volatile("cp.async.wait_group 1;\n" ::: "memory");
        __syncthreads();

        const __half* As = smh + (it & 1) * HSTAGE;
        const __half* Bs = As + 128 * HSTRIDE;

        #pragma unroll
        for (int ks = 0; ks < 4; ks++) {
            const int kb = ks * 16;
            uint32_t a[4][4];
            #pragma unroll
            for (int mt = 0; mt < 4; mt++) {
                int r = wm * 64 + mt * 16 + g;
                a[mt][0] = ldsm_u32(&As[r * HSTRIDE       + kb     + 2*tg]);
                a[mt][1] = ldsm_u32(&As[(r + 8) * HSTRIDE + kb     + 2*tg]);
                a[mt][2] = ldsm_u32(&As[r * HSTRIDE       + kb + 8 + 2*tg]);
                a[mt][3] = ldsm_u32(&As[(r + 8) * HSTRIDE + kb + 8 + 2*tg]);
            }
            #pragma unroll
            for (int nt = 0; nt < 4; nt++) {
                int j = wn * 32 + nt * 8 + g;
                uint32_t b0 = ldsm_u32(&Bs[j * HSTRIDE + kb     + 2*tg]);
                uint32_t b1 = ldsm_u32(&Bs[j * HSTRIDE + kb + 8 + 2*tg]);
                #pragma unroll
                for (int mt = 0; mt < 4; mt++)
                    mma_f16(acc[mt][nt], a[mt], b0, b1);
            }
        }
        __syncthreads();
    }

    #pragma unroll
    for (int mt = 0; mt < 4; mt++) {
        int r = rowBase + wm * 64 + mt * 16 + g;
        #pragma unroll
        for (int nt = 0; nt < 4; nt++) {
            int jc = colBase + wn * 32 + nt * 8 + 2 * tg;
            if (mode == 0) {
                float* C = (float*)Cv;
                C[(size_t)r       * ldc + jc    ] = acc[mt][nt][0];
                C[(size_t)r       * ldc + jc + 1] = acc[mt][nt][1];
                C[(size_t)(r + 8) * ldc + jc    ] = acc[mt][nt][2];
                C[(size_t)(r + 8) * ldc + jc + 1] = acc[mt][nt][3];
            } else {
                __half* C = (__half*)Cv;
                int h = jc >> 6, d = jc & 63;
                int b1r = r / S,  s1 = r - b1r * S;
                int r2  = r + 8;
                int b2r = r2 / S, s2 = r2 - b2r * S;
                if (mode == 1) {
                    __half* p0 = C + (((size_t)(b1r * NHEADS + h) * S + s1) << 6) + d;
                    __half* p1 = C + (((size_t)(b2r * NHEADS + h) * S + s2) << 6) + d;
                    *reinterpret_cast<uint32_t*>(p0) = f2h2(acc[mt][nt][0], acc[mt][nt][1]);
                    *reinterpret_cast<uint32_t*>(p1) = f2h2(acc[mt][nt][2], acc[mt][nt][3]);
                } else {
                    // mode 2: transposed V store -> [bh][d][S]
                    size_t base0 = ((size_t)(b1r * NHEADS + h) * DH + d) * S;
                    size_t base1 = ((size_t)(b2r * NHEADS + h) * DH + d) * S;
                    C[base0 + s1]     = __float2half_rn(acc[mt][nt][0]);
                    C[base0 + S + s1] = __float2half_rn(acc[mt][nt][1]);
                    C[base1 + s2]     = __float2half_rn(acc[mt][nt][2]);
                    C[base1 + S + s2] = __float2half_rn(acc[mt][nt][3]);
                }
            }
        }
    }
}

// ---------------- fp16 pos GEMM: pos[m, l] = q[m,:]·peT[l,:], K=64, fp32 out ----------------
__global__ __launch_bounds__(256, 2)
void pos_kernel(const __half* __restrict__ gq, const __half* __restrict__ peT,
                float* __restrict__ gpos)
{
    extern __shared__ __half sph[];
    __half* As  = sph;                    // 128 x 72
    __half* Bst = sph + 128 * HSTRIDE;    // 2 x (64 x 72)

    const int tid  = threadIdx.x;
    const int warp = tid >> 5, lane = tid & 31;
    const int g  = lane >> 2, tg = lane & 3;
    const int r0 = warp * 16 + g;
    const size_t rowBase = (size_t)blockIdx.x * 128;

    #pragma unroll
    for (int i = tid; i < 1024; i += 256) {       // A: 128 rows x 8 chunks
        int r = i >> 3, ko = i & 7;
        cp_async16(&As[r * HSTRIDE + ko * 8], gq + (rowBase + r) * DH + ko * 8);
    }
    asm volatile("cp.async.commit_group;\n" ::: "memory");

    #pragma unroll
    for (int i = tid; i < 512; i += 256) {        // B tile 0
        int r = i >> 3, ko = i & 7;
        cp_async16(&Bst[r * HSTRIDE + ko * 8], peT + (size_t)r * DH + ko * 8);
    }
    asm volatile("cp.async.commit_group;\n" ::: "memory");
    asm volatile("cp.async.wait_group 1;\n" ::: "memory");
    __syncthreads();

    uint32_t qf[4][4];
    #pragma unroll
    for (int ks = 0; ks < 4; ks++) {
        const int kb = ks * 16;
        qf[ks][0] = ldsm_u32(&As[r0 * HSTRIDE       + kb     + 2*tg]);
        qf[ks][1] = ldsm_u32(&As[(r0+8) * HSTRIDE   + kb     + 2*tg]);
        qf[ks][2] = ldsm_u32(&As[r0 * HSTRIDE       + kb + 8 + 2*tg]);
        qf[ks][3] = ldsm_u32(&As[(r0+8) * HSTRIDE   + kb + 8 + 2*tg]);
    }

    for (int ct = 0; ct < 32; ct++) {
        __syncthreads();
        if (ct + 1 < 32) {
            const __half* bsrc = peT + (size_t)(ct + 1) * 64 * DH;
            __half* Bn = Bst + ((ct + 1) & 1) * (64 * HSTRIDE);
            #pragma unroll
            for (int i = tid; i < 512; i += 256) {
                int r = i >> 3, ko = i & 7;
                cp_async16(&Bn[r * HSTRIDE + ko * 8], bsrc + (size_t)r * DH + ko * 8);
            }
            asm volatile("cp.async.commit_group;\n" ::: "memory");
            asm volatile("cp.async.wait_group 1;\n" ::: "memory");
        } else {
            asm volatile("cp.async.wait_group 0;\n" ::: "memory");
        }
        __syncthreads();

        const __half* Bs = Bst + (ct & 1) * (64 * HSTRIDE);

        float s[8][4];
        #pragma unroll
        for (int nt = 0; nt < 8; nt++)
            #pragma unroll
            for (int i = 0; i < 4; i++) s[nt][i] = 0.f;
        #pragma unroll
        for (int ks = 0; ks < 4; ks++) {
            const int kb = ks * 16;
            #pragma unroll
            for (int nt = 0; nt < 8; nt++) {
                int j = nt*8 + g;
                uint32_t b0 = ldsm_u32(&Bs[j * HSTRIDE + kb     + 2*tg]);
                uint32_t b1 = ldsm_u32(&Bs[j * HSTRIDE + kb + 8 + 2*tg]);
                mma_f16(s[nt], qf[ks], b0, b1);
            }
        }

        float* pr0 = gpos + (rowBase + r0) * (size_t)LWIN + ct * 64;
        float* pr1 = pr0 + (size_t)8 * LWIN;
        #pragma unroll
        for (int nt = 0; nt < 8; nt++) {
            int col = nt*8 + 2*tg;
            pr0[col    ] = s[nt][0];
            pr0[col + 1] = s[nt][1];
            pr1[col    ] = s[nt][2];
            pr1[col + 1] = s[nt][3];
        }
    }
}

// ---------------- fp16 flash attention ----------------
// smem halfs: stage s at s*9216: K 64x72, V(transposed) 64x72; Ps at 18432 (128x72).
__global__ __launch_bounds__(256, 2)
void attn_kernel(const __half* __restrict__ gq, const __half* __restrict__ gk,
                 const __half* __restrict__ gv, const float* __restrict__ gpos,
                 __half* __restrict__ gatt)
{
    extern __shared__ __half smA[];
    __half* Ps = smA + 18432;       // 128 x 72 (also Q staging)

    const int bh = blockIdx.x;
    const int m0 = blockIdx.y * QTILE;
    const int tid  = threadIdx.x;
    const int warp = tid >> 5, lane = tid & 31;
    const int g  = lane >> 2, tg = lane & 3;
    const int r0 = warp*16 + g;

    // stage Q
    {
        const __half* qb = gq + ((size_t)bh * MEMQ + m0) * DH;
        #pragma unroll
        for (int i = tid; i < 1024; i += 256) {
            int r = i >> 3, ko = i & 7;
            cp_async16(&Ps[r * HSTRIDE + ko * 8], qb + r * DH + ko * 8);
        }
    }
    asm volatile("cp.async.commit_group;\n" ::: "memory");

    // prefetch KV tile 0
    {
        const __half* kb = gk + ((size_t)bh * KVLEN + m0) * DH;
        const __half* vb = gv + ((size_t)bh * DH) * KVLEN + m0;   // [d][j] rows
        __half* Ks = smA;
        __half* Vs = smA + 4608;
        #pragma unroll
        for (int i = tid; i < 512; i += 256) {
            int r = i >> 3, ko = i & 7;
            cp_async16(&Ks[r * HSTRIDE + ko * 8], kb + r * DH + ko * 8);
            cp_async16(&Vs[r * HSTRIDE + ko * 8], vb + (size_t)r * KVLEN + ko * 8);
        }
    }
    asm volatile("cp.async.commit_group;\n" ::: "memory");
    asm volatile("cp.async.wait_group 1;\n" ::: "memory");
    __syncthreads();

    uint32_t qf[4][4];
    #pragma unroll
    for (int ks = 0; ks < 4; ks++) {
        const int kb = ks * 16;
        qf[ks][0] = ldsm_u32(&Ps[r0 * HSTRIDE       + kb     + 2*tg]);
        qf[ks][1] = ldsm_u32(&Ps[(r0+8) * HSTRIDE   + kb     + 2*tg]);
        qf[ks][2] = ldsm_u32(&Ps[r0 * HSTRIDE       + kb + 8 + 2*tg]);
        qf[ks][3] = ldsm_u32(&Ps[(r0+8) * HSTRIDE   + kb + 8 + 2*tg]);
    }

    float o[8][4];
    #pragma unroll
    for (int nt = 0; nt < 8; nt++)
        #pragma unroll
        for (int i = 0; i < 4; i++) o[nt][i] = 0.f;
    float mi0 = -1e30f, mi1 = -1e30f, li0 = 0.f, li1 = 0.f;

    const float* posr0 = gpos + ((size_t)bh * MEMQ + m0 + r0) * LWIN;
    const float* posr1 = posr0 + (size_t)8 * LWIN;

    for (int t = 0; t < 34; t++) {
        __syncthreads();
        if (t + 1 < 34) {
            const int j1 = m0 + (t + 1) * 64;
            const __half* kb = gk + ((size_t)bh * KVLEN + j1) * DH;
            const __half* vb = gv + ((size_t)bh * DH) * KVLEN + j1;
            __half* Kn = smA + ((t + 1) & 1) * 9216;
            __half* Vn = Kn + 4608;
            #pragma unroll
            for (int i = tid; i < 512; i += 256) {
                int r = i >> 3, ko = i & 7;
                cp_async16(&Kn[r * HSTRIDE + ko * 8], kb + r * DH + ko * 8);
                cp_async16(&Vn[r * HSTRIDE + ko * 8], vb + (size_t)r * KVLEN + ko * 8);
            }
            asm volatile("cp.async.commit_group;\n" ::: "memory");
            asm volatile("cp.async.wait_group 1;\n" ::: "memory");
        } else {
            asm volatile("cp.async.wait_group 0;\n" ::: "memory");
        }
        __syncthreads();

        const __half* Ks = smA + (t & 1) * 9216;
        const __half* Vs = Ks + 4608;

        // S = Q @ K^T
        float s[8][4];
        #pragma unroll
        for (int nt = 0; nt < 8; nt++)
            #pragma unroll
            for (int i = 0; i < 4; i++) s[nt][i] = 0.f;
        #pragma unroll
        for (int ks = 0; ks < 4; ks++) {
            const int kb = ks * 16;
            #pragma unroll
            for (int nt = 0; nt < 8; nt++) {
                int j = nt*8 + g;
                uint32_t b0 = ldsm_u32(&Ks[j * HSTRIDE + kb     + 2*tg]);
                uint32_t b1 = ldsm_u32(&Ks[j * HSTRIDE + kb + 8 + 2*tg]);
                mma_f16(s[nt], qf[ks], b0, b1);
            }
        }

        // bias + window mask + scale
        #pragma unroll
        for (int nt = 0; nt < 8; nt++) {
            int jj = nt*8 + 2*tg;
            int lA = t*64 + jj - r0;
            int lB = lA - 8;
            #pragma unroll
            for (int e = 0; e < 2; e++) {
                int l1 = lA + e;
                s[nt][e]     = (l1 >= 0 && l1 < LWIN)
                             ? (s[nt][e]     + __ldg(posr0 + l1)) * 0.125f : -1e30f;
                int l2 = lB + e;
                s[nt][2 + e] = (l2 >= 0 && l2 < LWIN)
                             ? (s[nt][2 + e] + __ldg(posr1 + l2)) * 0.125f : -1e30f;
            }
        }

        // online softmax
        float mx0 = -1e30f, mx1 = -1e30f;
        #pragma unroll
        for (int nt = 0; nt < 8; nt++) {
            mx0 = fmaxf(mx0, fmaxf(s[nt][0], s[nt][1]));
            mx1 = fmaxf(mx1, fmaxf(s[nt][2], s[nt][3]));
        }
        mx0 = fmaxf(mx0, __shfl_xor_sync(0xffffffffu, mx0, 1));
        mx0 = fmaxf(mx0, __shfl_xor_sync(0xffffffffu, mx0, 2));
        mx1 = fmaxf(mx1, __shfl_xor_sync(0xffffffffu, mx1, 1));
        mx1 = fmaxf(mx1, __shfl_xor_sync(0xffffffffu, mx1, 2));
        float mn0 = fmaxf(mi0, mx0), mn1 = fmaxf(mi1, mx1);
        float al0 = __expf(mi0 - mn0), al1 = __expf(mi1 - mn1);
        float rs0 = 0.f, rs1 = 0.f;
        #pragma unroll
        for (int nt = 0; nt < 8; nt++) {
            s[nt][0] = __expf(s[nt][0] - mn0);
            s[nt][1] = __expf(s[nt][1] - mn0);
            s[nt][2] = __expf(s[nt][2] - mn1);
            s[nt][3] = __expf(s[nt][3] - mn1);
            rs0 += s[nt][0] + s[nt][1];
            rs1 += s[nt][2] + s[nt][3];
        }
        rs0 += __shfl_xor_sync(0xffffffffu, rs0, 1);
        rs0 += __shfl_xor_sync(0xffffffffu, rs0, 2);
        rs1 += __shfl_xor_sync(0xffffffffu, rs1, 1);
        rs1 += __shfl_xor_sync(0xffffffffu, rs1, 2);
        li0 = li0 * al0 + rs0;
        li1 = li1 * al1 + rs1;
        mi0 = mn0; mi1 = mn1;

        // rescale O, stage P (half2 packs)
        #pragma unroll
        for (int nt = 0; nt < 8; nt++) {
            o[nt][0] *= al0; o[nt][1] *= al0; o[nt][2] *= al1; o[nt][3] *= al1;
            int col = nt*8 + 2*tg;
            *reinterpret_cast<uint32_t*>(&Ps[r0 * HSTRIDE + col])
                = f2h2(s[nt][0], s[nt][1]);
            *reinterpret_cast<uint32_t*>(&Ps[(r0+8) * HSTRIDE + col])
                = f2h2(s[nt][2], s[nt][3]);
        }
        __syncwarp();

        // O += P @ V   (V transposed in smem: row d, col j)
        #pragma unroll
        for (int ks = 0; ks < 4; ks++) {
            const int kb = ks * 16;
            uint32_t a[4];
            a[0] = ldsm_u32(&Ps[r0 * HSTRIDE       + kb     + 2*tg]);
            a[1] = ldsm_u32(&Ps[(r0+8) * HSTRIDE   + kb     + 2*tg]);
            a[2] = ldsm_u32(&Ps[r0 * HSTRIDE       + kb + 8 + 2*tg]);
            a[3] = ldsm_u32(&Ps[(r0+8) * HSTRIDE   + kb + 8 + 2*tg]);
            #pragma unroll
            for (int nt = 0; nt < 8; nt++) {
                int d = nt*8 + g;
                uint32_t b0 = ldsm_u32(&Vs[d * HSTRIDE + kb     + 2*tg]);
                uint32_t b1 = ldsm_u32(&Vs[d * HSTRIDE + kb + 8 + 2*tg]);
                mma_f16(o[nt], a, b0, b1);
            }
        }
        __syncwarp();
    }

    // normalize + write half [B][M][H][D]
    const float inv0 = 1.f / li0, inv1 = 1.f / li1;
    const int b = bh >> 4, h = bh & 15;
    #pragma unroll
    for (int nt = 0; nt < 8; nt++) {
        int d = nt*8 + 2*tg;
        size_t i0 = (((size_t)(b*MEMQ + (m0 + r0    )) * NHEADS + h) << 6) + d;
        size_t i1 = (((size_t)(b*MEMQ + (m0 + r0 + 8)) * NHEADS + h) << 6) + d;
        *reinterpret_cast<uint32_t*>(&gatt[i0]) = f2h2(o[nt][0] * inv0, o[nt][1] * inv0);
        *reinterpret_cast<uint32_t*>(&gatt[i1]) = f2h2(o[nt][2] * inv1, o[nt][3] * inv1);
    }
}

// ---------------- launch ----------------
extern "C" void kernel_launch(void* const* d_in, const int* in_sizes, int n_in,
                              void* d_out, int out_size)
{
    const float* query = (const float*)d_in[0];
    const float* key   = (const float*)d_in[1];
    const float* value = (const float*)d_in[2];
    const float* keype = (const float*)d_in[3];
    const float* Wq    = (const float*)d_in[4];
    const float* Wk    = (const float*)d_in[5];
    const float* Wv    = (const float*)d_in[6];
    const float* Wo    = (const float*)d_in[7];
    float* out = (float*)d_out;

    __half *pq, *pk, *pv, *ppeT, *patt, *pqc, *pkc, *pvc, *pw0, *pw1, *pw2, *pw3;
    float *ppos;
    cudaGetSymbolAddress((void**)&pq,   g_q);
    cudaGetSymbolAddress((void**)&pk,   g_k);
    cudaGetSymbolAddress((void**)&pv,   g_v);
    cudaGetSymbolAddress((void**)&ppeT, g_peT);
    cudaGetSymbolAddress((void**)&ppos, g_pos);
    cudaGetSymbolAddress((void**)&patt, g_att);
    cudaGetSymbolAddress((void**)&pqc,  g_qc);
    cudaGetSymbolAddress((void**)&pkc,  g_kc);
    cudaGetSymbolAddress((void**)&pvc,  g_vc);
    cudaGetSymbolAddress((void**)&pw0,  g_w0);
    cudaGetSymbolAddress((void**)&pw1,  g_w1);
    cudaGetSymbolAddress((void**)&pw2,  g_w2);
    cudaGetSymbolAddress((void**)&pw3,  g_w3);

    const int gemm_smem = 2 * HSTAGE * 2;                     // 73728 B
    const int pos_smem  = (128 * HSTRIDE + 2 * 64 * HSTRIDE) * 2;  // 36864 B
    const int attn_smem = (2 * 9216 + 128 * HSTRIDE) * 2;     // 55296 B
    cudaFuncSetAttribute(gemm_h, cudaFuncAttributeMaxDynamicSharedMemorySize, gemm_smem);
    cudaFuncSetAttribute(pos_kernel, cudaFuncAttributeMaxDynamicSharedMemorySize, pos_smem);
    cudaFuncSetAttribute(attn_kernel, cudaFuncAttributeMaxDynamicSharedMemorySize, attn_smem);

    const int nq4 = NBATCH * MEMQ  * HIDDIM / 4;
    const int nk4 = NBATCH * KVLEN * HIDDIM / 4;
    const int nw4 = HIDDIM * HIDDIM / 4;
    half_cast<<<(nq4 + 255) / 256, 256>>>((const float4*)query, (uint2*)pqc, nq4);
    half_cast<<<(nk4 + 255) / 256, 256>>>((const float4*)key,   (uint2*)pkc, nk4);
    half_cast<<<(nk4 + 255) / 256, 256>>>((const float4*)value, (uint2*)pvc, nk4);
    half_cast<<<(nw4 + 255) / 256, 256>>>((const float4*)Wq, (uint2*)pw0, nw4);
    half_cast<<<(nw4 + 255) / 256, 256>>>((const float4*)Wk, (uint2*)pw1, nw4);
    half_cast<<<(nw4 + 255) / 256, 256>>>((const float4*)Wv, (uint2*)pw2, nw4);
    half_cast<<<(nw4 + 255) / 256, 256>>>((const float4*)Wo, (uint2*)pw3, nw4);
    transpose_pe<<<512, 256>>>(keype, ppeT);

    // projections
    gemm_h<<<dim3(32, 8),  256, gemm_smem>>>(pqc, HIDDIM, pw0, pq, HIDDIM, 0, 1, MEMQ);
    gemm_h<<<dim3(160, 8), 256, gemm_smem>>>(pkc, HIDDIM, pw1, pk, HIDDIM, 0, 1, KVLEN);
    gemm_h<<<dim3(160, 8), 256, gemm_smem>>>(pvc, HIDDIM, pw2, pv, HIDDIM, 0, 2, KVLEN);
    pos_kernel<<<512, 256, pos_smem>>>(pq, ppeT, ppos);
    attn_kernel<<<dim3(BHTOT, 4), 256, attn_smem>>>(pq, pk, pv, ppos, patt);
    // out = att @ Wo^T (f32 output)
    gemm_h<<<dim3(32, 8), 256, gemm_smem>>>(patt, HIDDIM, pw3, out, HIDDIM, HIDDIM, 0, 0);
}

// round 13
// speedup vs baseline: 1.6920x; 1.0016x over previous
#include <cuda_runtime.h>
#include <cuda_fp16.h>
#include <cstdint>
#include <cstddef>

#define HIDDIM 1024
#define NHEADS 16
#define MEMQ   512
#define LWIN   2048
#define KVLEN  2560
#define DH     64
#define NBATCH 8
#define BHTOT  128
#define QTILE  128

// ---------------- scratch ----------------
static __device__ __half g_q  [(size_t)BHTOT * MEMQ  * DH];     // [bh][m][d]
static __device__ __half g_k  [(size_t)BHTOT * KVLEN * DH];     // [bh][j][d]
static __device__ __half g_v  [(size_t)BHTOT * DH * KVLEN];     // [bh][d][j]  (transposed)
static __device__ __half g_peT[(size_t)LWIN * DH];              // [l][d]
static __device__ float  g_pos[(size_t)BHTOT * MEMQ  * LWIN];   // fp32
static __device__ __half g_att[(size_t)NBATCH * MEMQ * HIDDIM]; // [b][m][h][d]
static __device__ __half g_qc [(size_t)NBATCH * MEMQ  * HIDDIM];
static __device__ __half g_kc [(size_t)NBATCH * KVLEN * HIDDIM];
static __device__ __half g_vc [(size_t)NBATCH * KVLEN * HIDDIM];
static __device__ __half g_w0 [(size_t)HIDDIM * HIDDIM];
static __device__ __half g_w1 [(size_t)HIDDIM * HIDDIM];
static __device__ __half g_w2 [(size_t)HIDDIM * HIDDIM];
static __device__ __half g_w3 [(size_t)HIDDIM * HIDDIM];

// ---------------- helpers ----------------
__device__ __forceinline__ uint32_t f2h2(float a, float b){
    __half2 h = __floats2half2_rn(a, b);
    return *reinterpret_cast<uint32_t*>(&h);
}
__device__ __forceinline__ void mma_f16(float c[4], const uint32_t a[4],
                                        uint32_t b0, uint32_t b1){
    asm("mma.sync.aligned.m16n8k16.row.col.f32.f16.f16.f32 "
        "{%0,%1,%2,%3}, {%4,%5,%6,%7}, {%8,%9}, {%0,%1,%2,%3};"
        : "+f"(c[0]), "+f"(c[1]), "+f"(c[2]), "+f"(c[3])
        : "r"(a[0]), "r"(a[1]), "r"(a[2]), "r"(a[3]), "r"(b0), "r"(b1));
}
__device__ __forceinline__ void cp_async16(void* sptr, const void* gptr){
    uint32_t sa = (uint32_t)__cvta_generic_to_shared(sptr);
    asm volatile("cp.async.cg.shared.global [%0], [%1], 16;\n" :: "r"(sa), "l"(gptr));
}
__device__ __forceinline__ uint32_t ldsm_u32(const __half* p){
    return *reinterpret_cast<const uint32_t*>(p);
}

// ---------------- fp32 -> fp16 cast (float4 -> 4 halfs) ----------------
__global__ void half_cast(const float4* __restrict__ src, uint2* __restrict__ dst, int n4){
    int i = blockIdx.x * 256 + threadIdx.x;
    if (i < n4) {
        float4 v = src[i];
        uint2 o;
        o.x = f2h2(v.x, v.y);
        o.y = f2h2(v.z, v.w);
        dst[i] = o;
    }
}

// ---------------- pe transpose -> half ----------------
__global__ void transpose_pe(const float* __restrict__ pe, __half* __restrict__ peT){
    int idx = blockIdx.x * 256 + threadIdx.x;
    int l = idx >> 6;
    int d = idx & 63;
    peT[idx] = __float2half_rn(pe[(size_t)d * LWIN + l]);
}

// ---------------- fp16 pipelined NT GEMM: C[n,j] = sum_c A[n,c]*B[j,c] ----------------
// BM=128 BN=128 BK=64(halfs), 2-stage cp.async. smem stride 72 halfs (conflict-free).
// mode 0: plain f32 store; mode 1: head-split half store; mode 2: head-split TRANSPOSED
// half store to [bh][d][S] (for V).
#define HSTRIDE 72
#define HSTAGE  (256 * HSTRIDE)       // halfs per stage (A rows 0-127, B rows 128-255)

__global__ __launch_bounds__(256, 2)
void gemm_h(const __half* __restrict__ A, int lda,
            const __half* __restrict__ B,
            void* __restrict__ Cv,
            int K, int ldc, int mode, int S)
{
    extern __shared__ __half smh[];

    const int tid  = threadIdx.x;
    const int warp = tid >> 5, lane = tid & 31;
    const int wm = warp >> 2, wn = warp & 3;
    const int g  = lane >> 2, tg = lane & 3;
    const int rowBase = blockIdx.x * 128;
    const int colBase = blockIdx.y * 128;

    float acc[4][4][4];
    #pragma unroll
    for (int mt = 0; mt < 4; mt++)
        #pragma unroll
        for (int nt = 0; nt < 4; nt++)
            #pragma unroll
            for (int i = 0; i < 4; i++) acc[mt][nt][i] = 0.f;

    const int niter = K >> 6;

    auto load_tiles = [&](int st, int k0){
        __half* As = smh + st * HSTAGE;
        __half* Bs = As + 128 * HSTRIDE;
        #pragma unroll
        for (int i = 0; i < 4; i++) {                 // A: 128 rows x 8 chunks
            int c = tid + i * 256;
            int row = c >> 3, ko = c & 7;
            cp_async16(&As[row * HSTRIDE + ko * 8],
                       A + (size_t)(rowBase + row) * lda + k0 + ko * 8);
        }
        #pragma unroll
        for (int i = 0; i < 4; i++) {                 // B: 128 rows x 8 chunks
            int c = tid + i * 256;
            int row = c >> 3, ko = c & 7;
            cp_async16(&Bs[row * HSTRIDE + ko * 8],
                       B + (size_t)(colBase + row) * K + k0 + ko * 8);
        }
    };

    load_tiles(0, 0);
    asm volatile("cp.async.commit_group;\n" ::: "memory");

    for (int it = 0; it < niter; it++) {
        if (it + 1 < niter) load_tiles((it + 1) & 1, (it + 1) << 6);
        asm volatile("cp.async.commit_group;\n" ::: "memory");
        asm volatile("cp.async.wait_group 1;\n" ::: "memory");
        __syncthreads();

        const __half* As = smh + (it & 1) * HSTAGE;
        const __half* Bs = As + 128 * HSTRIDE;

        #pragma unroll
        for (int ks = 0; ks < 4; ks++) {
            const int kb = ks * 16;
            uint32_t a[4][4];
            #pragma unroll
            for (int mt = 0; mt < 4; mt++) {
                int r = wm * 64 + mt * 16 + g;
                a[mt][0] = ldsm_u32(&As[r * HSTRIDE       + kb     + 2*tg]);
                a[mt][1] = ldsm_u32(&As[(r + 8) * HSTRIDE + kb     + 2*tg]);
                a[mt][2] = ldsm_u32(&As[r * HSTRIDE       + kb + 8 + 2*tg]);
                a[mt][3] = ldsm_u32(&As[(r + 8) * HSTRIDE + kb + 8 + 2*tg]);
            }
            #pragma unroll
            for (int nt = 0; nt < 4; nt++) {
                int j = wn * 32 + nt * 8 + g;
                uint32_t b0 = ldsm_u32(&Bs[j * HSTRIDE + kb     + 2*tg]);
                uint32_t b1 = ldsm_u32(&Bs[j * HSTRIDE + kb + 8 + 2*tg]);
                #pragma unroll
                for (int mt = 0; mt < 4; mt++)
                    mma_f16(acc[mt][nt], a[mt], b0, b1);
            }
        }
        __syncthreads();
    }

    #pragma unroll
    for (int mt = 0; mt < 4; mt++) {
        int r = rowBase + wm * 64 + mt * 16 + g;
        #pragma unroll
        for (int nt = 0; nt < 4; nt++) {
            int jc = colBase + wn * 32 + nt * 8 + 2 * tg;
            if (mode == 0) {
                float* C = (float*)Cv;
                C[(size_t)r       * ldc + jc    ] = acc[mt][nt][0];
                C[(size_t)r       * ldc + jc + 1] = acc[mt][nt][1];
                C[(size_t)(r + 8) * ldc + jc    ] = acc[mt][nt][2];
                C[(size_t)(r + 8) * ldc + jc + 1] = acc[mt][nt][3];
            } else {
                __half* C = (__half*)Cv;
                int h = jc >> 6, d = jc & 63;
                int b1r = r / S,  s1 = r - b1r * S;
                int r2  = r + 8;
                int b2r = r2 / S, s2 = r2 - b2r * S;
                if (mode == 1) {
                    __half* p0 = C + (((size_t)(b1r * NHEADS + h) * S + s1) << 6) + d;
                    __half* p1 = C + (((size_t)(b2r * NHEADS + h) * S + s2) << 6) + d;
                    *reinterpret_cast<uint32_t*>(p0) = f2h2(acc[mt][nt][0], acc[mt][nt][1]);
                    *reinterpret_cast<uint32_t*>(p1) = f2h2(acc[mt][nt][2], acc[mt][nt][3]);
                } else {
                    // mode 2: transposed V store -> [bh][d][S]
                    size_t base0 = ((size_t)(b1r * NHEADS + h) * DH + d) * S;
                    size_t base1 = ((size_t)(b2r * NHEADS + h) * DH + d) * S;
                    C[base0 + s1]     = __float2half_rn(acc[mt][nt][0]);
                    C[base0 + S + s1] = __float2half_rn(acc[mt][nt][1]);
                    C[base1 + s2]     = __float2half_rn(acc[mt][nt][2]);
                    C[base1 + S + s2] = __float2half_rn(acc[mt][nt][3]);
                }
            }
        }
    }
}

// ---------------- fp16 pos GEMM: pos[m, l] = q[m,:]·peT[l,:], K=64, fp32 out ----------------
__global__ __launch_bounds__(256, 2)
void pos_kernel(const __half* __restrict__ gq, const __half* __restrict__ peT,
                float* __restrict__ gpos)
{
    extern __shared__ __half sph[];
    __half* As  = sph;                    // 128 x 72
    __half* Bst = sph + 128 * HSTRIDE;    // 2 x (64 x 72)

    const int tid  = threadIdx.x;
    const int warp = tid >> 5, lane = tid & 31;
    const int g  = lane >> 2, tg = lane & 3;
    const int r0 = warp * 16 + g;
    const size_t rowBase = (size_t)blockIdx.x * 128;

    #pragma unroll
    for (int i = tid; i < 1024; i += 256) {       // A: 128 rows x 8 chunks
        int r = i >> 3, ko = i & 7;
        cp_async16(&As[r * HSTRIDE + ko * 8], gq + (rowBase + r) * DH + ko * 8);
    }
    asm volatile("cp.async.commit_group;\n" ::: "memory");

    #pragma unroll
    for (int i = tid; i < 512; i += 256) {        // B tile 0
        int r = i >> 3, ko = i & 7;
        cp_async16(&Bst[r * HSTRIDE + ko * 8], peT + (size_t)r * DH + ko * 8);
    }
    asm volatile("cp.async.commit_group;\n" ::: "memory");
    asm volatile("cp.async.wait_group 1;\n" ::: "memory");
    __syncthreads();

    uint32_t qf[4][4];
    #pragma unroll
    for (int ks = 0; ks < 4; ks++) {
        const int kb = ks * 16;
        qf[ks][0] = ldsm_u32(&As[r0 * HSTRIDE       + kb     + 2*tg]);
        qf[ks][1] = ldsm_u32(&As[(r0+8) * HSTRIDE   + kb     + 2*tg]);
        qf[ks][2] = ldsm_u32(&As[r0 * HSTRIDE       + kb + 8 + 2*tg]);
        qf[ks][3] = ldsm_u32(&As[(r0+8) * HSTRIDE   + kb + 8 + 2*tg]);
    }

    for (int ct = 0; ct < 32; ct++) {
        __syncthreads();
        if (ct + 1 < 32) {
            const __half* bsrc = peT + (size_t)(ct + 1) * 64 * DH;
            __half* Bn = Bst + ((ct + 1) & 1) * (64 * HSTRIDE);
            #pragma unroll
            for (int i = tid; i < 512; i += 256) {
                int r = i >> 3, ko = i & 7;
                cp_async16(&Bn[r * HSTRIDE + ko * 8], bsrc + (size_t)r * DH + ko * 8);
            }
            asm volatile("cp.async.commit_group;\n" ::: "memory");
            asm volatile("cp.async.wait_group 1;\n" ::: "memory");
        } else {
            asm volatile("cp.async.wait_group 0;\n" ::: "memory");
        }
        __syncthreads();

        const __half* Bs = Bst + (ct & 1) * (64 * HSTRIDE);

        float s[8][4];
        #pragma unroll
        for (int nt = 0; nt < 8; nt++)
            #pragma unroll
            for (int i = 0; i < 4; i++) s[nt][i] = 0.f;
        #pragma unroll
        for (int ks = 0; ks < 4; ks++) {
            const int kb = ks * 16;
            #pragma unroll
            for (int nt = 0; nt < 8; nt++) {
                int j = nt*8 + g;
                uint32_t b0 = ldsm_u32(&Bs[j * HSTRIDE + kb     + 2*tg]);
                uint32_t b1 = ldsm_u32(&Bs[j * HSTRIDE + kb + 8 + 2*tg]);
                mma_f16(s[nt], qf[ks], b0, b1);
            }
        }

        float* pr0 = gpos + (rowBase + r0) * (size_t)LWIN + ct * 64;
        float* pr1 = pr0 + (size_t)8 * LWIN;
        #pragma unroll
        for (int nt = 0; nt < 8; nt++) {
            int col = nt*8 + 2*tg;
            pr0[col    ] = s[nt][0];
            pr0[col + 1] = s[nt][1];
            pr1[col    ] = s[nt][2];
            pr1[col + 1] = s[nt][3];
        }
    }
}

// ---------------- fp16 flash attention ----------------
// smem halfs: stage s at s*9216: K 64x72, V(transposed) 64x72; Ps at 18432 (128x72).
__global__ __launch_bounds__(256, 2)
void attn_kernel(const __half* __restrict__ gq, const __half* __restrict__ gk,
                 const __half* __restrict__ gv, const float* __restrict__ gpos,
                 __half* __restrict__ gatt)
{
    extern __shared__ __half smA[];
    __half* Ps = smA + 18432;       // 128 x 72 (also Q staging)

    const int bh = blockIdx.x;
    const int m0 = blockIdx.y * QTILE;
    const int tid  = threadIdx.x;
    const int warp = tid >> 5, lane = tid & 31;
    const int g  = lane >> 2, tg = lane & 3;
    const int r0 = warp*16 + g;

    // stage Q
    {
        const __half* qb = gq + ((size_t)bh * MEMQ + m0) * DH;
        #pragma unroll
        for (int i = tid; i < 1024; i += 256) {
            int r = i >> 3, ko = i & 7;
            cp_async16(&Ps[r * HSTRIDE + ko * 8], qb + r * DH + ko * 8);
        }
    }
    asm volatile("cp.async.commit_group;\n" ::: "memory");

    // prefetch KV tile 0
    {
        const __half* kb = gk + ((size_t)bh * KVLEN + m0) * DH;
        const __half* vb = gv + ((size_t)bh * DH) * KVLEN + m0;   // [d][j] rows
        __half* Ks = smA;
        __half* Vs = smA + 4608;
        #pragma unroll
        for (int i = tid; i < 512; i += 256) {
            int r = i >> 3, ko = i & 7;
            cp_async16(&Ks[r * HSTRIDE + ko * 8], kb + r * DH + ko * 8);
            cp_async16(&Vs[r * HSTRIDE + ko * 8], vb + (size_t)r * KVLEN + ko * 8);
        }
    }
    asm volatile("cp.async.commit_group;\n" ::: "memory");
    asm volatile("cp.async.wait_group 1;\n" ::: "memory");
    __syncthreads();

    uint32_t qf[4][4];
    #pragma unroll
    for (int ks = 0; ks < 4; ks++) {
        const int kb = ks * 16;
        qf[ks][0] = ldsm_u32(&Ps[r0 * HSTRIDE       + kb     + 2*tg]);
        qf[ks][1] = ldsm_u32(&Ps[(r0+8) * HSTRIDE   + kb     + 2*tg]);
        qf[ks][2] = ldsm_u32(&Ps[r0 * HSTRIDE       + kb + 8 + 2*tg]);
        qf[ks][3] = ldsm_u32(&Ps[(r0+8) * HSTRIDE   + kb + 8 + 2*tg]);
    }

    float o[8][4];
    #pragma unroll
    for (int nt = 0; nt < 8; nt++)
        #pragma unroll
        for (int i = 0; i < 4; i++) o[nt][i] = 0.f;
    float mi0 = -1e30f, mi1 = -1e30f, li0 = 0.f, li1 = 0.f;

    const float* posr0 = gpos + ((size_t)bh * MEMQ + m0 + r0) * LWIN;
    const float* posr1 = posr0 + (size_t)8 * LWIN;

    for (int t = 0; t < 34; t++) {
        __syncthreads();
        if (t + 1 < 34) {
            const int j1 = m0 + (t + 1) * 64;
            const __half* kb = gk + ((size_t)bh * KVLEN + j1) * DH;
            const __half* vb = gv + ((size_t)bh * DH) * KVLEN + j1;
            __half* Kn = smA + ((t + 1) & 1) * 9216;
            __half* Vn = Kn + 4608;
            #pragma unroll
            for (int i = tid; i < 512; i += 256) {
                int r = i >> 3, ko = i & 7;
                cp_async16(&Kn[r * HSTRIDE + ko * 8], kb + r * DH + ko * 8);
                cp_async16(&Vn[r * HSTRIDE + ko * 8], vb + (size_t)r * KVLEN + ko * 8);
            }
            asm volatile("cp.async.commit_group;\n" ::: "memory");
            asm volatile("cp.async.wait_group 1;\n" ::: "memory");
        } else {
            asm volatile("cp.async.wait_group 0;\n" ::: "memory");
        }
        __syncthreads();

        const __half* Ks = smA + (t & 1) * 9216;
        const __half* Vs = Ks + 4608;

        // S = Q @ K^T
        float s[8][4];
        #pragma unroll
        for (int nt = 0; nt < 8; nt++)
            #pragma unroll
            for (int i = 0; i < 4; i++) s[nt][i] = 0.f;
        #pragma unroll
        for (int ks = 0; ks < 4; ks++) {
            const int kb = ks * 16;
            #pragma unroll
            for (int nt = 0; nt < 8; nt++) {
                int j = nt*8 + g;
                uint32_t b0 = ldsm_u32(&Ks[j * HSTRIDE + kb     + 2*tg]);
                uint32_t b1 = ldsm_u32(&Ks[j * HSTRIDE + kb + 8 + 2*tg]);
                mma_f16(s[nt], qf[ks], b0, b1);
            }
        }

        // bias + window mask + scale
        #pragma unroll
        for (int nt = 0; nt < 8; nt++) {
            int jj = nt*8 + 2*tg;
            int lA = t*64 + jj - r0;
            int lB = lA - 8;
            #pragma unroll
            for (int e = 0; e < 2; e++) {
                int l1 = lA + e;
                s[nt][e]     = (l1 >= 0 && l1 < LWIN)
                             ? (s[nt][e]     + __ldg(posr0 + l1)) * 0.125f : -1e30f;
                int l2 = lB + e;
                s[nt][2 + e] = (l2 >= 0 && l2 < LWIN)
                             ? (s[nt][2 + e] + __ldg(posr1 + l2)) * 0.125f : -1e30f;
            }
        }

        // online softmax
        float mx0 = -1e30f, mx1 = -1e30f;
        #pragma unroll
        for (int nt = 0; nt < 8; nt++) {
            mx0 = fmaxf(mx0, fmaxf(s[nt][0], s[nt][1]));
            mx1 = fmaxf(mx1, fmaxf(s[nt][2], s[nt][3]));
        }
        mx0 = fmaxf(mx0, __shfl_xor_sync(0xffffffffu, mx0, 1));
        mx0 = fmaxf(mx0, __shfl_xor_sync(0xffffffffu, mx0, 2));
        mx1 = fmaxf(mx1, __shfl_xor_sync(0xffffffffu, mx1, 1));
        mx1 = fmaxf(mx1, __shfl_xor_sync(0xffffffffu, mx1, 2));
        float mn0 = fmaxf(mi0, mx0), mn1 = fmaxf(mi1, mx1);
        float al0 = __expf(mi0 - mn0), al1 = __expf(mi1 - mn1);
        float rs0 = 0.f, rs1 = 0.f;
        #pragma unroll
        for (int nt = 0; nt < 8; nt++) {
            s[nt][0] = __expf(s[nt][0] - mn0);
            s[nt][1] = __expf(s[nt][1] - mn0);
            s[nt][2] = __expf(s[nt][2] - mn1);
            s[nt][3] = __expf(s[nt][3] - mn1);
            rs0 += s[nt][0] + s[nt][1];
            rs1 += s[nt][2] + s[nt][3];
        }
        rs0 += __shfl_xor_sync(0xffffffffu, rs0, 1);
        rs0 += __shfl_xor_sync(0xffffffffu, rs0, 2);
        rs1 += __shfl_xor_sync(0xffffffffu, rs1, 1);
        rs1 += __shfl_xor_sync(0xffffffffu, rs1, 2);
        li0 = li0 * al0 + rs0;
        li1 = li1 * al1 + rs1;
        mi0 = mn0; mi1 = mn1;

        // rescale O, stage P (half2 packs)
        #pragma unroll
        for (int nt = 0; nt < 8; nt++) {
            o[nt][0] *= al0; o[nt][1] *= al0; o[nt][2] *= al1; o[nt][3] *= al1;
            int col = nt*8 + 2*tg;
            *reinterpret_cast<uint32_t*>(&Ps[r0 * HSTRIDE + col])
                = f2h2(s[nt][0], s[nt][1]);
            *reinterpret_cast<uint32_t*>(&Ps[(r0+8) * HSTRIDE + col])
                = f2h2(s[nt][2], s[nt][3]);
        }
        __syncwarp();

        // O += P @ V   (V transposed in smem: row d, col j)
        #pragma unroll
        for (int ks = 0; ks < 4; ks++) {
            const int kb = ks * 16;
            uint32_t a[4];
            a[0] = ldsm_u32(&Ps[r0 * HSTRIDE       + kb     + 2*tg]);
            a[1] = ldsm_u32(&Ps[(r0+8) * HSTRIDE   + kb     + 2*tg]);
            a[2] = ldsm_u32(&Ps[r0 * HSTRIDE       + kb + 8 + 2*tg]);
            a[3] = ldsm_u32(&Ps[(r0+8) * HSTRIDE   + kb + 8 + 2*tg]);
            #pragma unroll
            for (int nt = 0; nt < 8; nt++) {
                int d = nt*8 + g;
                uint32_t b0 = ldsm_u32(&Vs[d * HSTRIDE + kb     + 2*tg]);
                uint32_t b1 = ldsm_u32(&Vs[d * HSTRIDE + kb + 8 + 2*tg]);
                mma_f16(o[nt], a, b0, b1);
            }
        }
        __syncwarp();
    }

    // normalize + write half [B][M][H][D]
    const float inv0 = 1.f / li0, inv1 = 1.f / li1;
    const int b = bh >> 4, h = bh & 15;
    #pragma unroll
    for (int nt = 0; nt < 8; nt++) {
        int d = nt*8 + 2*tg;
        size_t i0 = (((size_t)(b*MEMQ + (m0 + r0    )) * NHEADS + h) << 6) + d;
        size_t i1 = (((size_t)(b*MEMQ + (m0 + r0 + 8)) * NHEADS + h) << 6) + d;
        *reinterpret_cast<uint32_t*>(&gatt[i0]) = f2h2(o[nt][0] * inv0, o[nt][1] * inv0);
        *reinterpret_cast<uint32_t*>(&gatt[i1]) = f2h2(o[nt][2] * inv1, o[nt][3] * inv1);
    }
}

// ---------------- launch ----------------
extern "C" void kernel_launch(void* const* d_in, const int* in_sizes, int n_in,
                              void* d_out, int out_size)
{
    const float* query = (const float*)d_in[0];
    const float* key   = (const float*)d_in[1];
    const float* value = (const float*)d_in[2];
    const float* keype = (const float*)d_in[3];
    const float* Wq    = (const float*)d_in[4];
    const float* Wk    = (const float*)d_in[5];
    const float* Wv    = (const float*)d_in[6];
    const float* Wo    = (const float*)d_in[7];
    float* out = (float*)d_out;

    __half *pq, *pk, *pv, *ppeT, *patt, *pqc, *pkc, *pvc, *pw0, *pw1, *pw2, *pw3;
    float *ppos;
    cudaGetSymbolAddress((void**)&pq,   g_q);
    cudaGetSymbolAddress((void**)&pk,   g_k);
    cudaGetSymbolAddress((void**)&pv,   g_v);
    cudaGetSymbolAddress((void**)&ppeT, g_peT);
    cudaGetSymbolAddress((void**)&ppos, g_pos);
    cudaGetSymbolAddress((void**)&patt, g_att);
    cudaGetSymbolAddress((void**)&pqc,  g_qc);
    cudaGetSymbolAddress((void**)&pkc,  g_kc);
    cudaGetSymbolAddress((void**)&pvc,  g_vc);
    cudaGetSymbolAddress((void**)&pw0,  g_w0);
    cudaGetSymbolAddress((void**)&pw1,  g_w1);
    cudaGetSymbolAddress((void**)&pw2,  g_w2);
    cudaGetSymbolAddress((void**)&pw3,  g_w3);

    const int gemm_smem = 2 * HSTAGE * 2;                     // 73728 B
    const int pos_smem  = (128 * HSTRIDE + 2 * 64 * HSTRIDE) * 2;  // 36864 B
    const int attn_smem = (2 * 9216 + 128 * HSTRIDE) * 2;     // 55296 B
    cudaFuncSetAttribute(gemm_h, cudaFuncAttributeMaxDynamicSharedMemorySize, gemm_smem);
    cudaFuncSetAttribute(pos_kernel, cudaFuncAttributeMaxDynamicSharedMemorySize, pos_smem);
    cudaFuncSetAttribute(attn_kernel, cudaFuncAttributeMaxDynamicSharedMemorySize, attn_smem);

    const int nq4 = NBATCH * MEMQ  * HIDDIM / 4;
    const int nk4 = NBATCH * KVLEN * HIDDIM / 4;
    const int nw4 = HIDDIM * HIDDIM / 4;
    half_cast<<<(nq4 + 255) / 256, 256>>>((const float4*)query, (uint2*)pqc, nq4);
    half_cast<<<(nk4 + 255) / 256, 256>>>((const float4*)key,   (uint2*)pkc, nk4);
    half_cast<<<(nk4 + 255) / 256, 256>>>((const float4*)value, (uint2*)pvc, nk4);
    half_cast<<<(nw4 + 255) / 256, 256>>>((const float4*)Wq, (uint2*)pw0, nw4);
    half_cast<<<(nw4 + 255) / 256, 256>>>((const float4*)Wk, (uint2*)pw1, nw4);
    half_cast<<<(nw4 + 255) / 256, 256>>>((const float4*)Wv, (uint2*)pw2, nw4);
    half_cast<<<(nw4 + 255) / 256, 256>>>((const float4*)Wo, (uint2*)pw3, nw4);
    transpose_pe<<<512, 256>>>(keype, ppeT);

    // projections
    gemm_h<<<dim3(32, 8),  256, gemm_smem>>>(pqc, HIDDIM, pw0, pq, HIDDIM, 0, 1, MEMQ);
    gemm_h<<<dim3(160, 8), 256, gemm_smem>>>(pkc, HIDDIM, pw1, pk, HIDDIM, 0, 1, KVLEN);
    gemm_h<<<dim3(160, 8), 256, gemm_smem>>>(pvc, HIDDIM, pw2, pv, HIDDIM, 0, 2, KVLEN);
    pos_kernel<<<512, 256, pos_smem>>>(pq, ppeT, ppos);
    attn_kernel<<<dim3(BHTOT, 4), 256, attn_smem>>>(pq, pk, pv, ppos, patt);
    // out = att @ Wo^T (f32 output)
    gemm_h<<<dim3(32, 8), 256, gemm_smem>>>(patt, HIDDIM, pw3, out, HIDDIM, HIDDIM, 0, 0);
}

// round 14
// speedup vs baseline: 1.7784x; 1.0511x over previous
#include <cuda_runtime.h>
#include <cuda_fp16.h>
#include <cstdint>
#include <cstddef>

#define HIDDIM 1024
#define NHEADS 16
#define MEMQ   512
#define LWIN   2048
#define KVLEN  2560
#define DH     64
#define NBATCH 8
#define BHTOT  128
#define QTILE  128

// ---------------- scratch ----------------
static __device__ __half g_q  [(size_t)BHTOT * MEMQ  * DH];     // [bh][m][d]
static __device__ __half g_k  [(size_t)BHTOT * KVLEN * DH];     // [bh][j][d]
static __device__ __half g_v  [(size_t)BHTOT * DH * KVLEN];     // [bh][d][j]  (transposed)
static __device__ __half g_peT[(size_t)LWIN * DH];              // [l][d]
static __device__ __half g_pos[(size_t)BHTOT * MEMQ  * LWIN];   // fp16 (halved traffic)
static __device__ __half g_att[(size_t)NBATCH * MEMQ * HIDDIM]; // [b][m][h][d]
static __device__ __half g_qc [(size_t)NBATCH * MEMQ  * HIDDIM];
static __device__ __half g_kc [(size_t)NBATCH * KVLEN * HIDDIM];
static __device__ __half g_vc [(size_t)NBATCH * KVLEN * HIDDIM];
static __device__ __half g_w0 [(size_t)HIDDIM * HIDDIM];
static __device__ __half g_w1 [(size_t)HIDDIM * HIDDIM];
static __device__ __half g_w2 [(size_t)HIDDIM * HIDDIM];
static __device__ __half g_w3 [(size_t)HIDDIM * HIDDIM];

// ---------------- helpers ----------------
__device__ __forceinline__ uint32_t f2h2(float a, float b){
    __half2 h = __floats2half2_rn(a, b);
    return *reinterpret_cast<uint32_t*>(&h);
}
__device__ __forceinline__ void mma_f16(float c[4], const uint32_t a[4],
                                        uint32_t b0, uint32_t b1){
    asm("mma.sync.aligned.m16n8k16.row.col.f32.f16.f16.f32 "
        "{%0,%1,%2,%3}, {%4,%5,%6,%7}, {%8,%9}, {%0,%1,%2,%3};"
        : "+f"(c[0]), "+f"(c[1]), "+f"(c[2]), "+f"(c[3])
        : "r"(a[0]), "r"(a[1]), "r"(a[2]), "r"(a[3]), "r"(b0), "r"(b1));
}
__device__ __forceinline__ void cp_async16(void* sptr, const void* gptr){
    uint32_t sa = (uint32_t)__cvta_generic_to_shared(sptr);
    asm volatile("cp.async.cg.shared.global [%0], [%1], 16;\n" :: "r"(sa), "l"(gptr));
}
__device__ __forceinline__ uint32_t ldsm_u32(const __half* p){
    return *reinterpret_cast<const uint32_t*>(p);
}

// ---------------- fp32 -> fp16 cast (float4 -> 4 halfs) ----------------
__global__ void half_cast(const float4* __restrict__ src, uint2* __restrict__ dst, int n4){
    int i = blockIdx.x * 256 + threadIdx.x;
    if (i < n4) {
        float4 v = src[i];
        uint2 o;
        o.x = f2h2(v.x, v.y);
        o.y = f2h2(v.z, v.w);
        dst[i] = o;
    }
}

// merged cast of the four 1024x1024 weight matrices (one launch)
__global__ void w4_cast(const float4* __restrict__ s0, const float4* __restrict__ s1,
                        const float4* __restrict__ s2, const float4* __restrict__ s3,
                        uint2* __restrict__ d0, uint2* __restrict__ d1,
                        uint2* __restrict__ d2, uint2* __restrict__ d3, int n4){
    int i = blockIdx.x * 256 + threadIdx.x;
    int m = i / n4, r = i - m * n4;
    const float4* s = (m == 0) ? s0 : (m == 1) ? s1 : (m == 2) ? s2 : s3;
    uint2*       d  = (m == 0) ? d0 : (m == 1) ? d1 : (m == 2) ? d2 : d3;
    float4 v = s[r];
    uint2 o;
    o.x = f2h2(v.x, v.y);
    o.y = f2h2(v.z, v.w);
    d[r] = o;
}

// ---------------- pe transpose -> half ----------------
__global__ void transpose_pe(const float* __restrict__ pe, __half* __restrict__ peT){
    int idx = blockIdx.x * 256 + threadIdx.x;
    int l = idx >> 6;
    int d = idx & 63;
    peT[idx] = __float2half_rn(pe[(size_t)d * LWIN + l]);
}

// ---------------- fp16 pipelined NT GEMM ----------------
#define HSTRIDE 72
#define HSTAGE  (256 * HSTRIDE)

__global__ __launch_bounds__(256, 2)
void gemm_h(const __half* __restrict__ A, int lda,
            const __half* __restrict__ B,
            void* __restrict__ Cv,
            int K, int ldc, int mode, int S)
{
    extern __shared__ __half smh[];

    const int tid  = threadIdx.x;
    const int warp = tid >> 5, lane = tid & 31;
    const int wm = warp >> 2, wn = warp & 3;
    const int g  = lane >> 2, tg = lane & 3;
    const int rowBase = blockIdx.x * 128;
    const int colBase = blockIdx.y * 128;

    float acc[4][4][4];
    #pragma unroll
    for (int mt = 0; mt < 4; mt++)
        #pragma unroll
        for (int nt = 0; nt < 4; nt++)
            #pragma unroll
            for (int i = 0; i < 4; i++) acc[mt][nt][i] = 0.f;

    const int niter = K >> 6;

    auto load_tiles = [&](int st, int k0){
        __half* As = smh + st * HSTAGE;
        __half* Bs = As + 128 * HSTRIDE;
        #pragma unroll
        for (int i = 0; i < 4; i++) {
            int c = tid + i * 256;
            int row = c >> 3, ko = c & 7;
            cp_async16(&As[row * HSTRIDE + ko * 8],
                       A + (size_t)(rowBase + row) * lda + k0 + ko * 8);
        }
        #pragma unroll
        for (int i = 0; i < 4; i++) {
            int c = tid + i * 256;
            int row = c >> 3, ko = c & 7;
            cp_async16(&Bs[row * HSTRIDE + ko * 8],
                       B + (size_t)(colBase + row) * K + k0 + ko * 8);
        }
    };

    load_tiles(0, 0);
    asm volatile("cp.async.commit_group;\n" ::: "memory");

    for (int it = 0; it < niter; it++) {
        if (it + 1 < niter) load_tiles((it + 1) & 1, (it + 1) << 6);
        asm volatile("cp.async.commit_group;\n" ::: "memory");
        asm volatile("cp.async.wait_group 1;\n" ::: "memory");
        __syncthreads();

        const __half* As = smh + (it & 1) * HSTAGE;
        const __half* Bs = As + 128 * HSTRIDE;

        #pragma unroll
        for (int ks = 0; ks < 4; ks++) {
            const int kb = ks * 16;
            uint32_t a[4][4];
            #pragma unroll
            for (int mt = 0; mt < 4; mt++) {
                int r = wm * 64 + mt * 16 + g;
                a[mt][0] = ldsm_u32(&As[r * HSTRIDE       + kb     + 2*tg]);
                a[mt][1] = ldsm_u32(&As[(r + 8) * HSTRIDE + kb     + 2*tg]);
                a[mt][2] = ldsm_u32(&As[r * HSTRIDE       + kb + 8 + 2*tg]);
                a[mt][3] = ldsm_u32(&As[(r + 8) * HSTRIDE + kb + 8 + 2*tg]);
            }
            #pragma unroll
            for (int nt = 0; nt < 4; nt++) {
                int j = wn * 32 + nt * 8 + g;
                uint32_t b0 = ldsm_u32(&Bs[j * HSTRIDE + kb     + 2*tg]);
                uint32_t b1 = ldsm_u32(&Bs[j * HSTRIDE + kb + 8 + 2*tg]);
                #pragma unroll
                for (int mt = 0; mt < 4; mt++)
                    mma_f16(acc[mt][nt], a[mt], b0, b1);
            }
        }
        __syncthreads();
    }

    #pragma unroll
    for (int mt = 0; mt < 4; mt++) {
        int r = rowBase + wm * 64 + mt * 16 + g;
        #pragma unroll
        for (int nt = 0; nt < 4; nt++) {
            int jc = colBase + wn * 32 + nt * 8 + 2 * tg;
            if (mode == 0) {
                float* C = (float*)Cv;
                C[(size_t)r       * ldc + jc    ] = acc[mt][nt][0];
                C[(size_t)r       * ldc + jc + 1] = acc[mt][nt][1];
                C[(size_t)(r + 8) * ldc + jc    ] = acc[mt][nt][2];
                C[(size_t)(r + 8) * ldc + jc + 1] = acc[mt][nt][3];
            } else {
                __half* C = (__half*)Cv;
                int h = jc >> 6, d = jc & 63;
                int b1r = r / S,  s1 = r - b1r * S;
                int r2  = r + 8;
                int b2r = r2 / S, s2 = r2 - b2r * S;
                if (mode == 1) {
                    __half* p0 = C + (((size_t)(b1r * NHEADS + h) * S + s1) << 6) + d;
                    __half* p1 = C + (((size_t)(b2r * NHEADS + h) * S + s2) << 6) + d;
                    *reinterpret_cast<uint32_t*>(p0) = f2h2(acc[mt][nt][0], acc[mt][nt][1]);
                    *reinterpret_cast<uint32_t*>(p1) = f2h2(acc[mt][nt][2], acc[mt][nt][3]);
                } else {
                    size_t base0 = ((size_t)(b1r * NHEADS + h) * DH + d) * S;
                    size_t base1 = ((size_t)(b2r * NHEADS + h) * DH + d) * S;
                    C[base0 + s1]     = __float2half_rn(acc[mt][nt][0]);
                    C[base0 + S + s1] = __float2half_rn(acc[mt][nt][1]);
                    C[base1 + s2]     = __float2half_rn(acc[mt][nt][2]);
                    C[base1 + S + s2] = __float2half_rn(acc[mt][nt][3]);
                }
            }
        }
    }
}

// ---------------- fp16 pos GEMM: pos[m, l] = q[m,:]·peT[l,:], half out ----------------
__global__ __launch_bounds__(256, 2)
void pos_kernel(const __half* __restrict__ gq, const __half* __restrict__ peT,
                __half* __restrict__ gpos)
{
    extern __shared__ __half sph[];
    __half* As  = sph;                    // 128 x 72
    __half* Bst = sph + 128 * HSTRIDE;    // 2 x (64 x 72)

    const int tid  = threadIdx.x;
    const int warp = tid >> 5, lane = tid & 31;
    const int g  = lane >> 2, tg = lane & 3;
    const int r0 = warp * 16 + g;
    const size_t rowBase = (size_t)blockIdx.x * 128;

    #pragma unroll
    for (int i = tid; i < 1024; i += 256) {
        int r = i >> 3, ko = i & 7;
        cp_async16(&As[r * HSTRIDE + ko * 8], gq + (rowBase + r) * DH + ko * 8);
    }
    asm volatile("cp.async.commit_group;\n" ::: "memory");

    #pragma unroll
    for (int i = tid; i < 512; i += 256) {
        int r = i >> 3, ko = i & 7;
        cp_async16(&Bst[r * HSTRIDE + ko * 8], peT + (size_t)r * DH + ko * 8);
    }
    asm volatile("cp.async.commit_group;\n" ::: "memory");
    asm volatile("cp.async.wait_group 1;\n" ::: "memory");
    __syncthreads();

    uint32_t qf[4][4];
    #pragma unroll
    for (int ks = 0; ks < 4; ks++) {
        const int kb = ks * 16;
        qf[ks][0] = ldsm_u32(&As[r0 * HSTRIDE       + kb     + 2*tg]);
        qf[ks][1] = ldsm_u32(&As[(r0+8) * HSTRIDE   + kb     + 2*tg]);
        qf[ks][2] = ldsm_u32(&As[r0 * HSTRIDE       + kb + 8 + 2*tg]);
        qf[ks][3] = ldsm_u32(&As[(r0+8) * HSTRIDE   + kb + 8 + 2*tg]);
    }

    for (int ct = 0; ct < 32; ct++) {
        __syncthreads();
        if (ct + 1 < 32) {
            const __half* bsrc = peT + (size_t)(ct + 1) * 64 * DH;
            __half* Bn = Bst + ((ct + 1) & 1) * (64 * HSTRIDE);
            #pragma unroll
            for (int i = tid; i < 512; i += 256) {
                int r = i >> 3, ko = i & 7;
                cp_async16(&Bn[r * HSTRIDE + ko * 8], bsrc + (size_t)r * DH + ko * 8);
            }
            asm volatile("cp.async.commit_group;\n" ::: "memory");
            asm volatile("cp.async.wait_group 1;\n" ::: "memory");
        } else {
            asm volatile("cp.async.wait_group 0;\n" ::: "memory");
        }
        __syncthreads();

        const __half* Bs = Bst + (ct & 1) * (64 * HSTRIDE);

        float s[8][4];
        #pragma unroll
        for (int nt = 0; nt < 8; nt++)
            #pragma unroll
            for (int i = 0; i < 4; i++) s[nt][i] = 0.f;
        #pragma unroll
        for (int ks = 0; ks < 4; ks++) {
            const int kb = ks * 16;
            #pragma unroll
            for (int nt = 0; nt < 8; nt++) {
                int j = nt*8 + g;
                uint32_t b0 = ldsm_u32(&Bs[j * HSTRIDE + kb     + 2*tg]);
                uint32_t b1 = ldsm_u32(&Bs[j * HSTRIDE + kb + 8 + 2*tg]);
                mma_f16(s[nt], qf[ks], b0, b1);
            }
        }

        __half* pr0 = gpos + (rowBase + r0) * (size_t)LWIN + ct * 64;
        __half* pr1 = pr0 + (size_t)8 * LWIN;
        #pragma unroll
        for (int nt = 0; nt < 8; nt++) {
            int col = nt*8 + 2*tg;
            *reinterpret_cast<uint32_t*>(pr0 + col) = f2h2(s[nt][0], s[nt][1]);
            *reinterpret_cast<uint32_t*>(pr1 + col) = f2h2(s[nt][2], s[nt][3]);
        }
    }
}

// ---------------- fp16 flash attention (pos bias in half) ----------------
__global__ __launch_bounds__(256, 2)
void attn_kernel(const __half* __restrict__ gq, const __half* __restrict__ gk,
                 const __half* __restrict__ gv, const __half* __restrict__ gpos,
                 __half* __restrict__ gatt)
{
    extern __shared__ __half smA[];
    __half* Ps = smA + 18432;       // 128 x 72 (also Q staging)

    const int bh = blockIdx.x;
    const int m0 = blockIdx.y * QTILE;
    const int tid  = threadIdx.x;
    const int warp = tid >> 5, lane = tid & 31;
    const int g  = lane >> 2, tg = lane & 3;
    const int r0 = warp*16 + g;

    {
        const __half* qb = gq + ((size_t)bh * MEMQ + m0) * DH;
        #pragma unroll
        for (int i = tid; i < 1024; i += 256) {
            int r = i >> 3, ko = i & 7;
            cp_async16(&Ps[r * HSTRIDE + ko * 8], qb + r * DH + ko * 8);
        }
    }
    asm volatile("cp.async.commit_group;\n" ::: "memory");

    {
        const __half* kb = gk + ((size_t)bh * KVLEN + m0) * DH;
        const __half* vb = gv + ((size_t)bh * DH) * KVLEN + m0;
        __half* Ks = smA;
        __half* Vs = smA + 4608;
        #pragma unroll
        for (int i = tid; i < 512; i += 256) {
            int r = i >> 3, ko = i & 7;
            cp_async16(&Ks[r * HSTRIDE + ko * 8], kb + r * DH + ko * 8);
            cp_async16(&Vs[r * HSTRIDE + ko * 8], vb + (size_t)r * KVLEN + ko * 8);
        }
    }
    asm volatile("cp.async.commit_group;\n" ::: "memory");
    asm volatile("cp.async.wait_group 1;\n" ::: "memory");
    __syncthreads();

    uint32_t qf[4][4];
    #pragma unroll
    for (int ks = 0; ks < 4; ks++) {
        const int kb = ks * 16;
        qf[ks][0] = ldsm_u32(&Ps[r0 * HSTRIDE       + kb     + 2*tg]);
        qf[ks][1] = ldsm_u32(&Ps[(r0+8) * HSTRIDE   + kb     + 2*tg]);
        qf[ks][2] = ldsm_u32(&Ps[r0 * HSTRIDE       + kb + 8 + 2*tg]);
        qf[ks][3] = ldsm_u32(&Ps[(r0+8) * HSTRIDE   + kb + 8 + 2*tg]);
    }

    float o[8][4];
    #pragma unroll
    for (int nt = 0; nt < 8; nt++)
        #pragma unroll
        for (int i = 0; i < 4; i++) o[nt][i] = 0.f;
    float mi0 = -1e30f, mi1 = -1e30f, li0 = 0.f, li1 = 0.f;

    const __half* posr0 = gpos + ((size_t)bh * MEMQ + m0 + r0) * LWIN;
    const __half* posr1 = posr0 + (size_t)8 * LWIN;

    for (int t = 0; t < 34; t++) {
        __syncthreads();
        if (t + 1 < 34) {
            const int j1 = m0 + (t + 1) * 64;
            const __half* kb = gk + ((size_t)bh * KVLEN + j1) * DH;
            const __half* vb = gv + ((size_t)bh * DH) * KVLEN + j1;
            __half* Kn = smA + ((t + 1) & 1) * 9216;
            __half* Vn = Kn + 4608;
            #pragma unroll
            for (int i = tid; i < 512; i += 256) {
                int r = i >> 3, ko = i & 7;
                cp_async16(&Kn[r * HSTRIDE + ko * 8], kb + r * DH + ko * 8);
                cp_async16(&Vn[r * HSTRIDE + ko * 8], vb + (size_t)r * KVLEN + ko * 8);
            }
            asm volatile("cp.async.commit_group;\n" ::: "memory");
            asm volatile("cp.async.wait_group 1;\n" ::: "memory");
        } else {
            asm volatile("cp.async.wait_group 0;\n" ::: "memory");
        }
        __syncthreads();

        const __half* Ks = smA + (t & 1) * 9216;
        const __half* Vs = Ks + 4608;

        float s[8][4];
        #pragma unroll
        for (int nt = 0; nt < 8; nt++)
            #pragma unroll
            for (int i = 0; i < 4; i++) s[nt][i] = 0.f;
        #pragma unroll
        for (int ks = 0; ks < 4; ks++) {
            const int kb = ks * 16;
            #pragma unroll
            for (int nt = 0; nt < 8; nt++) {
                int j = nt*8 + g;
                uint32_t b0 = ldsm_u32(&Ks[j * HSTRIDE + kb     + 2*tg]);
                uint32_t b1 = ldsm_u32(&Ks[j * HSTRIDE + kb + 8 + 2*tg]);
                mma_f16(s[nt], qf[ks], b0, b1);
            }
        }

        #pragma unroll
        for (int nt = 0; nt < 8; nt++) {
            int jj = nt*8 + 2*tg;
            int lA = t*64 + jj - r0;
            int lB = lA - 8;
            #pragma unroll
            for (int e = 0; e < 2; e++) {
                int l1 = lA + e;
                s[nt][e]     = (l1 >= 0 && l1 < LWIN)
                             ? (s[nt][e]     + __half2float(__ldg(posr0 + l1))) * 0.125f
                             : -1e30f;
                int l2 = lB + e;
                s[nt][2 + e] = (l2 >= 0 && l2 < LWIN)
                             ? (s[nt][2 + e] + __half2float(__ldg(posr1 + l2))) * 0.125f
                             : -1e30f;
            }
        }

        float mx0 = -1e30f, mx1 = -1e30f;
        #pragma unroll
        for (int nt = 0; nt < 8; nt++) {
            mx0 = fmaxf(mx0, fmaxf(s[nt][0], s[nt][1]));
            mx1 = fmaxf(mx1, fmaxf(s[nt][2], s[nt][3]));
        }
        mx0 = fmaxf(mx0, __shfl_xor_sync(0xffffffffu, mx0, 1));
        mx0 = fmaxf(mx0, __shfl_xor_sync(0xffffffffu, mx0, 2));
        mx1 = fmaxf(mx1, __shfl_xor_sync(0xffffffffu, mx1, 1));
        mx1 = fmaxf(mx1, __shfl_xor_sync(0xffffffffu, mx1, 2));
        float mn0 = fmaxf(mi0, mx0), mn1 = fmaxf(mi1, mx1);
        float al0 = __expf(mi0 - mn0), al1 = __expf(mi1 - mn1);
        float rs0 = 0.f, rs1 = 0.f;
        #pragma unroll
        for (int nt = 0; nt < 8; nt++) {
            s[nt][0] = __expf(s[nt][0] - mn0);
            s[nt][1] = __expf(s[nt][1] - mn0);
            s[nt][2] = __expf(s[nt][2] - mn1);
            s[nt][3] = __expf(s[nt][3] - mn1);
            rs0 += s[nt][0] + s[nt][1];
            rs1 += s[nt][2] + s[nt][3];
        }
        rs0 += __shfl_xor_sync(0xffffffffu, rs0, 1);
        rs0 += __shfl_xor_sync(0xffffffffu, rs0, 2);
        rs1 += __shfl_xor_sync(0xffffffffu, rs1, 1);
        rs1 += __shfl_xor_sync(0xffffffffu, rs1, 2);
        li0 = li0 * al0 + rs0;
        li1 = li1 * al1 + rs1;
        mi0 = mn0; mi1 = mn1;

        #pragma unroll
        for (int nt = 0; nt < 8; nt++) {
            o[nt][0] *= al0; o[nt][1] *= al0; o[nt][2] *= al1; o[nt][3] *= al1;
            int col = nt*8 + 2*tg;
            *reinterpret_cast<uint32_t*>(&Ps[r0 * HSTRIDE + col])
                = f2h2(s[nt][0], s[nt][1]);
            *reinterpret_cast<uint32_t*>(&Ps[(r0+8) * HSTRIDE + col])
                = f2h2(s[nt][2], s[nt][3]);
        }
        __syncwarp();

        #pragma unroll
        for (int ks = 0; ks < 4; ks++) {
            const int kb = ks * 16;
            uint32_t a[4];
            a[0] = ldsm_u32(&Ps[r0 * HSTRIDE       + kb     + 2*tg]);
            a[1] = ldsm_u32(&Ps[(r0+8) * HSTRIDE   + kb     + 2*tg]);
            a[2] = ldsm_u32(&Ps[r0 * HSTRIDE       + kb + 8 + 2*tg]);
            a[3] = ldsm_u32(&Ps[(r0+8) * HSTRIDE   + kb + 8 + 2*tg]);
            #pragma unroll
            for (int nt = 0; nt < 8; nt++) {
                int d = nt*8 + g;
                uint32_t b0 = ldsm_u32(&Vs[d * HSTRIDE + kb     + 2*tg]);
                uint32_t b1 = ldsm_u32(&Vs[d * HSTRIDE + kb + 8 + 2*tg]);
                mma_f16(o[nt], a, b0, b1);
            }
        }
        __syncwarp();
    }

    const float inv0 = 1.f / li0, inv1 = 1.f / li1;
    const int b = bh >> 4, h = bh & 15;
    #pragma unroll
    for (int nt = 0; nt < 8; nt++) {
        int d = nt*8 + 2*tg;
        size_t i0 = (((size_t)(b*MEMQ + (m0 + r0    )) * NHEADS + h) << 6) + d;
        size_t i1 = (((size_t)(b*MEMQ + (m0 + r0 + 8)) * NHEADS + h) << 6) + d;
        *reinterpret_cast<uint32_t*>(&gatt[i0]) = f2h2(o[nt][0] * inv0, o[nt][1] * inv0);
        *reinterpret_cast<uint32_t*>(&gatt[i1]) = f2h2(o[nt][2] * inv1, o[nt][3] * inv1);
    }
}

// ---------------- launch ----------------
extern "C" void kernel_launch(void* const* d_in, const int* in_sizes, int n_in,
                              void* d_out, int out_size)
{
    const float* query = (const float*)d_in[0];
    const float* key   = (const float*)d_in[1];
    const float* value = (const float*)d_in[2];
    const float* keype = (const float*)d_in[3];
    const float* Wq    = (const float*)d_in[4];
    const float* Wk    = (const float*)d_in[5];
    const float* Wv    = (const float*)d_in[6];
    const float* Wo    = (const float*)d_in[7];
    float* out = (float*)d_out;

    __half *pq, *pk, *pv, *ppeT, *ppos, *patt, *pqc, *pkc, *pvc, *pw0, *pw1, *pw2, *pw3;
    cudaGetSymbolAddress((void**)&pq,   g_q);
    cudaGetSymbolAddress((void**)&pk,   g_k);
    cudaGetSymbolAddress((void**)&pv,   g_v);
    cudaGetSymbolAddress((void**)&ppeT, g_peT);
    cudaGetSymbolAddress((void**)&ppos, g_pos);
    cudaGetSymbolAddress((void**)&patt, g_att);
    cudaGetSymbolAddress((void**)&pqc,  g_qc);
    cudaGetSymbolAddress((void**)&pkc,  g_kc);
    cudaGetSymbolAddress((void**)&pvc,  g_vc);
    cudaGetSymbolAddress((void**)&pw0,  g_w0);
    cudaGetSymbolAddress((void**)&pw1,  g_w1);
    cudaGetSymbolAddress((void**)&pw2,  g_w2);
    cudaGetSymbolAddress((void**)&pw3,  g_w3);

    const int gemm_smem = 2 * HSTAGE * 2;                          // 73728 B
    const int pos_smem  = (128 * HSTRIDE + 2 * 64 * HSTRIDE) * 2;  // 36864 B
    const int attn_smem = (2 * 9216 + 128 * HSTRIDE) * 2;          // 55296 B
    cudaFuncSetAttribute(gemm_h, cudaFuncAttributeMaxDynamicSharedMemorySize, gemm_smem);
    cudaFuncSetAttribute(pos_kernel, cudaFuncAttributeMaxDynamicSharedMemorySize, pos_smem);
    cudaFuncSetAttribute(attn_kernel, cudaFuncAttributeMaxDynamicSharedMemorySize, attn_smem);

    const int nq4 = NBATCH * MEMQ  * HIDDIM / 4;
    const int nk4 = NBATCH * KVLEN * HIDDIM / 4;
    const int nw4 = HIDDIM * HIDDIM / 4;
    half_cast<<<(nq4 + 255) / 256, 256>>>((const float4*)query, (uint2*)pqc, nq4);
    half_cast<<<(nk4 + 255) / 256, 256>>>((const float4*)key,   (uint2*)pkc, nk4);
    half_cast<<<(nk4 + 255) / 256, 256>>>((const float4*)value, (uint2*)pvc, nk4);
    w4_cast<<<(4 * nw4 + 255) / 256, 256>>>(
        (const float4*)Wq, (const float4*)Wk, (const float4*)Wv, (const float4*)Wo,
        (uint2*)pw0, (uint2*)pw1, (uint2*)pw2, (uint2*)pw3, nw4);
    transpose_pe<<<512, 256>>>(keype, ppeT);

    gemm_h<<<dim3(32, 8),  256, gemm_smem>>>(pqc, HIDDIM, pw0, pq, HIDDIM, 0, 1, MEMQ);
    gemm_h<<<dim3(160, 8), 256, gemm_smem>>>(pkc, HIDDIM, pw1, pk, HIDDIM, 0, 1, KVLEN);
    gemm_h<<<dim3(160, 8), 256, gemm_smem>>>(pvc, HIDDIM, pw2, pv, HIDDIM, 0, 2, KVLEN);
    pos_kernel<<<512, 256, pos_smem>>>(pq, ppeT, ppos);
    attn_kernel<<<dim3(BHTOT, 4), 256, attn_smem>>>(pq, pk, pv, ppos, patt);
    gemm_h<<<dim3(32, 8), 256, gemm_smem>>>(patt, HIDDIM, pw3, out, HIDDIM, HIDDIM, 0, 0);
}

// round 15
// speedup vs baseline: 1.8284x; 1.0281x over previous
#include <cuda_runtime.h>
#include <cuda_fp16.h>
#include <cstdint>
#include <cstddef>

#define HIDDIM 1024
#define NHEADS 16
#define MEMQ   512
#define LWIN   2048
#define KVLEN  2560
#define DH     64
#define NBATCH 8
#define BHTOT  128
#define QTILE  128

// ---------------- scratch ----------------
static __device__ __half g_q  [(size_t)BHTOT * MEMQ  * DH];     // [bh][m][d]
static __device__ __half g_k  [(size_t)BHTOT * KVLEN * DH];     // [bh][j][d]
static __device__ __half g_v  [(size_t)BHTOT * DH * KVLEN];     // [bh][d][j]  (transposed)
static __device__ __half g_peT[(size_t)LWIN * DH];              // [l][d]
static __device__ __half g_pos[(size_t)BHTOT * MEMQ  * LWIN];   // fp16
static __device__ __half g_att[(size_t)NBATCH * MEMQ * HIDDIM]; // [b][m][h][d]
static __device__ __half g_qc [(size_t)NBATCH * MEMQ  * HIDDIM];
static __device__ __half g_kc [(size_t)NBATCH * KVLEN * HIDDIM];
static __device__ __half g_vc [(size_t)NBATCH * KVLEN * HIDDIM];
static __device__ __half g_w0 [(size_t)HIDDIM * HIDDIM];
static __device__ __half g_w1 [(size_t)HIDDIM * HIDDIM];
static __device__ __half g_w2 [(size_t)HIDDIM * HIDDIM];
static __device__ __half g_w3 [(size_t)HIDDIM * HIDDIM];

// ---------------- helpers ----------------
__device__ __forceinline__ uint32_t f2h2(float a, float b){
    __half2 h = __floats2half2_rn(a, b);
    return *reinterpret_cast<uint32_t*>(&h);
}
__device__ __forceinline__ void mma_f16(float c[4], const uint32_t a[4],
                                        uint32_t b0, uint32_t b1){
    asm("mma.sync.aligned.m16n8k16.row.col.f32.f16.f16.f32 "
        "{%0,%1,%2,%3}, {%4,%5,%6,%7}, {%8,%9}, {%0,%1,%2,%3};"
        : "+f"(c[0]), "+f"(c[1]), "+f"(c[2]), "+f"(c[3])
        : "r"(a[0]), "r"(a[1]), "r"(a[2]), "r"(a[3]), "r"(b0), "r"(b1));
}
__device__ __forceinline__ void cp_async16(void* sptr, const void* gptr){
    uint32_t sa = (uint32_t)__cvta_generic_to_shared(sptr);
    asm volatile("cp.async.cg.shared.global [%0], [%1], 16;\n" :: "r"(sa), "l"(gptr));
}
__device__ __forceinline__ uint32_t ldsm_u32(const __half* p){
    return *reinterpret_cast<const uint32_t*>(p);
}

// ---------------- merged cast: query + key + value + 4 weights, one launch ----------------
__global__ void cast_all(const float4* __restrict__ sq, const float4* __restrict__ sk,
                         const float4* __restrict__ sv,
                         const float4* __restrict__ w0, const float4* __restrict__ w1,
                         const float4* __restrict__ w2, const float4* __restrict__ w3,
                         uint2* __restrict__ dq, uint2* __restrict__ dk,
                         uint2* __restrict__ dv,
                         uint2* __restrict__ dw0, uint2* __restrict__ dw1,
                         uint2* __restrict__ dw2, uint2* __restrict__ dw3,
                         int nq4, int nk4, int nw4)
{
    int i = blockIdx.x * 256 + threadIdx.x;
    const float4* s;
    uint2* d;
    int r;
    if (i < nq4)                { s = sq; d = dq; r = i; }
    else if (i < nq4 + nk4)     { s = sk; d = dk; r = i - nq4; }
    else if (i < nq4 + 2*nk4)   { s = sv; d = dv; r = i - nq4 - nk4; }
    else {
        int j = i - nq4 - 2*nk4;
        int m = j / nw4;
        r = j - m * nw4;
        s = (m == 0) ? w0 : (m == 1) ? w1 : (m == 2) ? w2 : w3;
        d = (m == 0) ? dw0 : (m == 1) ? dw1 : (m == 2) ? dw2 : dw3;
    }
    float4 v = s[r];
    uint2 o;
    o.x = f2h2(v.x, v.y);
    o.y = f2h2(v.z, v.w);
    d[r] = o;
}

// ---------------- pe transpose -> half ----------------
__global__ void transpose_pe(const float* __restrict__ pe, __half* __restrict__ peT){
    int idx = blockIdx.x * 256 + threadIdx.x;
    int l = idx >> 6;
    int d = idx & 63;
    peT[idx] = __float2half_rn(pe[(size_t)d * LWIN + l]);
}

#define HSTRIDE 72
#define HSTAGE  (256 * HSTRIDE)

// ---------------- merged projections (q/k/v) — one launch, block decode ----------------
// blocks [0,256): q proj (32x8, mode 1, S=MEMQ)
// blocks [256,1536): k proj (160x8, mode 1, S=KVLEN)
// blocks [1536,2816): v proj (160x8, mode 2 transposed, S=KVLEN)
__global__ __launch_bounds__(256, 2)
void proj_h(const __half* __restrict__ Aq, const __half* __restrict__ Ak,
            const __half* __restrict__ Av,
            const __half* __restrict__ B0, const __half* __restrict__ B1,
            const __half* __restrict__ B2,
            __half* __restrict__ Cq, __half* __restrict__ Ck, __half* __restrict__ Cv2)
{
    extern __shared__ __half smh[];

    const __half *A, *B;
    __half* C;
    int mode, S, bx, by;
    {
        int idx = blockIdx.x;
        if (idx < 256)        { A = Aq; B = B0; C = Cq;  mode = 1; S = MEMQ;  bx = idx & 31;  by = idx >> 5; }
        else if (idx < 1536)  { int j = idx - 256;  A = Ak; B = B1; C = Ck;  mode = 1; S = KVLEN; bx = j % 160; by = j / 160; }
        else                  { int j = idx - 1536; A = Av; B = B2; C = Cv2; mode = 2; S = KVLEN; bx = j % 160; by = j / 160; }
    }
    const int K = HIDDIM, lda = HIDDIM;
    const int rowBase = bx * 128;
    const int colBase = by * 128;

    const int tid  = threadIdx.x;
    const int warp = tid >> 5, lane = tid & 31;
    const int wm = warp >> 2, wn = warp & 3;
    const int g  = lane >> 2, tg = lane & 3;

    float acc[4][4][4];
    #pragma unroll
    for (int mt = 0; mt < 4; mt++)
        #pragma unroll
        for (int nt = 0; nt < 4; nt++)
            #pragma unroll
            for (int i = 0; i < 4; i++) acc[mt][nt][i] = 0.f;

    const int niter = K >> 6;

    auto load_tiles = [&](int st, int k0){
        __half* As = smh + st * HSTAGE;
        __half* Bs = As + 128 * HSTRIDE;
        #pragma unroll
        for (int i = 0; i < 4; i++) {
            int c = tid + i * 256;
            int row = c >> 3, ko = c & 7;
            cp_async16(&As[row * HSTRIDE + ko * 8],
                       A + (size_t)(rowBase + row) * lda + k0 + ko * 8);
        }
        #pragma unroll
        for (int i = 0; i < 4; i++) {
            int c = tid + i * 256;
            int row = c >> 3, ko = c & 7;
            cp_async16(&Bs[row * HSTRIDE + ko * 8],
                       B + (size_t)(colBase + row) * K + k0 + ko * 8);
        }
    };

    load_tiles(0, 0);
    asm volatile("cp.async.commit_group;\n" ::: "memory");

    for (int it = 0; it < niter; it++) {
        if (it + 1 < niter) load_tiles((it + 1) & 1, (it + 1) << 6);
        asm volatile("cp.async.commit_group;\n" ::: "memory");
        asm volatile("cp.async.wait_group 1;\n" ::: "memory");
        __syncthreads();

        const __half* As = smh + (it & 1) * HSTAGE;
        const __half* Bs = As + 128 * HSTRIDE;

        #pragma unroll
        for (int ks = 0; ks < 4; ks++) {
            const int kb = ks * 16;
            uint32_t a[4][4];
            #pragma unroll
            for (int mt = 0; mt < 4; mt++) {
                int r = wm * 64 + mt * 16 + g;
                a[mt][0] = ldsm_u32(&As[r * HSTRIDE       + kb     + 2*tg]);
                a[mt][1] = ldsm_u32(&As[(r + 8) * HSTRIDE + kb     + 2*tg]);
                a[mt][2] = ldsm_u32(&As[r * HSTRIDE       + kb + 8 + 2*tg]);
                a[mt][3] = ldsm_u32(&As[(r + 8) * HSTRIDE + kb + 8 + 2*tg]);
            }
            #pragma unroll
            for (int nt = 0; nt < 4; nt++) {
                int j = wn * 32 + nt * 8 + g;
                uint32_t b0 = ldsm_u32(&Bs[j * HSTRIDE + kb     + 2*tg]);
                uint32_t b1 = ldsm_u32(&Bs[j * HSTRIDE + kb + 8 + 2*tg]);
                #pragma unroll
                for (int mt = 0; mt < 4; mt++)
                    mma_f16(acc[mt][nt], a[mt], b0, b1);
            }
        }
        __syncthreads();
    }

    #pragma unroll
    for (int mt = 0; mt < 4; mt++) {
        int r = rowBase + wm * 64 + mt * 16 + g;
        #pragma unroll
        for (int nt = 0; nt < 4; nt++) {
            int jc = colBase + wn * 32 + nt * 8 + 2 * tg;
            int h = jc >> 6, d = jc & 63;
            int b1r = r / S,  s1 = r - b1r * S;
            int r2  = r + 8;
            int b2r = r2 / S, s2 = r2 - b2r * S;
            if (mode == 1) {
                __half* p0 = C + (((size_t)(b1r * NHEADS + h) * S + s1) << 6) + d;
                __half* p1 = C + (((size_t)(b2r * NHEADS + h) * S + s2) << 6) + d;
                *reinterpret_cast<uint32_t*>(p0) = f2h2(acc[mt][nt][0], acc[mt][nt][1]);
                *reinterpret_cast<uint32_t*>(p1) = f2h2(acc[mt][nt][2], acc[mt][nt][3]);
            } else {
                size_t base0 = ((size_t)(b1r * NHEADS + h) * DH + d) * S;
                size_t base1 = ((size_t)(b2r * NHEADS + h) * DH + d) * S;
                C[base0 + s1]     = __float2half_rn(acc[mt][nt][0]);
                C[base0 + S + s1] = __float2half_rn(acc[mt][nt][1]);
                C[base1 + s2]     = __float2half_rn(acc[mt][nt][2]);
                C[base1 + S + s2] = __float2half_rn(acc[mt][nt][3]);
            }
        }
    }
}

// ---------------- fp16 NT GEMM (Wo only; fp32 output) ----------------
__global__ __launch_bounds__(256, 2)
void gemm_h(const __half* __restrict__ A, int lda,
            const __half* __restrict__ B,
            float* __restrict__ C,
            int K, int ldc)
{
    extern __shared__ __half smh[];

    const int tid  = threadIdx.x;
    const int warp = tid >> 5, lane = tid & 31;
    const int wm = warp >> 2, wn = warp & 3;
    const int g  = lane >> 2, tg = lane & 3;
    const int rowBase = blockIdx.x * 128;
    const int colBase = blockIdx.y * 128;

    float acc[4][4][4];
    #pragma unroll
    for (int mt = 0; mt < 4; mt++)
        #pragma unroll
        for (int nt = 0; nt < 4; nt++)
            #pragma unroll
            for (int i = 0; i < 4; i++) acc[mt][nt][i] = 0.f;

    const int niter = K >> 6;

    auto load_tiles = [&](int st, int k0){
        __half* As = smh + st * HSTAGE;
        __half* Bs = As + 128 * HSTRIDE;
        #pragma unroll
        for (int i = 0; i < 4; i++) {
            int c = tid + i * 256;
            int row = c >> 3, ko = c & 7;
            cp_async16(&As[row * HSTRIDE + ko * 8],
                       A + (size_t)(rowBase + row) * lda + k0 + ko * 8);
        }
        #pragma unroll
        for (int i = 0; i < 4; i++) {
            int c = tid + i * 256;
            int row = c >> 3, ko = c & 7;
            cp_async16(&Bs[row * HSTRIDE + ko * 8],
                       B + (size_t)(colBase + row) * K + k0 + ko * 8);
        }
    };

    load_tiles(0, 0);
    asm volatile("cp.async.commit_group;\n" ::: "memory");

    for (int it = 0; it < niter; it++) {
        if (it + 1 < niter) load_tiles((it + 1) & 1, (it + 1) << 6);
        asm volatile("cp.async.commit_group;\n" ::: "memory");
        asm volatile("cp.async.wait_group 1;\n" ::: "memory");
        __syncthreads();

        const __half* As = smh + (it & 1) * HSTAGE;
        const __half* Bs = As + 128 * HSTRIDE;

        #pragma unroll
        for (int ks = 0; ks < 4; ks++) {
            const int kb = ks * 16;
            uint32_t a[4][4];
            #pragma unroll
            for (int mt = 0; mt < 4; mt++) {
                int r = wm * 64 + mt * 16 + g;
                a[mt][0] = ldsm_u32(&As[r * HSTRIDE       + kb     + 2*tg]);
                a[mt][1] = ldsm_u32(&As[(r + 8) * HSTRIDE + kb     + 2*tg]);
                a[mt][2] = ldsm_u32(&As[r * HSTRIDE       + kb + 8 + 2*tg]);
                a[mt][3] = ldsm_u32(&As[(r + 8) * HSTRIDE + kb + 8 + 2*tg]);
            }
            #pragma unroll
            for (int nt = 0; nt < 4; nt++) {
                int j = wn * 32 + nt * 8 + g;
                uint32_t b0 = ldsm_u32(&Bs[j * HSTRIDE + kb     + 2*tg]);
                uint32_t b1 = ldsm_u32(&Bs[j * HSTRIDE + kb + 8 + 2*tg]);
                #pragma unroll
                for (int mt = 0; mt < 4; mt++)
                    mma_f16(acc[mt][nt], a[mt], b0, b1);
            }
        }
        __syncthreads();
    }

    #pragma unroll
    for (int mt = 0; mt < 4; mt++) {
        int r = rowBase + wm * 64 + mt * 16 + g;
        #pragma unroll
        for (int nt = 0; nt < 4; nt++) {
            int jc = colBase + wn * 32 + nt * 8 + 2 * tg;
            C[(size_t)r       * ldc + jc    ] = acc[mt][nt][0];
            C[(size_t)r       * ldc + jc + 1] = acc[mt][nt][1];
            C[(size_t)(r + 8) * ldc + jc    ] = acc[mt][nt][2];
            C[(size_t)(r + 8) * ldc + jc + 1] = acc[mt][nt][3];
        }
    }
}

// ---------------- fp16 pos GEMM: pos[m, l] = q[m,:]·peT[l,:], half out ----------------
__global__ __launch_bounds__(256, 2)
void pos_kernel(const __half* __restrict__ gq, const __half* __restrict__ peT,
                __half* __restrict__ gpos)
{
    extern __shared__ __half sph[];
    __half* As  = sph;                    // 128 x 72
    __half* Bst = sph + 128 * HSTRIDE;    // 2 x (64 x 72)

    const int tid  = threadIdx.x;
    const int warp = tid >> 5, lane = tid & 31;
    const int g  = lane >> 2, tg = lane & 3;
    const int r0 = warp * 16 + g;
    const size_t rowBase = (size_t)blockIdx.x * 128;

    #pragma unroll
    for (int i = tid; i < 1024; i += 256) {
        int r = i >> 3, ko = i & 7;
        cp_async16(&As[r * HSTRIDE + ko * 8], gq + (rowBase + r) * DH + ko * 8);
    }
    asm volatile("cp.async.commit_group;\n" ::: "memory");

    #pragma unroll
    for (int i = tid; i < 512; i += 256) {
        int r = i >> 3, ko = i & 7;
        cp_async16(&Bst[r * HSTRIDE + ko * 8], peT + (size_t)r * DH + ko * 8);
    }
    asm volatile("cp.async.commit_group;\n" ::: "memory");
    asm volatile("cp.async.wait_group 1;\n" ::: "memory");
    __syncthreads();

    uint32_t qf[4][4];
    #pragma unroll
    for (int ks = 0; ks < 4; ks++) {
        const int kb = ks * 16;
        qf[ks][0] = ldsm_u32(&As[r0 * HSTRIDE       + kb     + 2*tg]);
        qf[ks][1] = ldsm_u32(&As[(r0+8) * HSTRIDE   + kb     + 2*tg]);
        qf[ks][2] = ldsm_u32(&As[r0 * HSTRIDE       + kb + 8 + 2*tg]);
        qf[ks][3] = ldsm_u32(&As[(r0+8) * HSTRIDE   + kb + 8 + 2*tg]);
    }

    for (int ct = 0; ct < 32; ct++) {
        __syncthreads();
        if (ct + 1 < 32) {
            const __half* bsrc = peT + (size_t)(ct + 1) * 64 * DH;
            __half* Bn = Bst + ((ct + 1) & 1) * (64 * HSTRIDE);
            #pragma unroll
            for (int i = tid; i < 512; i += 256) {
                int r = i >> 3, ko = i & 7;
                cp_async16(&Bn[r * HSTRIDE + ko * 8], bsrc + (size_t)r * DH + ko * 8);
            }
            asm volatile("cp.async.commit_group;\n" ::: "memory");
            asm volatile("cp.async.wait_group 1;\n" ::: "memory");
        } else {
            asm volatile("cp.async.wait_group 0;\n" ::: "memory");
        }
        __syncthreads();

        const __half* Bs = Bst + (ct & 1) * (64 * HSTRIDE);

        float s[8][4];
        #pragma unroll
        for (int nt = 0; nt < 8; nt++)
            #pragma unroll
            for (int i = 0; i < 4; i++) s[nt][i] = 0.f;
        #pragma unroll
        for (int ks = 0; ks < 4; ks++) {
            const int kb = ks * 16;
            #pragma unroll
            for (int nt = 0; nt < 8; nt++) {
                int j = nt*8 + g;
                uint32_t b0 = ldsm_u32(&Bs[j * HSTRIDE + kb     + 2*tg]);
                uint32_t b1 = ldsm_u32(&Bs[j * HSTRIDE + kb + 8 + 2*tg]);
                mma_f16(s[nt], qf[ks], b0, b1);
            }
        }

        __half* pr0 = gpos + (rowBase + r0) * (size_t)LWIN + ct * 64;
        __half* pr1 = pr0 + (size_t)8 * LWIN;
        #pragma unroll
        for (int nt = 0; nt < 8; nt++) {
            int col = nt*8 + 2*tg;
            *reinterpret_cast<uint32_t*>(pr0 + col) = f2h2(s[nt][0], s[nt][1]);
            *reinterpret_cast<uint32_t*>(pr1 + col) = f2h2(s[nt][2], s[nt][3]);
        }
    }
}

// ---------------- fp16 flash attention (pos bias in half) ----------------
__global__ __launch_bounds__(256, 2)
void attn_kernel(const __half* __restrict__ gq, const __half* __restrict__ gk,
                 const __half* __restrict__ gv, const __half* __restrict__ gpos,
                 __half* __restrict__ gatt)
{
    extern __shared__ __half smA[];
    __half* Ps = smA + 18432;       // 128 x 72 (also Q staging)

    const int bh = blockIdx.x;
    const int m0 = blockIdx.y * QTILE;
    const int tid  = threadIdx.x;
    const int warp = tid >> 5, lane = tid & 31;
    const int g  = lane >> 2, tg = lane & 3;
    const int r0 = warp*16 + g;

    {
        const __half* qb = gq + ((size_t)bh * MEMQ + m0) * DH;
        #pragma unroll
        for (int i = tid; i < 1024; i += 256) {
            int r = i >> 3, ko = i & 7;
            cp_async16(&Ps[r * HSTRIDE + ko * 8], qb + r * DH + ko * 8);
        }
    }
    asm volatile("cp.async.commit_group;\n" ::: "memory");

    {
        const __half* kb = gk + ((size_t)bh * KVLEN + m0) * DH;
        const __half* vb = gv + ((size_t)bh * DH) * KVLEN + m0;
        __half* Ks = smA;
        __half* Vs = smA + 4608;
        #pragma unroll
        for (int i = tid; i < 512; i += 256) {
            int r = i >> 3, ko = i & 7;
            cp_async16(&Ks[r * HSTRIDE + ko * 8], kb + r * DH + ko * 8);
            cp_async16(&Vs[r * HSTRIDE + ko * 8], vb + (size_t)r * KVLEN + ko * 8);
        }
    }
    asm volatile("cp.async.commit_group;\n" ::: "memory");
    asm volatile("cp.async.wait_group 1;\n" ::: "memory");
    __syncthreads();

    uint32_t qf[4][4];
    #pragma unroll
    for (int ks = 0; ks < 4; ks++) {
        const int kb = ks * 16;
        qf[ks][0] = ldsm_u32(&Ps[r0 * HSTRIDE       + kb     + 2*tg]);
        qf[ks][1] = ldsm_u32(&Ps[(r0+8) * HSTRIDE   + kb     + 2*tg]);
        qf[ks][2] = ldsm_u32(&Ps[r0 * HSTRIDE       + kb + 8 + 2*tg]);
        qf[ks][3] = ldsm_u32(&Ps[(r0+8) * HSTRIDE   + kb + 8 + 2*tg]);
    }

    float o[8][4];
    #pragma unroll
    for (int nt = 0; nt < 8; nt++)
        #pragma unroll
        for (int i = 0; i < 4; i++) o[nt][i] = 0.f;
    float mi0 = -1e30f, mi1 = -1e30f, li0 = 0.f, li1 = 0.f;

    const __half* posr0 = gpos + ((size_t)bh * MEMQ + m0 + r0) * LWIN;
    const __half* posr1 = posr0 + (size_t)8 * LWIN;

    for (int t = 0; t < 34; t++) {
        __syncthreads();
        if (t + 1 < 34) {
            const int j1 = m0 + (t + 1) * 64;
            const __half* kb = gk + ((size_t)bh * KVLEN + j1) * DH;
            const __half* vb = gv + ((size_t)bh * DH) * KVLEN + j1;
            __half* Kn = smA + ((t + 1) & 1) * 9216;
            __half* Vn = Kn + 4608;
            #pragma unroll
            for (int i = tid; i < 512; i += 256) {
                int r = i >> 3, ko = i & 7;
                cp_async16(&Kn[r * HSTRIDE + ko * 8], kb + r * DH + ko * 8);
                cp_async16(&Vn[r * HSTRIDE + ko * 8], vb + (size_t)r * KVLEN + ko * 8);
            }
            asm volatile("cp.async.commit_group;\n" ::: "memory");
            asm volatile("cp.async.wait_group 1;\n" ::: "memory");
        } else {
            asm volatile("cp.async.wait_group 0;\n" ::: "memory");
        }
        __syncthreads();

        const __half* Ks = smA + (t & 1) * 9216;
        const __half* Vs = Ks + 4608;

        float s[8][4];
        #pragma unroll
        for (int nt = 0; nt < 8; nt++)
            #pragma unroll
            for (int i = 0; i < 4; i++) s[nt][i] = 0.f;
        #pragma unroll
        for (int ks = 0; ks < 4; ks++) {
            const int kb = ks * 16;
            #pragma unroll
            for (int nt = 0; nt < 8; nt++) {
                int j = nt*8 + g;
                uint32_t b0 = ldsm_u32(&Ks[j * HSTRIDE + kb     + 2*tg]);
                uint32_t b1 = ldsm_u32(&Ks[j * HSTRIDE + kb + 8 + 2*tg]);
                mma_f16(s[nt], qf[ks], b0, b1);
            }
        }

        #pragma unroll
        for (int nt = 0; nt < 8; nt++) {
            int jj = nt*8 + 2*tg;
            int lA = t*64 + jj - r0;
            int lB = lA - 8;
            #pragma unroll
            for (int e = 0; e < 2; e++) {
                int l1 = lA + e;
                s[nt][e]     = (l1 >= 0 && l1 < LWIN)
                             ? (s[nt][e]     + __half2float(__ldg(posr0 + l1))) * 0.125f
                             : -1e30f;
                int l2 = lB + e;
                s[nt][2 + e] = (l2 >= 0 && l2 < LWIN)
                             ? (s[nt][2 + e] + __half2float(__ldg(posr1 + l2))) * 0.125f
                             : -1e30f;
            }
        }

        float mx0 = -1e30f, mx1 = -1e30f;
        #pragma unroll
        for (int nt = 0; nt < 8; nt++) {
            mx0 = fmaxf(mx0, fmaxf(s[nt][0], s[nt][1]));
            mx1 = fmaxf(mx1, fmaxf(s[nt][2], s[nt][3]));
        }
        mx0 = fmaxf(mx0, __shfl_xor_sync(0xffffffffu, mx0, 1));
        mx0 = fmaxf(mx0, __shfl_xor_sync(0xffffffffu, mx0, 2));
        mx1 = fmaxf(mx1, __shfl_xor_sync(0xffffffffu, mx1, 1));
        mx1 = fmaxf(mx1, __shfl_xor_sync(0xffffffffu, mx1, 2));
        float mn0 = fmaxf(mi0, mx0), mn1 = fmaxf(mi1, mx1);
        float al0 = __expf(mi0 - mn0), al1 = __expf(mi1 - mn1);
        float rs0 = 0.f, rs1 = 0.f;
        #pragma unroll
        for (int nt = 0; nt < 8; nt++) {
            s[nt][0] = __expf(s[nt][0] - mn0);
            s[nt][1] = __expf(s[nt][1] - mn0);
            s[nt][2] = __expf(s[nt][2] - mn1);
            s[nt][3] = __expf(s[nt][3] - mn1);
            rs0 += s[nt][0] + s[nt][1];
            rs1 += s[nt][2] + s[nt][3];
        }
        rs0 += __shfl_xor_sync(0xffffffffu, rs0, 1);
        rs0 += __shfl_xor_sync(0xffffffffu, rs0, 2);
        rs1 += __shfl_xor_sync(0xffffffffu, rs1, 1);
        rs1 += __shfl_xor_sync(0xffffffffu, rs1, 2);
        li0 = li0 * al0 + rs0;
        li1 = li1 * al1 + rs1;
        mi0 = mn0; mi1 = mn1;

        #pragma unroll
        for (int nt = 0; nt < 8; nt++) {
            o[nt][0] *= al0; o[nt][1] *= al0; o[nt][2] *= al1; o[nt][3] *= al1;
            int col = nt*8 + 2*tg;
            *reinterpret_cast<uint32_t*>(&Ps[r0 * HSTRIDE + col])
                = f2h2(s[nt][0], s[nt][1]);
            *reinterpret_cast<uint32_t*>(&Ps[(r0+8) * HSTRIDE + col])
                = f2h2(s[nt][2], s[nt][3]);
        }
        __syncwarp();

        #pragma unroll
        for (int ks = 0; ks < 4; ks++) {
            const int kb = ks * 16;
            uint32_t a[4];
            a[0] = ldsm_u32(&Ps[r0 * HSTRIDE       + kb     + 2*tg]);
            a[1] = ldsm_u32(&Ps[(r0+8) * HSTRIDE   + kb     + 2*tg]);
            a[2] = ldsm_u32(&Ps[r0 * HSTRIDE       + kb + 8 + 2*tg]);
            a[3] = ldsm_u32(&Ps[(r0+8) * HSTRIDE   + kb + 8 + 2*tg]);
            #pragma unroll
            for (int nt = 0; nt < 8; nt++) {
                int d = nt*8 + g;
                uint32_t b0 = ldsm_u32(&Vs[d * HSTRIDE + kb     + 2*tg]);
                uint32_t b1 = ldsm_u32(&Vs[d * HSTRIDE + kb + 8 + 2*tg]);
                mma_f16(o[nt], a, b0, b1);
            }
        }
        __syncwarp();
    }

    const float inv0 = 1.f / li0, inv1 = 1.f / li1;
    const int b = bh >> 4, h = bh & 15;
    #pragma unroll
    for (int nt = 0; nt < 8; nt++) {
        int d = nt*8 + 2*tg;
        size_t i0 = (((size_t)(b*MEMQ + (m0 + r0    )) * NHEADS + h) << 6) + d;
        size_t i1 = (((size_t)(b*MEMQ + (m0 + r0 + 8)) * NHEADS + h) << 6) + d;
        *reinterpret_cast<uint32_t*>(&gatt[i0]) = f2h2(o[nt][0] * inv0, o[nt][1] * inv0);
        *reinterpret_cast<uint32_t*>(&gatt[i1]) = f2h2(o[nt][2] * inv1, o[nt][3] * inv1);
    }
}

// ---------------- launch ----------------
extern "C" void kernel_launch(void* const* d_in, const int* in_sizes, int n_in,
                              void* d_out, int out_size)
{
    const float* query = (const float*)d_in[0];
    const float* key   = (const float*)d_in[1];
    const float* value = (const float*)d_in[2];
    const float* keype = (const float*)d_in[3];
    const float* Wq    = (const float*)d_in[4];
    const float* Wk    = (const float*)d_in[5];
    const float* Wv    = (const float*)d_in[6];
    const float* Wo    = (const float*)d_in[7];
    float* out = (float*)d_out;

    __half *pq, *pk, *pv, *ppeT, *ppos, *patt, *pqc, *pkc, *pvc, *pw0, *pw1, *pw2, *pw3;
    cudaGetSymbolAddress((void**)&pq,   g_q);
    cudaGetSymbolAddress((void**)&pk,   g_k);
    cudaGetSymbolAddress((void**)&pv,   g_v);
    cudaGetSymbolAddress((void**)&ppeT, g_peT);
    cudaGetSymbolAddress((void**)&ppos, g_pos);
    cudaGetSymbolAddress((void**)&patt, g_att);
    cudaGetSymbolAddress((void**)&pqc,  g_qc);
    cudaGetSymbolAddress((void**)&pkc,  g_kc);
    cudaGetSymbolAddress((void**)&pvc,  g_vc);
    cudaGetSymbolAddress((void**)&pw0,  g_w0);
    cudaGetSymbolAddress((void**)&pw1,  g_w1);
    cudaGetSymbolAddress((void**)&pw2,  g_w2);
    cudaGetSymbolAddress((void**)&pw3,  g_w3);

    const int gemm_smem = 2 * HSTAGE * 2;                          // 73728 B
    const int pos_smem  = (128 * HSTRIDE + 2 * 64 * HSTRIDE) * 2;  // 36864 B
    const int attn_smem = (2 * 9216 + 128 * HSTRIDE) * 2;          // 55296 B
    cudaFuncSetAttribute(proj_h, cudaFuncAttributeMaxDynamicSharedMemorySize, gemm_smem);
    cudaFuncSetAttribute(gemm_h, cudaFuncAttributeMaxDynamicSharedMemorySize, gemm_smem);
    cudaFuncSetAttribute(pos_kernel, cudaFuncAttributeMaxDynamicSharedMemorySize, pos_smem);
    cudaFuncSetAttribute(attn_kernel, cudaFuncAttributeMaxDynamicSharedMemorySize, attn_smem);

    const int nq4 = NBATCH * MEMQ  * HIDDIM / 4;   // 1,048,576
    const int nk4 = NBATCH * KVLEN * HIDDIM / 4;   // 5,242,880
    const int nw4 = HIDDIM * HIDDIM / 4;           // 262,144
    const int ntot4 = nq4 + 2 * nk4 + 4 * nw4;     // 12,582,912 (= 49152 * 256)

    cast_all<<<ntot4 / 256, 256>>>(
        (const float4*)query, (const float4*)key, (const float4*)value,
        (const float4*)Wq, (const float4*)Wk, (const float4*)Wv, (const float4*)Wo,
        (uint2*)pqc, (uint2*)pkc, (uint2*)pvc,
        (uint2*)pw0, (uint2*)pw1, (uint2*)pw2, (uint2*)pw3,
        nq4, nk4, nw4);
    transpose_pe<<<512, 256>>>(keype, ppeT);

    // all three projections in one launch (256 + 1280 + 1280 blocks)
    proj_h<<<2816, 256, gemm_smem>>>(pqc, pkc, pvc, pw0, pw1, pw2, pq, pk, pv);
    pos_kernel<<<512, 256, pos_smem>>>(pq, ppeT, ppos);
    attn_kernel<<<dim3(BHTOT, 4), 256, attn_smem>>>(pq, pk, pv, ppos, patt);
    gemm_h<<<dim3(32, 8), 256, gemm_smem>>>(patt, HIDDIM, pw3, out, HIDDIM, HIDDIM);
}

// round 16
// speedup vs baseline: 1.8811x; 1.0289x over previous
#include <cuda_runtime.h>
#include <cuda_fp16.h>
#include <cstdint>
#include <cstddef>

#define HIDDIM 1024
#define NHEADS 16
#define MEMQ   512
#define LWIN   2048
#define KVLEN  2560
#define DH     64
#define NBATCH 8
#define BHTOT  128
#define QTILE  128

// ---------------- scratch ----------------
static __device__ __half g_q  [(size_t)BHTOT * MEMQ  * DH];     // [bh][m][d]
static __device__ __half g_k  [(size_t)BHTOT * KVLEN * DH];     // [bh][j][d]
static __device__ __half g_v  [(size_t)BHTOT * DH * KVLEN];     // [bh][d][j]  (transposed)
static __device__ __half g_peT[(size_t)LWIN * DH];              // [l][d]
static __device__ __half g_pos[(size_t)BHTOT * MEMQ  * LWIN];   // fp16
static __device__ __half g_att[(size_t)NBATCH * MEMQ * HIDDIM]; // [b][m][h][d]
static __device__ __half g_qc [(size_t)NBATCH * MEMQ  * HIDDIM];
static __device__ __half g_kc [(size_t)NBATCH * KVLEN * HIDDIM];
static __device__ __half g_vc [(size_t)NBATCH * KVLEN * HIDDIM];
static __device__ __half g_w0 [(size_t)HIDDIM * HIDDIM];
static __device__ __half g_w1 [(size_t)HIDDIM * HIDDIM];
static __device__ __half g_w2 [(size_t)HIDDIM * HIDDIM];
static __device__ __half g_w3 [(size_t)HIDDIM * HIDDIM];

// ---------------- helpers ----------------
__device__ __forceinline__ uint32_t f2h2(float a, float b){
    __half2 h = __floats2half2_rn(a, b);
    return *reinterpret_cast<uint32_t*>(&h);
}
__device__ __forceinline__ void mma_f16(float c[4], const uint32_t a[4],
                                        uint32_t b0, uint32_t b1){
    asm("mma.sync.aligned.m16n8k16.row.col.f32.f16.f16.f32 "
        "{%0,%1,%2,%3}, {%4,%5,%6,%7}, {%8,%9}, {%0,%1,%2,%3};"
        : "+f"(c[0]), "+f"(c[1]), "+f"(c[2]), "+f"(c[3])
        : "r"(a[0]), "r"(a[1]), "r"(a[2]), "r"(a[3]), "r"(b0), "r"(b1));
}
__device__ __forceinline__ void cp_async16(void* sptr, const void* gptr){
    uint32_t sa = (uint32_t)__cvta_generic_to_shared(sptr);
    asm volatile("cp.async.cg.shared.global [%0], [%1], 16;\n" :: "r"(sa), "l"(gptr));
}
__device__ __forceinline__ uint32_t ldsm_u32(const __half* p){
    return *reinterpret_cast<const uint32_t*>(p);
}

// ---------------- merged cast + pe transpose, one launch ----------------
// blocks [0, ntot4/256): elementwise casts; blocks beyond: pe transpose.
__global__ void cast_all(const float4* __restrict__ sq, const float4* __restrict__ sk,
                         const float4* __restrict__ sv,
                         const float4* __restrict__ w0, const float4* __restrict__ w1,
                         const float4* __restrict__ w2, const float4* __restrict__ w3,
                         const float* __restrict__ pe,
                         uint2* __restrict__ dq, uint2* __restrict__ dk,
                         uint2* __restrict__ dv,
                         uint2* __restrict__ dw0, uint2* __restrict__ dw1,
                         uint2* __restrict__ dw2, uint2* __restrict__ dw3,
                         __half* __restrict__ peT,
                         int nq4, int nk4, int nw4, int ncast_blocks)
{
    if ((int)blockIdx.x >= ncast_blocks) {
        int idx = (blockIdx.x - ncast_blocks) * 256 + threadIdx.x;  // 131072 total
        int l = idx >> 6;
        int d = idx & 63;
        peT[idx] = __float2half_rn(pe[(size_t)d * LWIN + l]);
        return;
    }
    int i = blockIdx.x * 256 + threadIdx.x;
    const float4* s;
    uint2* d;
    int r;
    if (i < nq4)                { s = sq; d = dq; r = i; }
    else if (i < nq4 + nk4)     { s = sk; d = dk; r = i - nq4; }
    else if (i < nq4 + 2*nk4)   { s = sv; d = dv; r = i - nq4 - nk4; }
    else {
        int j = i - nq4 - 2*nk4;
        int m = j / nw4;
        r = j - m * nw4;
        s = (m == 0) ? w0 : (m == 1) ? w1 : (m == 2) ? w2 : w3;
        d = (m == 0) ? dw0 : (m == 1) ? dw1 : (m == 2) ? dw2 : dw3;
    }
    float4 v = s[r];
    uint2 o;
    o.x = f2h2(v.x, v.y);
    o.y = f2h2(v.z, v.w);
    d[r] = o;
}

#define HSTRIDE 72
#define HSTAGE  (256 * HSTRIDE)

// ---------------- merged projections (q/k/v) — one launch, block decode ----------------
__global__ __launch_bounds__(256, 2)
void proj_h(const __half* __restrict__ Aq, const __half* __restrict__ Ak,
            const __half* __restrict__ Av,
            const __half* __restrict__ B0, const __half* __restrict__ B1,
            const __half* __restrict__ B2,
            __half* __restrict__ Cq, __half* __restrict__ Ck, __half* __restrict__ Cv2)
{
    extern __shared__ __half smh[];

    const __half *A, *B;
    __half* C;
    int mode, S, bx, by;
    {
        int idx = blockIdx.x;
        if (idx < 256)        { A = Aq; B = B0; C = Cq;  mode = 1; S = MEMQ;  bx = idx & 31;  by = idx >> 5; }
        else if (idx < 1536)  { int j = idx - 256;  A = Ak; B = B1; C = Ck;  mode = 1; S = KVLEN; bx = j % 160; by = j / 160; }
        else                  { int j = idx - 1536; A = Av; B = B2; C = Cv2; mode = 2; S = KVLEN; bx = j % 160; by = j / 160; }
    }
    const int K = HIDDIM, lda = HIDDIM;
    const int rowBase = bx * 128;
    const int colBase = by * 128;

    const int tid  = threadIdx.x;
    const int warp = tid >> 5, lane = tid & 31;
    const int wm = warp >> 2, wn = warp & 3;
    const int g  = lane >> 2, tg = lane & 3;

    float acc[4][4][4];
    #pragma unroll
    for (int mt = 0; mt < 4; mt++)
        #pragma unroll
        for (int nt = 0; nt < 4; nt++)
            #pragma unroll
            for (int i = 0; i < 4; i++) acc[mt][nt][i] = 0.f;

    const int niter = K >> 6;

    auto load_tiles = [&](int st, int k0){
        __half* As = smh + st * HSTAGE;
        __half* Bs = As + 128 * HSTRIDE;
        #pragma unroll
        for (int i = 0; i < 4; i++) {
            int c = tid + i * 256;
            int row = c >> 3, ko = c & 7;
            cp_async16(&As[row * HSTRIDE + ko * 8],
                       A + (size_t)(rowBase + row) * lda + k0 + ko * 8);
        }
        #pragma unroll
        for (int i = 0; i < 4; i++) {
            int c = tid + i * 256;
            int row = c >> 3, ko = c & 7;
            cp_async16(&Bs[row * HSTRIDE + ko * 8],
                       B + (size_t)(colBase + row) * K + k0 + ko * 8);
        }
    };

    load_tiles(0, 0);
    asm volatile("cp.async.commit_group;\n" ::: "memory");

    for (int it = 0; it < niter; it++) {
        if (it + 1 < niter) load_tiles((it + 1) & 1, (it + 1) << 6);
        asm volatile("cp.async.commit_group;\n" ::: "memory");
        asm volatile("cp.async.wait_group 1;\n" ::: "memory");
        __syncthreads();

        const __half* As = smh + (it & 1) * HSTAGE;
        const __half* Bs = As + 128 * HSTRIDE;

        #pragma unroll
        for (int ks = 0; ks < 4; ks++) {
            const int kb = ks * 16;
            uint32_t a[4][4];
            #pragma unroll
            for (int mt = 0; mt < 4; mt++) {
                int r = wm * 64 + mt * 16 + g;
                a[mt][0] = ldsm_u32(&As[r * HSTRIDE       + kb     + 2*tg]);
                a[mt][1] = ldsm_u32(&As[(r + 8) * HSTRIDE + kb     + 2*tg]);
                a[mt][2] = ldsm_u32(&As[r * HSTRIDE       + kb + 8 + 2*tg]);
                a[mt][3] = ldsm_u32(&As[(r + 8) * HSTRIDE + kb + 8 + 2*tg]);
            }
            #pragma unroll
            for (int nt = 0; nt < 4; nt++) {
                int j = wn * 32 + nt * 8 + g;
                uint32_t b0 = ldsm_u32(&Bs[j * HSTRIDE + kb     + 2*tg]);
                uint32_t b1 = ldsm_u32(&Bs[j * HSTRIDE + kb + 8 + 2*tg]);
                #pragma unroll
                for (int mt = 0; mt < 4; mt++)
                    mma_f16(acc[mt][nt], a[mt], b0, b1);
            }
        }
        __syncthreads();
    }

    #pragma unroll
    for (int mt = 0; mt < 4; mt++) {
        int r = rowBase + wm * 64 + mt * 16 + g;
        #pragma unroll
        for (int nt = 0; nt < 4; nt++) {
            int jc = colBase + wn * 32 + nt * 8 + 2 * tg;
            int h = jc >> 6, d = jc & 63;
            int b1r = r / S,  s1 = r - b1r * S;
            int r2  = r + 8;
            int b2r = r2 / S, s2 = r2 - b2r * S;
            if (mode == 1) {
                __half* p0 = C + (((size_t)(b1r * NHEADS + h) * S + s1) << 6) + d;
                __half* p1 = C + (((size_t)(b2r * NHEADS + h) * S + s2) << 6) + d;
                *reinterpret_cast<uint32_t*>(p0) = f2h2(acc[mt][nt][0], acc[mt][nt][1]);
                *reinterpret_cast<uint32_t*>(p1) = f2h2(acc[mt][nt][2], acc[mt][nt][3]);
            } else {
                size_t base0 = ((size_t)(b1r * NHEADS + h) * DH + d) * S;
                size_t base1 = ((size_t)(b2r * NHEADS + h) * DH + d) * S;
                C[base0 + s1]     = __float2half_rn(acc[mt][nt][0]);
                C[base0 + S + s1] = __float2half_rn(acc[mt][nt][1]);
                C[base1 + s2]     = __float2half_rn(acc[mt][nt][2]);
                C[base1 + S + s2] = __float2half_rn(acc[mt][nt][3]);
            }
        }
    }
}

// ---------------- fp16 NT GEMM (Wo only; fp32 output) ----------------
__global__ __launch_bounds__(256, 2)
void gemm_h(const __half* __restrict__ A, int lda,
            const __half* __restrict__ B,
            float* __restrict__ C,
            int K, int ldc)
{
    extern __shared__ __half smh[];

    const int tid  = threadIdx.x;
    const int warp = tid >> 5, lane = tid & 31;
    const int wm = warp >> 2, wn = warp & 3;
    const int g  = lane >> 2, tg = lane & 3;
    const int rowBase = blockIdx.x * 128;
    const int colBase = blockIdx.y * 128;

    float acc[4][4][4];
    #pragma unroll
    for (int mt = 0; mt < 4; mt++)
        #pragma unroll
        for (int nt = 0; nt < 4; nt++)
            #pragma unroll
            for (int i = 0; i < 4; i++) acc[mt][nt][i] = 0.f;

    const int niter = K >> 6;

    auto load_tiles = [&](int st, int k0){
        __half* As = smh + st * HSTAGE;
        __half* Bs = As + 128 * HSTRIDE;
        #pragma unroll
        for (int i = 0; i < 4; i++) {
            int c = tid + i * 256;
            int row = c >> 3, ko = c & 7;
            cp_async16(&As[row * HSTRIDE + ko * 8],
                       A + (size_t)(rowBase + row) * lda + k0 + ko * 8);
        }
        #pragma unroll
        for (int i = 0; i < 4; i++) {
            int c = tid + i * 256;
            int row = c >> 3, ko = c & 7;
            cp_async16(&Bs[row * HSTRIDE + ko * 8],
                       B + (size_t)(colBase + row) * K + k0 + ko * 8);
        }
    };

    load_tiles(0, 0);
    asm volatile("cp.async.commit_group;\n" ::: "memory");

    for (int it = 0; it < niter; it++) {
        if (it + 1 < niter) load_tiles((it + 1) & 1, (it + 1) << 6);
        asm volatile("cp.async.commit_group;\n" ::: "memory");
        asm volatile("cp.async.wait_group 1;\n" ::: "memory");
        __syncthreads();

        const __half* As = smh + (it & 1) * HSTAGE;
        const __half* Bs = As + 128 * HSTRIDE;

        #pragma unroll
        for (int ks = 0; ks < 4; ks++) {
            const int kb = ks * 16;
            uint32_t a[4][4];
            #pragma unroll
            for (int mt = 0; mt < 4; mt++) {
                int r = wm * 64 + mt * 16 + g;
                a[mt][0] = ldsm_u32(&As[r * HSTRIDE       + kb     + 2*tg]);
                a[mt][1] = ldsm_u32(&As[(r + 8) * HSTRIDE + kb     + 2*tg]);
                a[mt][2] = ldsm_u32(&As[r * HSTRIDE       + kb + 8 + 2*tg]);
                a[mt][3] = ldsm_u32(&As[(r + 8) * HSTRIDE + kb + 8 + 2*tg]);
            }
            #pragma unroll
            for (int nt = 0; nt < 4; nt++) {
                int j = wn * 32 + nt * 8 + g;
                uint32_t b0 = ldsm_u32(&Bs[j * HSTRIDE + kb     + 2*tg]);
                uint32_t b1 = ldsm_u32(&Bs[j * HSTRIDE + kb + 8 + 2*tg]);
                #pragma unroll
                for (int mt = 0; mt < 4; mt++)
                    mma_f16(acc[mt][nt], a[mt], b0, b1);
            }
        }
        __syncthreads();
    }

    #pragma unroll
    for (int mt = 0; mt < 4; mt++) {
        int r = rowBase + wm * 64 + mt * 16 + g;
        #pragma unroll
        for (int nt = 0; nt < 4; nt++) {
            int jc = colBase + wn * 32 + nt * 8 + 2 * tg;
            C[(size_t)r       * ldc + jc    ] = acc[mt][nt][0];
            C[(size_t)r       * ldc + jc + 1] = acc[mt][nt][1];
            C[(size_t)(r + 8) * ldc + jc    ] = acc[mt][nt][2];
            C[(size_t)(r + 8) * ldc + jc + 1] = acc[mt][nt][3];
        }
    }
}

// ---------------- fp16 pos GEMM with smem-staged coalesced epilogue ----------------
__global__ __launch_bounds__(256, 3)
void pos_kernel(const __half* __restrict__ gq, const __half* __restrict__ peT,
                __half* __restrict__ gpos)
{
    extern __shared__ __half sph[];
    __half* As  = sph;                    // 128 x 72 (A tile, then per-ct store staging)
    __half* Bst = sph + 128 * HSTRIDE;    // 2 x (64 x 72)

    const int tid  = threadIdx.x;
    const int warp = tid >> 5, lane = tid & 31;
    const int g  = lane >> 2, tg = lane & 3;
    const int r0 = warp * 16 + g;
    const size_t rowBase = (size_t)blockIdx.x * 128;

    #pragma unroll
    for (int i = tid; i < 1024; i += 256) {
        int r = i >> 3, ko = i & 7;
        cp_async16(&As[r * HSTRIDE + ko * 8], gq + (rowBase + r) * DH + ko * 8);
    }
    asm volatile("cp.async.commit_group;\n" ::: "memory");

    #pragma unroll
    for (int i = tid; i < 512; i += 256) {
        int r = i >> 3, ko = i & 7;
        cp_async16(&Bst[r * HSTRIDE + ko * 8], peT + (size_t)r * DH + ko * 8);
    }
    asm volatile("cp.async.commit_group;\n" ::: "memory");
    asm volatile("cp.async.wait_group 1;\n" ::: "memory");
    __syncthreads();

    uint32_t qf[4][4];
    #pragma unroll
    for (int ks = 0; ks < 4; ks++) {
        const int kb = ks * 16;
        qf[ks][0] = ldsm_u32(&As[r0 * HSTRIDE       + kb     + 2*tg]);
        qf[ks][1] = ldsm_u32(&As[(r0+8) * HSTRIDE   + kb     + 2*tg]);
        qf[ks][2] = ldsm_u32(&As[r0 * HSTRIDE       + kb + 8 + 2*tg]);
        qf[ks][3] = ldsm_u32(&As[(r0+8) * HSTRIDE   + kb + 8 + 2*tg]);
    }
    __syncthreads();   // all quads hoisted before As is reused as staging

    for (int ct = 0; ct < 32; ct++) {
        if (ct + 1 < 32) {
            const __half* bsrc = peT + (size_t)(ct + 1) * 64 * DH;
            __half* Bn = Bst + ((ct + 1) & 1) * (64 * HSTRIDE);
            #pragma unroll
            for (int i = tid; i < 512; i += 256) {
                int r = i >> 3, ko = i & 7;
                cp_async16(&Bn[r * HSTRIDE + ko * 8], bsrc + (size_t)r * DH + ko * 8);
            }
            asm volatile("cp.async.commit_group;\n" ::: "memory");
            asm volatile("cp.async.wait_group 1;\n" ::: "memory");
        } else {
            asm volatile("cp.async.wait_group 0;\n" ::: "memory");
        }
        __syncthreads();

        const __half* Bs = Bst + (ct & 1) * (64 * HSTRIDE);

        float s[8][4];
        #pragma unroll
        for (int nt = 0; nt < 8; nt++)
            #pragma unroll
            for (int i = 0; i < 4; i++) s[nt][i] = 0.f;
        #pragma unroll
        for (int ks = 0; ks < 4; ks++) {
            const int kb = ks * 16;
            #pragma unroll
            for (int nt = 0; nt < 8; nt++) {
                int j = nt*8 + g;
                uint32_t b0 = ldsm_u32(&Bs[j * HSTRIDE + kb     + 2*tg]);
                uint32_t b1 = ldsm_u32(&Bs[j * HSTRIDE + kb + 8 + 2*tg]);
                mma_f16(s[nt], qf[ks], b0, b1);
            }
        }

        // stage fragments into As (conflict-free attn-proven pattern)
        #pragma unroll
        for (int nt = 0; nt < 8; nt++) {
            int col = nt*8 + 2*tg;
            *reinterpret_cast<uint32_t*>(&As[r0 * HSTRIDE + col])
                = f2h2(s[nt][0], s[nt][1]);
            *reinterpret_cast<uint32_t*>(&As[(r0+8) * HSTRIDE + col])
                = f2h2(s[nt][2], s[nt][3]);
        }
        __syncthreads();

        // coalesced copy-out: 8 lanes cover one 128-B row; 32 rows per sweep
        #pragma unroll
        for (int it2 = 0; it2 < 4; it2++) {
            int row = it2 * 32 + (tid >> 3);
            int o16 = (tid & 7) * 8;          // halfs offset (16B chunks)
            uint4 v = *reinterpret_cast<const uint4*>(&As[row * HSTRIDE + o16]);
            *reinterpret_cast<uint4*>(gpos + (rowBase + row) * (size_t)LWIN
                                      + ct * 64 + o16) = v;
        }
        __syncthreads();   // staging consumed before next iteration overwrites
    }
}

// ---------------- fp16 flash attention (pos bias in half) ----------------
__global__ __launch_bounds__(256, 2)
void attn_kernel(const __half* __restrict__ gq, const __half* __restrict__ gk,
                 const __half* __restrict__ gv, const __half* __restrict__ gpos,
                 __half* __restrict__ gatt)
{
    extern __shared__ __half smA[];
    __half* Ps = smA + 18432;       // 128 x 72 (also Q staging)

    const int bh = blockIdx.x;
    const int m0 = blockIdx.y * QTILE;
    const int tid  = threadIdx.x;
    const int warp = tid >> 5, lane = tid & 31;
    const int g  = lane >> 2, tg = lane & 3;
    const int r0 = warp*16 + g;

    {
        const __half* qb = gq + ((size_t)bh * MEMQ + m0) * DH;
        #pragma unroll
        for (int i = tid; i < 1024; i += 256) {
            int r = i >> 3, ko = i & 7;
            cp_async16(&Ps[r * HSTRIDE + ko * 8], qb + r * DH + ko * 8);
        }
    }
    asm volatile("cp.async.commit_group;\n" ::: "memory");

    {
        const __half* kb = gk + ((size_t)bh * KVLEN + m0) * DH;
        const __half* vb = gv + ((size_t)bh * DH) * KVLEN + m0;
        __half* Ks = smA;
        __half* Vs = smA + 4608;
        #pragma unroll
        for (int i = tid; i < 512; i += 256) {
            int r = i >> 3, ko = i & 7;
            cp_async16(&Ks[r * HSTRIDE + ko * 8], kb + r * DH + ko * 8);
            cp_async16(&Vs[r * HSTRIDE + ko * 8], vb + (size_t)r * KVLEN + ko * 8);
        }
    }
    asm volatile("cp.async.commit_group;\n" ::: "memory");
    asm volatile("cp.async.wait_group 1;\n" ::: "memory");
    __syncthreads();

    uint32_t qf[4][4];
    #pragma unroll
    for (int ks = 0; ks < 4; ks++) {
        const int kb = ks * 16;
        qf[ks][0] = ldsm_u32(&Ps[r0 * HSTRIDE       + kb     + 2*tg]);
        qf[ks][1] = ldsm_u32(&Ps[(r0+8) * HSTRIDE   + kb     + 2*tg]);
        qf[ks][2] = ldsm_u32(&Ps[r0 * HSTRIDE       + kb + 8 + 2*tg]);
        qf[ks][3] = ldsm_u32(&Ps[(r0+8) * HSTRIDE   + kb + 8 + 2*tg]);
    }

    float o[8][4];
    #pragma unroll
    for (int nt = 0; nt < 8; nt++)
        #pragma unroll
        for (int i = 0; i < 4; i++) o[nt][i] = 0.f;
    float mi0 = -1e30f, mi1 = -1e30f, li0 = 0.f, li1 = 0.f;

    const __half* posr0 = gpos + ((size_t)bh * MEMQ + m0 + r0) * LWIN;
    const __half* posr1 = posr0 + (size_t)8 * LWIN;

    for (int t = 0; t < 34; t++) {
        __syncthreads();
        if (t + 1 < 34) {
            const int j1 = m0 + (t + 1) * 64;
            const __half* kb = gk + ((size_t)bh * KVLEN + j1) * DH;
            const __half* vb = gv + ((size_t)bh * DH) * KVLEN + j1;
            __half* Kn = smA + ((t + 1) & 1) * 9216;
            __half* Vn = Kn + 4608;
            #pragma unroll
            for (int i = tid; i < 512; i += 256) {
                int r = i >> 3, ko = i & 7;
                cp_async16(&Kn[r * HSTRIDE + ko * 8], kb + r * DH + ko * 8);
                cp_async16(&Vn[r * HSTRIDE + ko * 8], vb + (size_t)r * KVLEN + ko * 8);
            }
            asm volatile("cp.async.commit_group;\n" ::: "memory");
            asm volatile("cp.async.wait_group 1;\n" ::: "memory");
        } else {
            asm volatile("cp.async.wait_group 0;\n" ::: "memory");
        }
        __syncthreads();

        const __half* Ks = smA + (t & 1) * 9216;
        const __half* Vs = Ks + 4608;

        float s[8][4];
        #pragma unroll
        for (int nt = 0; nt < 8; nt++)
            #pragma unroll
            for (int i = 0; i < 4; i++) s[nt][i] = 0.f;
        #pragma unroll
        for (int ks = 0; ks < 4; ks++) {
            const int kb = ks * 16;
            #pragma unroll
            for (int nt = 0; nt < 8; nt++) {
                int j = nt*8 + g;
                uint32_t b0 = ldsm_u32(&Ks[j * HSTRIDE + kb     + 2*tg]);
                uint32_t b1 = ldsm_u32(&Ks[j * HSTRIDE + kb + 8 + 2*tg]);
                mma_f16(s[nt], qf[ks], b0, b1);
            }
        }

        #pragma unroll
        for (int nt = 0; nt < 8; nt++) {
            int jj = nt*8 + 2*tg;
            int lA = t*64 + jj - r0;
            int lB = lA - 8;
            #pragma unroll
            for (int e = 0; e < 2; e++) {
                int l1 = lA + e;
                s[nt][e]     = (l1 >= 0 && l1 < LWIN)
                             ? (s[nt][e]     + __half2float(__ldg(posr0 + l1))) * 0.125f
                             : -1e30f;
                int l2 = lB + e;
                s[nt][2 + e] = (l2 >= 0 && l2 < LWIN)
                             ? (s[nt][2 + e] + __half2float(__ldg(posr1 + l2))) * 0.125f
                             : -1e30f;
            }
        }

        float mx0 = -1e30f, mx1 = -1e30f;
        #pragma unroll
        for (int nt = 0; nt < 8; nt++) {
            mx0 = fmaxf(mx0, fmaxf(s[nt][0], s[nt][1]));
            mx1 = fmaxf(mx1, fmaxf(s[nt][2], s[nt][3]));
        }
        mx0 = fmaxf(mx0, __shfl_xor_sync(0xffffffffu, mx0, 1));
        mx0 = fmaxf(mx0, __shfl_xor_sync(0xffffffffu, mx0, 2));
        mx1 = fmaxf(mx1, __shfl_xor_sync(0xffffffffu, mx1, 1));
        mx1 = fmaxf(mx1, __shfl_xor_sync(0xffffffffu, mx1, 2));
        float mn0 = fmaxf(mi0, mx0), mn1 = fmaxf(mi1, mx1);
        float al0 = __expf(mi0 - mn0), al1 = __expf(mi1 - mn1);
        float rs0 = 0.f, rs1 = 0.f;
        #pragma unroll
        for (int nt = 0; nt < 8; nt++) {
            s[nt][0] = __expf(s[nt][0] - mn0);
            s[nt][1] = __expf(s[nt][1] - mn0);
            s[nt][2] = __expf(s[nt][2] - mn1);
            s[nt][3] = __expf(s[nt][3] - mn1);
            rs0 += s[nt][0] + s[nt][1];
            rs1 += s[nt][2] + s[nt][3];
        }
        rs0 += __shfl_xor_sync(0xffffffffu, rs0, 1);
        rs0 += __shfl_xor_sync(0xffffffffu, rs0, 2);
        rs1 += __shfl_xor_sync(0xffffffffu, rs1, 1);
        rs1 += __shfl_xor_sync(0xffffffffu, rs1, 2);
        li0 = li0 * al0 + rs0;
        li1 = li1 * al1 + rs1;
        mi0 = mn0; mi1 = mn1;

        #pragma unroll
        for (int nt = 0; nt < 8; nt++) {
            o[nt][0] *= al0; o[nt][1] *= al0; o[nt][2] *= al1; o[nt][3] *= al1;
            int col = nt*8 + 2*tg;
            *reinterpret_cast<uint32_t*>(&Ps[r0 * HSTRIDE + col])
                = f2h2(s[nt][0], s[nt][1]);
            *reinterpret_cast<uint32_t*>(&Ps[(r0+8) * HSTRIDE + col])
                = f2h2(s[nt][2], s[nt][3]);
        }
        __syncwarp();

        #pragma unroll
        for (int ks = 0; ks < 4; ks++) {
            const int kb = ks * 16;
            uint32_t a[4];
            a[0] = ldsm_u32(&Ps[r0 * HSTRIDE       + kb     + 2*tg]);
            a[1] = ldsm_u32(&Ps[(r0+8) * HSTRIDE   + kb     + 2*tg]);
            a[2] = ldsm_u32(&Ps[r0 * HSTRIDE       + kb + 8 + 2*tg]);
            a[3] = ldsm_u32(&Ps[(r0+8) * HSTRIDE   + kb + 8 + 2*tg]);
            #pragma unroll
            for (int nt = 0; nt < 8; nt++) {
                int d = nt*8 + g;
                uint32_t b0 = ldsm_u32(&Vs[d * HSTRIDE + kb     + 2*tg]);
                uint32_t b1 = ldsm_u32(&Vs[d * HSTRIDE + kb + 8 + 2*tg]);
                mma_f16(o[nt], a, b0, b1);
            }
        }
        __syncwarp();
    }

    const float inv0 = 1.f / li0, inv1 = 1.f / li1;
    const int b = bh >> 4, h = bh & 15;
    #pragma unroll
    for (int nt = 0; nt < 8; nt++) {
        int d = nt*8 + 2*tg;
        size_t i0 = (((size_t)(b*MEMQ + (m0 + r0    )) * NHEADS + h) << 6) + d;
        size_t i1 = (((size_t)(b*MEMQ + (m0 + r0 + 8)) * NHEADS + h) << 6) + d;
        *reinterpret_cast<uint32_t*>(&gatt[i0]) = f2h2(o[nt][0] * inv0, o[nt][1] * inv0);
        *reinterpret_cast<uint32_t*>(&gatt[i1]) = f2h2(o[nt][2] * inv1, o[nt][3] * inv1);
    }
}

// ---------------- launch ----------------
extern "C" void kernel_launch(void* const* d_in, const int* in_sizes, int n_in,
                              void* d_out, int out_size)
{
    const float* query = (const float*)d_in[0];
    const float* key   = (const float*)d_in[1];
    const float* value = (const float*)d_in[2];
    const float* keype = (const float*)d_in[3];
    const float* Wq    = (const float*)d_in[4];
    const float* Wk    = (const float*)d_in[5];
    const float* Wv    = (const float*)d_in[6];
    const float* Wo    = (const float*)d_in[7];
    float* out = (float*)d_out;

    __half *pq, *pk, *pv, *ppeT, *ppos, *patt, *pqc, *pkc, *pvc, *pw0, *pw1, *pw2, *pw3;
    cudaGetSymbolAddress((void**)&pq,   g_q);
    cudaGetSymbolAddress((void**)&pk,   g_k);
    cudaGetSymbolAddress((void**)&pv,   g_v);
    cudaGetSymbolAddress((void**)&ppeT, g_peT);
    cudaGetSymbolAddress((void**)&ppos, g_pos);
    cudaGetSymbolAddress((void**)&patt, g_att);
    cudaGetSymbolAddress((void**)&pqc,  g_qc);
    cudaGetSymbolAddress((void**)&pkc,  g_kc);
    cudaGetSymbolAddress((void**)&pvc,  g_vc);
    cudaGetSymbolAddress((void**)&pw0,  g_w0);
    cudaGetSymbolAddress((void**)&pw1,  g_w1);
    cudaGetSymbolAddress((void**)&pw2,  g_w2);
    cudaGetSymbolAddress((void**)&pw3,  g_w3);

    const int gemm_smem = 2 * HSTAGE * 2;                          // 73728 B
    const int pos_smem  = (128 * HSTRIDE + 2 * 64 * HSTRIDE) * 2;  // 36864 B
    const int attn_smem = (2 * 9216 + 128 * HSTRIDE) * 2;          // 55296 B
    cudaFuncSetAttribute(proj_h, cudaFuncAttributeMaxDynamicSharedMemorySize, gemm_smem);
    cudaFuncSetAttribute(gemm_h, cudaFuncAttributeMaxDynamicSharedMemorySize, gemm_smem);
    cudaFuncSetAttribute(pos_kernel, cudaFuncAttributeMaxDynamicSharedMemorySize, pos_smem);
    cudaFuncSetAttribute(attn_kernel, cudaFuncAttributeMaxDynamicSharedMemorySize, attn_smem);

    const int nq4 = NBATCH * MEMQ  * HIDDIM / 4;   // 1,048,576
    const int nk4 = NBATCH * KVLEN * HIDDIM / 4;   // 5,242,880
    const int nw4 = HIDDIM * HIDDIM / 4;           // 262,144
    const int ntot4 = nq4 + 2 * nk4 + 4 * nw4;     // 12,582,912
    const int ncast_blocks = ntot4 / 256;          // 49152
    const int npe_blocks = (LWIN * DH) / 256;      // 512

    cast_all<<<ncast_blocks + npe_blocks, 256>>>(
        (const float4*)query, (const float4*)key, (const float4*)value,
        (const float4*)Wq, (const float4*)Wk, (const float4*)Wv, (const float4*)Wo,
        keype,
        (uint2*)pqc, (uint2*)pkc, (uint2*)pvc,
        (uint2*)pw0, (uint2*)pw1, (uint2*)pw2, (uint2*)pw3,
        ppeT, nq4, nk4, nw4, ncast_blocks);

    proj_h<<<2816, 256, gemm_smem>>>(pqc, pkc, pvc, pw0, pw1, pw2, pq, pk, pv);
    pos_kernel<<<512, 256, pos_smem>>>(pq, ppeT, ppos);
    attn_kernel<<<dim3(BHTOT, 4), 256, attn_smem>>>(pq, pk, pv, ppos, patt);
    gemm_h<<<dim3(32, 8), 256, gemm_smem>>>(patt, HIDDIM, pw3, out, HIDDIM, HIDDIM);
}

// round 17
// speedup vs baseline: 1.9276x; 1.0247x over previous
#include <cuda_runtime.h>
#include <cuda_fp16.h>
#include <cstdint>
#include <cstddef>

#define HIDDIM 1024
#define NHEADS 16
#define MEMQ   512
#define LWIN   2048
#define KVLEN  2560
#define DH     64
#define NBATCH 8
#define BHTOT  128
#define QTILE  128

// ---------------- scratch ----------------
static __device__ __half g_q  [(size_t)BHTOT * MEMQ  * DH];     // [bh][m][d]
static __device__ __half g_k  [(size_t)BHTOT * KVLEN * DH];     // [bh][j][d]
static __device__ __half g_v  [(size_t)BHTOT * DH * KVLEN];     // [bh][d][j]  (transposed)
static __device__ __half g_peT[(size_t)LWIN * DH];              // [l][d]
static __device__ __half g_pos[(size_t)BHTOT * MEMQ  * LWIN];   // fp16
static __device__ __half g_att[(size_t)NBATCH * MEMQ * HIDDIM]; // [b][m][h][d]
static __device__ __half g_qc [(size_t)NBATCH * MEMQ  * HIDDIM];
static __device__ __half g_kc [(size_t)NBATCH * KVLEN * HIDDIM];
static __device__ __half g_vc [(size_t)NBATCH * KVLEN * HIDDIM];
static __device__ __half g_w0 [(size_t)HIDDIM * HIDDIM];
static __device__ __half g_w1 [(size_t)HIDDIM * HIDDIM];
static __device__ __half g_w2 [(size_t)HIDDIM * HIDDIM];
static __device__ __half g_w3 [(size_t)HIDDIM * HIDDIM];

// ---------------- helpers ----------------
__device__ __forceinline__ uint32_t f2h2(float a, float b){
    __half2 h = __floats2half2_rn(a, b);
    return *reinterpret_cast<uint32_t*>(&h);
}
__device__ __forceinline__ void mma_f16(float c[4], const uint32_t a[4],
                                        uint32_t b0, uint32_t b1){
    asm("mma.sync.aligned.m16n8k16.row.col.f32.f16.f16.f32 "
        "{%0,%1,%2,%3}, {%4,%5,%6,%7}, {%8,%9}, {%0,%1,%2,%3};"
        : "+f"(c[0]), "+f"(c[1]), "+f"(c[2]), "+f"(c[3])
        : "r"(a[0]), "r"(a[1]), "r"(a[2]), "r"(a[3]), "r"(b0), "r"(b1));
}
__device__ __forceinline__ void cp_async16(void* sptr, const void* gptr){
    uint32_t sa = (uint32_t)__cvta_generic_to_shared(sptr);
    asm volatile("cp.async.cg.shared.global [%0], [%1], 16;\n" :: "r"(sa), "l"(gptr));
}
__device__ __forceinline__ uint32_t ldsm_u32(const __half* p){
    return *reinterpret_cast<const uint32_t*>(p);
}

// ---------------- merged cast + pe transpose, one launch ----------------
__global__ void cast_all(const float4* __restrict__ sq, const float4* __restrict__ sk,
                         const float4* __restrict__ sv,
                         const float4* __restrict__ w0, const float4* __restrict__ w1,
                         const float4* __restrict__ w2, const float4* __restrict__ w3,
                         const float* __restrict__ pe,
                         uint2* __restrict__ dq, uint2* __restrict__ dk,
                         uint2* __restrict__ dv,
                         uint2* __restrict__ dw0, uint2* __restrict__ dw1,
                         uint2* __restrict__ dw2, uint2* __restrict__ dw3,
                         __half* __restrict__ peT,
                         int nq4, int nk4, int nw4, int ncast_blocks)
{
    if ((int)blockIdx.x >= ncast_blocks) {
        int idx = (blockIdx.x - ncast_blocks) * 256 + threadIdx.x;
        int l = idx >> 6;
        int d = idx & 63;
        peT[idx] = __float2half_rn(pe[(size_t)d * LWIN + l]);
        return;
    }
    int i = blockIdx.x * 256 + threadIdx.x;
    const float4* s;
    uint2* d;
    int r;
    if (i < nq4)                { s = sq; d = dq; r = i; }
    else if (i < nq4 + nk4)     { s = sk; d = dk; r = i - nq4; }
    else if (i < nq4 + 2*nk4)   { s = sv; d = dv; r = i - nq4 - nk4; }
    else {
        int j = i - nq4 - 2*nk4;
        int m = j / nw4;
        r = j - m * nw4;
        s = (m == 0) ? w0 : (m == 1) ? w1 : (m == 2) ? w2 : w3;
        d = (m == 0) ? dw0 : (m == 1) ? dw1 : (m == 2) ? dw2 : dw3;
    }
    float4 v = s[r];
    uint2 o;
    o.x = f2h2(v.x, v.y);
    o.y = f2h2(v.z, v.w);
    d[r] = o;
}

#define HSTRIDE 72
#define HSTAGE  (256 * HSTRIDE)

// ---------------- merged projections (q/k/v) — one launch, block decode ----------------
__global__ __launch_bounds__(256, 2)
void proj_h(const __half* __restrict__ Aq, const __half* __restrict__ Ak,
            const __half* __restrict__ Av,
            const __half* __restrict__ B0, const __half* __restrict__ B1,
            const __half* __restrict__ B2,
            __half* __restrict__ Cq, __half* __restrict__ Ck, __half* __restrict__ Cv2)
{
    extern __shared__ __half smh[];

    const __half *A, *B;
    __half* C;
    int mode, S, bx, by;
    {
        int idx = blockIdx.x;
        if (idx < 256)        { A = Aq; B = B0; C = Cq;  mode = 1; S = MEMQ;  bx = idx & 31;  by = idx >> 5; }
        else if (idx < 1536)  { int j = idx - 256;  A = Ak; B = B1; C = Ck;  mode = 1; S = KVLEN; bx = j % 160; by = j / 160; }
        else                  { int j = idx - 1536; A = Av; B = B2; C = Cv2; mode = 2; S = KVLEN; bx = j % 160; by = j / 160; }
    }
    const int K = HIDDIM, lda = HIDDIM;
    const int rowBase = bx * 128;
    const int colBase = by * 128;

    const int tid  = threadIdx.x;
    const int warp = tid >> 5, lane = tid & 31;
    const int wm = warp >> 2, wn = warp & 3;
    const int g  = lane >> 2, tg = lane & 3;

    float acc[4][4][4];
    #pragma unroll
    for (int mt = 0; mt < 4; mt++)
        #pragma unroll
        for (int nt = 0; nt < 4; nt++)
            #pragma unroll
            for (int i = 0; i < 4; i++) acc[mt][nt][i] = 0.f;

    const int niter = K >> 6;

    auto load_tiles = [&](int st, int k0){
        __half* As = smh + st * HSTAGE;
        __half* Bs = As + 128 * HSTRIDE;
        #pragma unroll
        for (int i = 0; i < 4; i++) {
            int c = tid + i * 256;
            int row = c >> 3, ko = c & 7;
            cp_async16(&As[row * HSTRIDE + ko * 8],
                       A + (size_t)(rowBase + row) * lda + k0 + ko * 8);
        }
        #pragma unroll
        for (int i = 0; i < 4; i++) {
            int c = tid + i * 256;
            int row = c >> 3, ko = c & 7;
            cp_async16(&Bs[row * HSTRIDE + ko * 8],
                       B + (size_t)(colBase + row) * K + k0 + ko * 8);
        }
    };

    load_tiles(0, 0);
    asm volatile("cp.async.commit_group;\n" ::: "memory");

    for (int it = 0; it < niter; it++) {
        if (it + 1 < niter) load_tiles((it + 1) & 1, (it + 1) << 6);
        asm volatile("cp.async.commit_group;\n" ::: "memory");
        asm volatile("cp.async.wait_group 1;\n" ::: "memory");
        __syncthreads();

        const __half* As = smh + (it & 1) * HSTAGE;
        const __half* Bs = As + 128 * HSTRIDE;

        #pragma unroll
        for (int ks = 0; ks < 4; ks++) {
            const int kb = ks * 16;
            uint32_t a[4][4];
            #pragma unroll
            for (int mt = 0; mt < 4; mt++) {
                int r = wm * 64 + mt * 16 + g;
                a[mt][0] = ldsm_u32(&As[r * HSTRIDE       + kb     + 2*tg]);
                a[mt][1] = ldsm_u32(&As[(r + 8) * HSTRIDE + kb     + 2*tg]);
                a[mt][2] = ldsm_u32(&As[r * HSTRIDE       + kb + 8 + 2*tg]);
                a[mt][3] = ldsm_u32(&As[(r + 8) * HSTRIDE + kb + 8 + 2*tg]);
            }
            #pragma unroll
            for (int nt = 0; nt < 4; nt++) {
                int j = wn * 32 + nt * 8 + g;
                uint32_t b0 = ldsm_u32(&Bs[j * HSTRIDE + kb     + 2*tg]);
                uint32_t b1 = ldsm_u32(&Bs[j * HSTRIDE + kb + 8 + 2*tg]);
                #pragma unroll
                for (int mt = 0; mt < 4; mt++)
                    mma_f16(acc[mt][nt], a[mt], b0, b1);
            }
        }
        __syncthreads();
    }

    #pragma unroll
    for (int mt = 0; mt < 4; mt++) {
        int r = rowBase + wm * 64 + mt * 16 + g;
        #pragma unroll
        for (int nt = 0; nt < 4; nt++) {
            int jc = colBase + wn * 32 + nt * 8 + 2 * tg;
            int h = jc >> 6, d = jc & 63;
            int b1r = r / S,  s1 = r - b1r * S;
            int r2  = r + 8;
            int b2r = r2 / S, s2 = r2 - b2r * S;
            if (mode == 1) {
                __half* p0 = C + (((size_t)(b1r * NHEADS + h) * S + s1) << 6) + d;
                __half* p1 = C + (((size_t)(b2r * NHEADS + h) * S + s2) << 6) + d;
                *reinterpret_cast<uint32_t*>(p0) = f2h2(acc[mt][nt][0], acc[mt][nt][1]);
                *reinterpret_cast<uint32_t*>(p1) = f2h2(acc[mt][nt][2], acc[mt][nt][3]);
            } else {
                size_t base0 = ((size_t)(b1r * NHEADS + h) * DH + d) * S;
                size_t base1 = ((size_t)(b2r * NHEADS + h) * DH + d) * S;
                C[base0 + s1]     = __float2half_rn(acc[mt][nt][0]);
                C[base0 + S + s1] = __float2half_rn(acc[mt][nt][1]);
                C[base1 + s2]     = __float2half_rn(acc[mt][nt][2]);
                C[base1 + S + s2] = __float2half_rn(acc[mt][nt][3]);
            }
        }
    }
}

// ---------------- fp16 NT GEMM (Wo only; fp32 output) ----------------
__global__ __launch_bounds__(256, 2)
void gemm_h(const __half* __restrict__ A, int lda,
            const __half* __restrict__ B,
            float* __restrict__ C,
            int K, int ldc)
{
    extern __shared__ __half smh[];

    const int tid  = threadIdx.x;
    const int warp = tid >> 5, lane = tid & 31;
    const int wm = warp >> 2, wn = warp & 3;
    const int g  = lane >> 2, tg = lane & 3;
    const int rowBase = blockIdx.x * 128;
    const int colBase = blockIdx.y * 128;

    float acc[4][4][4];
    #pragma unroll
    for (int mt = 0; mt < 4; mt++)
        #pragma unroll
        for (int nt = 0; nt < 4; nt++)
            #pragma unroll
            for (int i = 0; i < 4; i++) acc[mt][nt][i] = 0.f;

    const int niter = K >> 6;

    auto load_tiles = [&](int st, int k0){
        __half* As = smh + st * HSTAGE;
        __half* Bs = As + 128 * HSTRIDE;
        #pragma unroll
        for (int i = 0; i < 4; i++) {
            int c = tid + i * 256;
            int row = c >> 3, ko = c & 7;
            cp_async16(&As[row * HSTRIDE + ko * 8],
                       A + (size_t)(rowBase + row) * lda + k0 + ko * 8);
        }
        #pragma unroll
        for (int i = 0; i < 4; i++) {
            int c = tid + i * 256;
            int row = c >> 3, ko = c & 7;
            cp_async16(&Bs[row * HSTRIDE + ko * 8],
                       B + (size_t)(colBase + row) * K + k0 + ko * 8);
        }
    };

    load_tiles(0, 0);
    asm volatile("cp.async.commit_group;\n" ::: "memory");

    for (int it = 0; it < niter; it++) {
        if (it + 1 < niter) load_tiles((it + 1) & 1, (it + 1) << 6);
        asm volatile("cp.async.commit_group;\n" ::: "memory");
        asm volatile("cp.async.wait_group 1;\n" ::: "memory");
        __syncthreads();

        const __half* As = smh + (it & 1) * HSTAGE;
        const __half* Bs = As + 128 * HSTRIDE;

        #pragma unroll
        for (int ks = 0; ks < 4; ks++) {
            const int kb = ks * 16;
            uint32_t a[4][4];
            #pragma unroll
            for (int mt = 0; mt < 4; mt++) {
                int r = wm * 64 + mt * 16 + g;
                a[mt][0] = ldsm_u32(&As[r * HSTRIDE       + kb     + 2*tg]);
                a[mt][1] = ldsm_u32(&As[(r + 8) * HSTRIDE + kb     + 2*tg]);
                a[mt][2] = ldsm_u32(&As[r * HSTRIDE       + kb + 8 + 2*tg]);
                a[mt][3] = ldsm_u32(&As[(r + 8) * HSTRIDE + kb + 8 + 2*tg]);
            }
            #pragma unroll
            for (int nt = 0; nt < 4; nt++) {
                int j = wn * 32 + nt * 8 + g;
                uint32_t b0 = ldsm_u32(&Bs[j * HSTRIDE + kb     + 2*tg]);
                uint32_t b1 = ldsm_u32(&Bs[j * HSTRIDE + kb + 8 + 2*tg]);
                #pragma unroll
                for (int mt = 0; mt < 4; mt++)
                    mma_f16(acc[mt][nt], a[mt], b0, b1);
            }
        }
        __syncthreads();
    }

    #pragma unroll
    for (int mt = 0; mt < 4; mt++) {
        int r = rowBase + wm * 64 + mt * 16 + g;
        #pragma unroll
        for (int nt = 0; nt < 4; nt++) {
            int jc = colBase + wn * 32 + nt * 8 + 2 * tg;
            C[(size_t)r       * ldc + jc    ] = acc[mt][nt][0];
            C[(size_t)r       * ldc + jc + 1] = acc[mt][nt][1];
            C[(size_t)(r + 8) * ldc + jc    ] = acc[mt][nt][2];
            C[(size_t)(r + 8) * ldc + jc + 1] = acc[mt][nt][3];
        }
    }
}

// ---------------- fp16 pos GEMM with smem-staged coalesced epilogue ----------------
__global__ __launch_bounds__(256, 3)
void pos_kernel(const __half* __restrict__ gq, const __half* __restrict__ peT,
                __half* __restrict__ gpos)
{
    extern __shared__ __half sph[];
    __half* As  = sph;                    // 128 x 72 (A tile, then per-ct store staging)
    __half* Bst = sph + 128 * HSTRIDE;    // 2 x (64 x 72)

    const int tid  = threadIdx.x;
    const int warp = tid >> 5, lane = tid & 31;
    const int g  = lane >> 2, tg = lane & 3;
    const int r0 = warp * 16 + g;
    const size_t rowBase = (size_t)blockIdx.x * 128;

    #pragma unroll
    for (int i = tid; i < 1024; i += 256) {
        int r = i >> 3, ko = i & 7;
        cp_async16(&As[r * HSTRIDE + ko * 8], gq + (rowBase + r) * DH + ko * 8);
    }
    asm volatile("cp.async.commit_group;\n" ::: "memory");

    #pragma unroll
    for (int i = tid; i < 512; i += 256) {
        int r = i >> 3, ko = i & 7;
        cp_async16(&Bst[r * HSTRIDE + ko * 8], peT + (size_t)r * DH + ko * 8);
    }
    asm volatile("cp.async.commit_group;\n" ::: "memory");
    asm volatile("cp.async.wait_group 1;\n" ::: "memory");
    __syncthreads();

    uint32_t qf[4][4];
    #pragma unroll
    for (int ks = 0; ks < 4; ks++) {
        const int kb = ks * 16;
        qf[ks][0] = ldsm_u32(&As[r0 * HSTRIDE       + kb     + 2*tg]);
        qf[ks][1] = ldsm_u32(&As[(r0+8) * HSTRIDE   + kb     + 2*tg]);
        qf[ks][2] = ldsm_u32(&As[r0 * HSTRIDE       + kb + 8 + 2*tg]);
        qf[ks][3] = ldsm_u32(&As[(r0+8) * HSTRIDE   + kb + 8 + 2*tg]);
    }
    __syncthreads();

    for (int ct = 0; ct < 32; ct++) {
        if (ct + 1 < 32) {
            const __half* bsrc = peT + (size_t)(ct + 1) * 64 * DH;
            __half* Bn = Bst + ((ct + 1) & 1) * (64 * HSTRIDE);
            #pragma unroll
            for (int i = tid; i < 512; i += 256) {
                int r = i >> 3, ko = i & 7;
                cp_async16(&Bn[r * HSTRIDE + ko * 8], bsrc + (size_t)r * DH + ko * 8);
            }
            asm volatile("cp.async.commit_group;\n" ::: "memory");
            asm volatile("cp.async.wait_group 1;\n" ::: "memory");
        } else {
            asm volatile("cp.async.wait_group 0;\n" ::: "memory");
        }
        __syncthreads();

        const __half* Bs = Bst + (ct & 1) * (64 * HSTRIDE);

        float s[8][4];
        #pragma unroll
        for (int nt = 0; nt < 8; nt++)
            #pragma unroll
            for (int i = 0; i < 4; i++) s[nt][i] = 0.f;
        #pragma unroll
        for (int ks = 0; ks < 4; ks++) {
            const int kb = ks * 16;
            #pragma unroll
            for (int nt = 0; nt < 8; nt++) {
                int j = nt*8 + g;
                uint32_t b0 = ldsm_u32(&Bs[j * HSTRIDE + kb     + 2*tg]);
                uint32_t b1 = ldsm_u32(&Bs[j * HSTRIDE + kb + 8 + 2*tg]);
                mma_f16(s[nt], qf[ks], b0, b1);
            }
        }

        #pragma unroll
        for (int nt = 0; nt < 8; nt++) {
            int col = nt*8 + 2*tg;
            *reinterpret_cast<uint32_t*>(&As[r0 * HSTRIDE + col])
                = f2h2(s[nt][0], s[nt][1]);
            *reinterpret_cast<uint32_t*>(&As[(r0+8) * HSTRIDE + col])
                = f2h2(s[nt][2], s[nt][3]);
        }
        __syncthreads();

        #pragma unroll
        for (int it2 = 0; it2 < 4; it2++) {
            int row = it2 * 32 + (tid >> 3);
            int o16 = (tid & 7) * 8;
            uint4 v = *reinterpret_cast<const uint4*>(&As[row * HSTRIDE + o16]);
            *reinterpret_cast<uint4*>(gpos + (rowBase + row) * (size_t)LWIN
                                      + ct * 64 + o16) = v;
        }
        __syncthreads();
    }
}

// ---------------- fp16 flash attention: P kept in registers (no smem round-trip) ----------------
__global__ __launch_bounds__(256, 2)
void attn_kernel(const __half* __restrict__ gq, const __half* __restrict__ gk,
                 const __half* __restrict__ gv, const __half* __restrict__ gpos,
                 __half* __restrict__ gatt)
{
    extern __shared__ __half smA[];
    __half* Qst = smA + 18432;      // 128 x 72 (Q staging only)

    const int bh = blockIdx.x;
    const int m0 = blockIdx.y * QTILE;
    const int tid  = threadIdx.x;
    const int warp = tid >> 5, lane = tid & 31;
    const int g  = lane >> 2, tg = lane & 3;
    const int r0 = warp*16 + g;

    {
        const __half* qb = gq + ((size_t)bh * MEMQ + m0) * DH;
        #pragma unroll
        for (int i = tid; i < 1024; i += 256) {
            int r = i >> 3, ko = i & 7;
            cp_async16(&Qst[r * HSTRIDE + ko * 8], qb + r * DH + ko * 8);
        }
    }
    asm volatile("cp.async.commit_group;\n" ::: "memory");

    {
        const __half* kb = gk + ((size_t)bh * KVLEN + m0) * DH;
        const __half* vb = gv + ((size_t)bh * DH) * KVLEN + m0;
        __half* Ks = smA;
        __half* Vs = smA + 4608;
        #pragma unroll
        for (int i = tid; i < 512; i += 256) {
            int r = i >> 3, ko = i & 7;
            cp_async16(&Ks[r * HSTRIDE + ko * 8], kb + r * DH + ko * 8);
            cp_async16(&Vs[r * HSTRIDE + ko * 8], vb + (size_t)r * KVLEN + ko * 8);
        }
    }
    asm volatile("cp.async.commit_group;\n" ::: "memory");
    asm volatile("cp.async.wait_group 1;\n" ::: "memory");
    __syncthreads();

    uint32_t qf[4][4];
    #pragma unroll
    for (int ks = 0; ks < 4; ks++) {
        const int kb = ks * 16;
        qf[ks][0] = ldsm_u32(&Qst[r0 * HSTRIDE       + kb     + 2*tg]);
        qf[ks][1] = ldsm_u32(&Qst[(r0+8) * HSTRIDE   + kb     + 2*tg]);
        qf[ks][2] = ldsm_u32(&Qst[r0 * HSTRIDE       + kb + 8 + 2*tg]);
        qf[ks][3] = ldsm_u32(&Qst[(r0+8) * HSTRIDE   + kb + 8 + 2*tg]);
    }

    float o[8][4];
    #pragma unroll
    for (int nt = 0; nt < 8; nt++)
        #pragma unroll
        for (int i = 0; i < 4; i++) o[nt][i] = 0.f;
    float mi0 = -1e30f, mi1 = -1e30f, li0 = 0.f, li1 = 0.f;

    const __half* posr0 = gpos + ((size_t)bh * MEMQ + m0 + r0) * LWIN;
    const __half* posr1 = posr0 + (size_t)8 * LWIN;

    for (int t = 0; t < 34; t++) {
        __syncthreads();
        if (t + 1 < 34) {
            const int j1 = m0 + (t + 1) * 64;
            const __half* kb = gk + ((size_t)bh * KVLEN + j1) * DH;
            const __half* vb = gv + ((size_t)bh * DH) * KVLEN + j1;
            __half* Kn = smA + ((t + 1) & 1) * 9216;
            __half* Vn = Kn + 4608;
            #pragma unroll
            for (int i = tid; i < 512; i += 256) {
                int r = i >> 3, ko = i & 7;
                cp_async16(&Kn[r * HSTRIDE + ko * 8], kb + r * DH + ko * 8);
                cp_async16(&Vn[r * HSTRIDE + ko * 8], vb + (size_t)r * KVLEN + ko * 8);
            }
            asm volatile("cp.async.commit_group;\n" ::: "memory");
            asm volatile("cp.async.wait_group 1;\n" ::: "memory");
        } else {
            asm volatile("cp.async.wait_group 0;\n" ::: "memory");
        }
        __syncthreads();

        const __half* Ks = smA + (t & 1) * 9216;
        const __half* Vs = Ks + 4608;

        // S = Q @ K^T
        float s[8][4];
        #pragma unroll
        for (int nt = 0; nt < 8; nt++)
            #pragma unroll
            for (int i = 0; i < 4; i++) s[nt][i] = 0.f;
        #pragma unroll
        for (int ks = 0; ks < 4; ks++) {
            const int kb = ks * 16;
            #pragma unroll
            for (int nt = 0; nt < 8; nt++) {
                int j = nt*8 + g;
                uint32_t b0 = ldsm_u32(&Ks[j * HSTRIDE + kb     + 2*tg]);
                uint32_t b1 = ldsm_u32(&Ks[j * HSTRIDE + kb + 8 + 2*tg]);
                mma_f16(s[nt], qf[ks], b0, b1);
            }
        }

        // bias + window mask + scale
        #pragma unroll
        for (int nt = 0; nt < 8; nt++) {
            int jj = nt*8 + 2*tg;
            int lA = t*64 + jj - r0;
            int lB = lA - 8;
            #pragma unroll
            for (int e = 0; e < 2; e++) {
                int l1 = lA + e;
                s[nt][e]     = (l1 >= 0 && l1 < LWIN)
                             ? (s[nt][e]     + __half2float(__ldg(posr0 + l1))) * 0.125f
                             : -1e30f;
                int l2 = lB + e;
                s[nt][2 + e] = (l2 >= 0 && l2 < LWIN)
                             ? (s[nt][2 + e] + __half2float(__ldg(posr1 + l2))) * 0.125f
                             : -1e30f;
            }
        }

        // online softmax
        float mx0 = -1e30f, mx1 = -1e30f;
        #pragma unroll
        for (int nt = 0; nt < 8; nt++) {
            mx0 = fmaxf(mx0, fmaxf(s[nt][0], s[nt][1]));
            mx1 = fmaxf(mx1, fmaxf(s[nt][2], s[nt][3]));
        }
        mx0 = fmaxf(mx0, __shfl_xor_sync(0xffffffffu, mx0, 1));
        mx0 = fmaxf(mx0, __shfl_xor_sync(0xffffffffu, mx0, 2));
        mx1 = fmaxf(mx1, __shfl_xor_sync(0xffffffffu, mx1, 1));
        mx1 = fmaxf(mx1, __shfl_xor_sync(0xffffffffu, mx1, 2));
        float mn0 = fmaxf(mi0, mx0), mn1 = fmaxf(mi1, mx1);
        float al0 = __expf(mi0 - mn0), al1 = __expf(mi1 - mn1);
        float rs0 = 0.f, rs1 = 0.f;
        #pragma unroll
        for (int nt = 0; nt < 8; nt++) {
            s[nt][0] = __expf(s[nt][0] - mn0);
            s[nt][1] = __expf(s[nt][1] - mn0);
            s[nt][2] = __expf(s[nt][2] - mn1);
            s[nt][3] = __expf(s[nt][3] - mn1);
            rs0 += s[nt][0] + s[nt][1];
            rs1 += s[nt][2] + s[nt][3];
        }
        rs0 += __shfl_xor_sync(0xffffffffu, rs0, 1);
        rs0 += __shfl_xor_sync(0xffffffffu, rs0, 2);
        rs1 += __shfl_xor_sync(0xffffffffu, rs1, 1);
        rs1 += __shfl_xor_sync(0xffffffffu, rs1, 2);
        li0 = li0 * al0 + rs0;
        li1 = li1 * al1 + rs1;
        mi0 = mn0; mi1 = mn1;

        // rescale O; pack P directly into mma A-fragments (bit-identical to the
        // old smem staging: same f2h2 at the same point, zero smem traffic)
        uint32_t ph0[8], ph1[8];
        #pragma unroll
        for (int nt = 0; nt < 8; nt++) {
            o[nt][0] *= al0; o[nt][1] *= al0; o[nt][2] *= al1; o[nt][3] *= al1;
            ph0[nt] = f2h2(s[nt][0], s[nt][1]);   // row r0,   cols nt*8+2tg..+1
            ph1[nt] = f2h2(s[nt][2], s[nt][3]);   // row r0+8, same cols
        }

        // O += P @ V   (A fragments straight from registers)
        #pragma unroll
        for (int ks = 0; ks < 4; ks++) {
            const int kb = ks * 16;
            uint32_t a[4];
            a[0] = ph0[2*ks];       // row r0,   cols kb+2tg
            a[1] = ph1[2*ks];       // row r0+8, cols kb+2tg
            a[2] = ph0[2*ks + 1];   // row r0,   cols kb+8+2tg
            a[3] = ph1[2*ks + 1];   // row r0+8, cols kb+8+2tg
            #pragma unroll
            for (int nt = 0; nt < 8; nt++) {
                int d = nt*8 + g;
                uint32_t b0 = ldsm_u32(&Vs[d * HSTRIDE + kb     + 2*tg]);
                uint32_t b1 = ldsm_u32(&Vs[d * HSTRIDE + kb + 8 + 2*tg]);
                mma_f16(o[nt], a, b0, b1);
            }
        }
    }

    const float inv0 = 1.f / li0, inv1 = 1.f / li1;
    const int b = bh >> 4, h = bh & 15;
    #pragma unroll
    for (int nt = 0; nt < 8; nt++) {
        int d = nt*8 + 2*tg;
        size_t i0 = (((size_t)(b*MEMQ + (m0 + r0    )) * NHEADS + h) << 6) + d;
        size_t i1 = (((size_t)(b*MEMQ + (m0 + r0 + 8)) * NHEADS + h) << 6) + d;
        *reinterpret_cast<uint32_t*>(&gatt[i0]) = f2h2(o[nt][0] * inv0, o[nt][1] * inv0);
        *reinterpret_cast<uint32_t*>(&gatt[i1]) = f2h2(o[nt][2] * inv1, o[nt][3] * inv1);
    }
}

// ---------------- launch ----------------
extern "C" void kernel_launch(void* const* d_in, const int* in_sizes, int n_in,
                              void* d_out, int out_size)
{
    const float* query = (const float*)d_in[0];
    const float* key   = (const float*)d_in[1];
    const float* value = (const float*)d_in[2];
    const float* keype = (const float*)d_in[3];
    const float* Wq    = (const float*)d_in[4];
    const float* Wk    = (const float*)d_in[5];
    const float* Wv    = (const float*)d_in[6];
    const float* Wo    = (const float*)d_in[7];
    float* out = (float*)d_out;

    __half *pq, *pk, *pv, *ppeT, *ppos, *patt, *pqc, *pkc, *pvc, *pw0, *pw1, *pw2, *pw3;
    cudaGetSymbolAddress((void**)&pq,   g_q);
    cudaGetSymbolAddress((void**)&pk,   g_k);
    cudaGetSymbolAddress((void**)&pv,   g_v);
    cudaGetSymbolAddress((void**)&ppeT, g_peT);
    cudaGetSymbolAddress((void**)&ppos, g_pos);
    cudaGetSymbolAddress((void**)&patt, g_att);
    cudaGetSymbolAddress((void**)&pqc,  g_qc);
    cudaGetSymbolAddress((void**)&pkc,  g_kc);
    cudaGetSymbolAddress((void**)&pvc,  g_vc);
    cudaGetSymbolAddress((void**)&pw0,  g_w0);
    cudaGetSymbolAddress((void**)&pw1,  g_w1);
    cudaGetSymbolAddress((void**)&pw2,  g_w2);
    cudaGetSymbolAddress((void**)&pw3,  g_w3);

    const int gemm_smem = 2 * HSTAGE * 2;                          // 73728 B
    const int pos_smem  = (128 * HSTRIDE + 2 * 64 * HSTRIDE) * 2;  // 36864 B
    const int attn_smem = (2 * 9216 + 128 * HSTRIDE) * 2;          // 55296 B
    cudaFuncSetAttribute(proj_h, cudaFuncAttributeMaxDynamicSharedMemorySize, gemm_smem);
    cudaFuncSetAttribute(gemm_h, cudaFuncAttributeMaxDynamicSharedMemorySize, gemm_smem);
    cudaFuncSetAttribute(pos_kernel, cudaFuncAttributeMaxDynamicSharedMemorySize, pos_smem);
    cudaFuncSetAttribute(attn_kernel, cudaFuncAttributeMaxDynamicSharedMemorySize, attn_smem);

    const int nq4 = NBATCH * MEMQ  * HIDDIM / 4;
    const int nk4 = NBATCH * KVLEN * HIDDIM / 4;
    const int nw4 = HIDDIM * HIDDIM / 4;
    const int ntot4 = nq4 + 2 * nk4 + 4 * nw4;
    const int ncast_blocks = ntot4 / 256;
    const int npe_blocks = (LWIN * DH) / 256;

    cast_all<<<ncast_blocks + npe_blocks, 256>>>(
        (const float4*)query, (const float4*)key, (const float4*)value,
        (const float4*)Wq, (const float4*)Wk, (const float4*)Wv, (const float4*)Wo,
        keype,
        (uint2*)pqc, (uint2*)pkc, (uint2*)pvc,
        (uint2*)pw0, (uint2*)pw1, (uint2*)pw2, (uint2*)pw3,
        ppeT, nq4, nk4, nw4, ncast_blocks);

    proj_h<<<2816, 256, gemm_smem>>>(pqc, pkc, pvc, pw0, pw1, pw2, pq, pk, pv);
    pos_kernel<<<512, 256, pos_smem>>>(pq, ppeT, ppos);
    attn_kernel<<<dim3(BHTOT, 4), 256, attn_smem>>>(pq, pk, pv, ppos, patt);
    gemm_h<<<dim3(32, 8), 256, gemm_smem>>>(patt, HIDDIM, pw3, out, HIDDIM, HIDDIM);
}